// round 7
// baseline (speedup 1.0000x reference)
#include <cuda_runtime.h>
#include <cuda_bf16.h>
#include <cstdint>
#include <math.h>

#define DIM   4096
#define NH    32
#define HD    128
#define BSZ   2
#define SEQ   2048

// ---------------- scratch (__device__ globals; no allocs allowed) ----------
__device__ float g_q[BSZ*SEQ*DIM];
__device__ float g_k[BSZ*SEQ*DIM];
__device__ float g_v[BSZ*SEQ*DIM];
__device__ float g_cos[SEQ*(HD/2)];
__device__ float g_sin[SEQ*(HD/2)];

// split buffers: bf16 hi + fp8 hi/lo (e4m3)
__device__ __nv_bfloat16 g_xhi[DIM*DIM];
__device__ uint8_t       g_x8h[DIM*DIM], g_x8l[DIM*DIM];
__device__ __nv_bfloat16 g_wqhi[DIM*DIM];
__device__ uint8_t       g_wq8h[DIM*DIM], g_wq8l[DIM*DIM];
__device__ __nv_bfloat16 g_wkhi[DIM*DIM];
__device__ uint8_t       g_wk8h[DIM*DIM], g_wk8l[DIM*DIM];
__device__ __nv_bfloat16 g_wvhi[DIM*DIM];
__device__ uint8_t       g_wv8h[DIM*DIM], g_wv8l[DIM*DIM];
__device__ __nv_bfloat16 g_wohi[DIM*DIM];
__device__ uint8_t       g_wo8h[DIM*DIM], g_wo8l[DIM*DIM];
__device__ __nv_bfloat16 g_ahi[DIM*DIM];
__device__ uint8_t       g_a8h[DIM*DIM], g_a8l[DIM*DIM];

// ---------------- base-ISA helpers (compute_103-safe) ----------------------
__device__ __forceinline__ uint32_t smem_u32(const void* p) {
    uint32_t a;
    asm("{ .reg .u64 t; cvta.to.shared.u64 t, %1; cvt.u32.u64 %0, t; }" : "=r"(a) : "l"(p));
    return a;
}
__device__ __forceinline__ void cpa16(uint32_t saddr, const void* g) {
    asm volatile("cp.async.cg.shared.global [%0], [%1], 16;" :: "r"(saddr), "l"(g));
}
__device__ __forceinline__ void ldsm4(uint32_t* r, uint32_t addr) {
    asm volatile("ldmatrix.sync.aligned.m8n8.x4.shared.b16 {%0,%1,%2,%3}, [%4];"
        : "=r"(r[0]), "=r"(r[1]), "=r"(r[2]), "=r"(r[3]) : "r"(addr));
}
__device__ __forceinline__ void mma16816(float* c, const uint32_t* a,
                                         uint32_t b0, uint32_t b1) {
    asm volatile("mma.sync.aligned.m16n8k16.row.col.f32.bf16.bf16.f32 "
        "{%0,%1,%2,%3}, {%4,%5,%6,%7}, {%8,%9}, {%0,%1,%2,%3};"
        : "+f"(c[0]), "+f"(c[1]), "+f"(c[2]), "+f"(c[3])
        : "r"(a[0]), "r"(a[1]), "r"(a[2]), "r"(a[3]), "r"(b0), "r"(b1));
}
// fp8 e4m3 mma, k32 (base ISA since sm_89)
__device__ __forceinline__ void mma_e4m3(float* c, const uint32_t* a,
                                         uint32_t b0, uint32_t b1) {
    asm volatile("mma.sync.aligned.m16n8k32.row.col.f32.e4m3.e4m3.f32 "
        "{%0,%1,%2,%3}, {%4,%5,%6,%7}, {%8,%9}, {%0,%1,%2,%3};"
        : "+f"(c[0]), "+f"(c[1]), "+f"(c[2]), "+f"(c[3])
        : "r"(a[0]), "r"(a[1]), "r"(a[2]), "r"(a[3]), "r"(b0), "r"(b1));
}
__device__ __forceinline__ void mma_tf32(float* c, const uint32_t* a,
                                         uint32_t b0, uint32_t b1) {
    asm volatile("mma.sync.aligned.m16n8k8.row.col.f32.tf32.tf32.f32 "
        "{%0,%1,%2,%3}, {%4,%5,%6,%7}, {%8,%9}, {%0,%1,%2,%3};"
        : "+f"(c[0]), "+f"(c[1]), "+f"(c[2]), "+f"(c[3])
        : "r"(a[0]), "r"(a[1]), "r"(a[2]), "r"(a[3]), "r"(b0), "r"(b1));
}
__device__ __forceinline__ uint32_t to_tf32(float x) {
    uint32_t r;
    asm("cvt.rna.tf32.f32 %0, %1;" : "=r"(r) : "f"(x));
    return r;
}
// pack two floats -> two e4m3 (low byte = lo_elem)
__device__ __forceinline__ uint16_t cvt2_e4m3(float hi_elem, float lo_elem) {
    uint16_t r;
    asm("cvt.rn.satfinite.e4m3x2.f32 %0, %1, %2;" : "=h"(r) : "f"(hi_elem), "f"(lo_elem));
    return r;
}
__device__ __forceinline__ uint32_t sw128(uint32_t off) {
    return off ^ ((off >> 3) & 0x70);
}

// ---------------------------------------------------------------------------
// fp32 -> (bf16 hi, e4m3 hi8, e4m3 lo8) splits.
// Activations: hi8 = x, lo8 = (x - hi)*2^9.
// Weights:     hi8 = w*2^6, lo8 = (w - hi)*2^15.
// ---------------------------------------------------------------------------
__global__ void split_act(const float* __restrict__ in,
                          __nv_bfloat16* __restrict__ hi,
                          uint8_t* __restrict__ h8, uint8_t* __restrict__ l8, int n4)
{
    int i = blockIdx.x * 256 + threadIdx.x;
    if (i >= n4) return;
    float4 v = ((const float4*)in)[i];
    __nv_bfloat162 h01 = __floats2bfloat162_rn(v.x, v.y);
    __nv_bfloat162 h23 = __floats2bfloat162_rn(v.z, v.w);
    ((__nv_bfloat162*)hi)[2*i]   = h01;
    ((__nv_bfloat162*)hi)[2*i+1] = h23;
    float2 f01 = __bfloat1622float2(h01);
    float2 f23 = __bfloat1622float2(h23);
    uint32_t hh = (uint32_t)cvt2_e4m3(v.y, v.x) | ((uint32_t)cvt2_e4m3(v.w, v.z) << 16);
    ((uint32_t*)h8)[i] = hh;
    uint32_t ll = (uint32_t)cvt2_e4m3((v.y - f01.y) * 512.f, (v.x - f01.x) * 512.f)
                | ((uint32_t)cvt2_e4m3((v.w - f23.y) * 512.f, (v.z - f23.x) * 512.f) << 16);
    ((uint32_t*)l8)[i] = ll;
}

__global__ void split_wt(const float* __restrict__ in,
                         __nv_bfloat16* __restrict__ hi,
                         uint8_t* __restrict__ h8, uint8_t* __restrict__ l8, int n4)
{
    int i = blockIdx.x * 256 + threadIdx.x;
    if (i >= n4) return;
    float4 v = ((const float4*)in)[i];
    __nv_bfloat162 h01 = __floats2bfloat162_rn(v.x, v.y);
    __nv_bfloat162 h23 = __floats2bfloat162_rn(v.z, v.w);
    ((__nv_bfloat162*)hi)[2*i]   = h01;
    ((__nv_bfloat162*)hi)[2*i+1] = h23;
    float2 f01 = __bfloat1622float2(h01);
    float2 f23 = __bfloat1622float2(h23);
    uint32_t hh = (uint32_t)cvt2_e4m3(v.y * 64.f, v.x * 64.f)
                | ((uint32_t)cvt2_e4m3(v.w * 64.f, v.z * 64.f) << 16);
    ((uint32_t*)h8)[i] = hh;
    uint32_t ll = (uint32_t)cvt2_e4m3((v.y - f01.y) * 32768.f, (v.x - f01.x) * 32768.f)
                | ((uint32_t)cvt2_e4m3((v.w - f23.y) * 32768.f, (v.z - f23.x) * 32768.f) << 16);
    ((uint32_t*)l8)[i] = ll;
}

// ---------------------------------------------------------------------------
// Mixed bf16+fp8 tensor-core GEMM (NT): C = Ahi*Bhi + 2^-15*(Ahi8*Blo8 + Alo8*Bhi8)
// CTA 128x128, BK=64, 8 warps (4Mx2N), warp tile 32x64, 3-stage cp.async.
// ---------------------------------------------------------------------------
__global__ void __launch_bounds__(256, 1)
gemm_mma(const __nv_bfloat16* __restrict__ Ahi, const uint8_t* __restrict__ A8h,
         const uint8_t* __restrict__ A8l,
         const __nv_bfloat16* __restrict__ Bhi, const uint8_t* __restrict__ B8h,
         const uint8_t* __restrict__ B8l,
         float* __restrict__ C)
{
    extern __shared__ char sm[];
    const uint32_t s0 = smem_u32(sm);

    const int tid  = threadIdx.x;
    const int wid  = tid >> 5;
    const int lane = tid & 31;
    const int bx = blockIdx.x;
    const int by = blockIdx.y;
    const int warp_m = wid >> 1;   // 0..3 (32 rows)
    const int warp_n = wid & 1;    // 0..1 (64 cols)

    float acc[2][8][4], accc[2][8][4];
#pragma unroll
    for (int t = 0; t < 2; t++)
#pragma unroll
        for (int n = 0; n < 8; n++)
#pragma unroll
            for (int j = 0; j < 4; j++) { acc[t][n][j] = 0.0f; accc[t][n][j] = 0.0f; }

    // stage (64KB): Ahi 16K | Bhi 16K | A8h 8K | A8l 8K | B8h 8K | B8l 8K
    auto load_stage = [&](int kt, int stage) {
        uint32_t sb = s0 + stage * 65536;
#pragma unroll
        for (int i = 0; i < 4; i++) {
            int li = tid + i * 256;
            int r = li >> 3, c = li & 7;
            cpa16(sb + sw128((uint32_t)(r * 128 + c * 16)),
                  Ahi + (size_t)(by * 128 + r) * 4096 + kt * 64 + c * 8);
            cpa16(sb + 16384 + sw128((uint32_t)(r * 128 + c * 16)),
                  Bhi + (size_t)(bx * 128 + r) * 4096 + kt * 64 + c * 8);
        }
#pragma unroll
        for (int i = 0; i < 2; i++) {
            int li = tid + i * 256;
            int r = li >> 2, c = li & 3;
            uint32_t off = sw128((uint32_t)(r * 64 + c * 16));
            cpa16(sb + 32768 + off, A8h + (size_t)(by * 128 + r) * 4096 + kt * 64 + c * 16);
            cpa16(sb + 40960 + off, A8l + (size_t)(by * 128 + r) * 4096 + kt * 64 + c * 16);
            cpa16(sb + 49152 + off, B8h + (size_t)(bx * 128 + r) * 4096 + kt * 64 + c * 16);
            cpa16(sb + 57344 + off, B8l + (size_t)(bx * 128 + r) * 4096 + kt * 64 + c * 16);
        }
        asm volatile("cp.async.commit_group;" ::: "memory");
    };

    const int lrow  = (lane & 7) + ((lane >> 3) & 1) * 8;
    const int khalf = (lane >> 4) * 16;

    const int NT = 4096 / 64;

    load_stage(0, 0);
    load_stage(1, 1);

    for (int kt = 0; kt < NT; kt++) {
        if (kt < NT - 1) asm volatile("cp.async.wait_group 1;" ::: "memory");
        else             asm volatile("cp.async.wait_group 0;" ::: "memory");
        __syncthreads();

        const uint32_t sbase = s0 + (kt % 3) * 65536;
        if (kt + 2 < NT) load_stage(kt + 2, (kt + 2) % 3);

#pragma unroll
        for (int s32 = 0; s32 < 2; s32++) {
            // ---- bf16 main product: two k16 steps ----
#pragma unroll
            for (int s16 = 0; s16 < 2; s16++) {
                const int kb = (s32 * 2 + s16) * 32;
                uint32_t ah[2][4], bh[4][4];
#pragma unroll
                for (int t = 0; t < 2; t++) {
                    uint32_t off = sw128((uint32_t)((warp_m * 32 + t * 16 + lrow) * 128
                                                    + khalf + kb));
                    ldsm4(ah[t], sbase + off);
                }
#pragma unroll
                for (int u = 0; u < 4; u++) {
                    uint32_t off = sw128((uint32_t)((warp_n * 64 + u * 16 + lrow) * 128
                                                    + khalf + kb));
                    ldsm4(bh[u], sbase + 16384 + off);
                }
#pragma unroll
                for (int t = 0; t < 2; t++)
#pragma unroll
                    for (int u = 0; u < 4; u++)
#pragma unroll
                        for (int j = 0; j < 2; j++)
                            mma16816(acc[t][u * 2 + j], ah[t], bh[u][j], bh[u][j + 2]);
            }
            // ---- fp8 corrections: one k32 step ----
            {
                const int kb8 = s32 * 32;
                uint32_t a8h[2][4], a8l[2][4], b8h[4][4], b8l[4][4];
#pragma unroll
                for (int t = 0; t < 2; t++) {
                    uint32_t off = sw128((uint32_t)((warp_m * 32 + t * 16 + lrow) * 64
                                                    + khalf + kb8));
                    ldsm4(a8h[t], sbase + 32768 + off);
                    ldsm4(a8l[t], sbase + 40960 + off);
                }
#pragma unroll
                for (int u = 0; u < 4; u++) {
                    uint32_t off = sw128((uint32_t)((warp_n * 64 + u * 16 + lrow) * 64
                                                    + khalf + kb8));
                    ldsm4(b8h[u], sbase + 49152 + off);
                    ldsm4(b8l[u], sbase + 57344 + off);
                }
#pragma unroll
                for (int t = 0; t < 2; t++)
#pragma unroll
                    for (int u = 0; u < 4; u++)
#pragma unroll
                        for (int j = 0; j < 2; j++) {
                            mma_e4m3(accc[t][u * 2 + j], a8h[t], b8l[u][j], b8l[u][j + 2]);
                            mma_e4m3(accc[t][u * 2 + j], a8l[t], b8h[u][j], b8h[u][j + 2]);
                        }
            }
        }
    }

    const float CS = 3.0517578125e-05f;   // 2^-15
    const int g  = lane >> 2;
    const int qc = lane & 3;
#pragma unroll
    for (int t = 0; t < 2; t++) {
        const int row = by * 128 + warp_m * 32 + t * 16 + g;
#pragma unroll
        for (int n = 0; n < 8; n++) {
            const int col = bx * 128 + warp_n * 64 + n * 8 + qc * 2;
            *(float2*)&C[(size_t)row * 4096 + col] =
                make_float2(acc[t][n][0] + accc[t][n][0] * CS,
                            acc[t][n][1] + accc[t][n][1] * CS);
            *(float2*)&C[(size_t)(row + 8) * 4096 + col] =
                make_float2(acc[t][n][2] + accc[t][n][2] * CS,
                            acc[t][n][3] + accc[t][n][3] * CS);
        }
    }
}

// ---------------------------------------------------------------------------
// RoPE
// ---------------------------------------------------------------------------
__global__ void rope_table(float* ct, float* st)
{
    int idx = blockIdx.x * 256 + threadIdx.x;
    if (idx >= SEQ * (HD / 2)) return;
    int s = idx >> 6;
    int j = idx & 63;
    double inv = pow(10000.0, -(double)(2 * j) / 128.0);
    double a = (double)s * inv;
    ct[idx] = (float)cos(a);
    st[idx] = (float)sin(a);
}

__global__ void rope_apply(float* __restrict__ q, float* __restrict__ k,
                           const float* __restrict__ ct, const float* __restrict__ st)
{
    int idx = blockIdx.x * 256 + threadIdx.x;
    if (idx >= BSZ * SEQ * NH * (HD / 2)) return;
    int j = idx & 63;
    int h = (idx >> 6) & 31;
    int s = (idx >> 11) & 2047;
    int b = idx >> 22;
    size_t base = (((size_t)(b * SEQ + s) * NH + h) << 7) + 2 * j;
    float c  = ct[s * 64 + j];
    float sn = st[s * 64 + j];
    float2 xq = *(float2*)&q[base];
    float2 xk = *(float2*)&k[base];
    float2 oq, ok;
    oq.x = xq.x * c - xq.y * sn;
    oq.y = xq.x * sn + xq.y * c;
    ok.x = xk.x * c - xk.y * sn;
    ok.y = xk.x * sn + xk.y * c;
    *(float2*)&q[base] = oq;
    *(float2*)&k[base] = ok;
}

// ---------------------------------------------------------------------------
// Tensor-core causal flash attention (tf32 mma.m16n8k8).
// Epilogue emits bf16 hi + e4m3 hi8/lo8 split (feeds wo GEMM).
// ---------------------------------------------------------------------------
#define KS_STRIDE 132
#define PS_STRIDE 68
#define ATTN_SMEM ((2*64*KS_STRIDE + 4*16*PS_STRIDE) * 4)

__global__ void __launch_bounds__(128)
attn_tc(const float* __restrict__ Q, const float* __restrict__ Kg,
        const float* __restrict__ Vg,
        __nv_bfloat16* __restrict__ Ohi, uint8_t* __restrict__ O8h,
        uint8_t* __restrict__ O8l)
{
    extern __shared__ float smf[];
    float* Ks = smf;
    float* Vs = smf + 64 * KS_STRIDE;
    float* Ps = smf + 2 * 64 * KS_STRIDE;

    const int tid  = threadIdx.x;
    const int w    = tid >> 5;
    const int lane = tid & 31;
    const int qt = blockIdx.x;
    const int h  = blockIdx.y;
    const int b  = blockIdx.z;
    const int g  = lane >> 2;
    const int qc = lane & 3;
    float* Pw = Ps + w * 16 * PS_STRIDE;

    const float scale = 0.08838834764831845f;
    const int q0 = qt * 64 + w * 16;

    uint32_t qa[16][4];
    {
        const float* q_r0 = Q + ((size_t)b * SEQ + q0 + g)     * 4096 + h * 128;
        const float* q_r1 = Q + ((size_t)b * SEQ + q0 + g + 8) * 4096 + h * 128;
#pragma unroll
        for (int kc = 0; kc < 16; kc++) {
            qa[kc][0] = to_tf32(q_r0[kc * 8 + qc]     * scale);
            qa[kc][1] = to_tf32(q_r1[kc * 8 + qc]     * scale);
            qa[kc][2] = to_tf32(q_r0[kc * 8 + qc + 4] * scale);
            qa[kc][3] = to_tf32(q_r1[kc * 8 + qc + 4] * scale);
        }
    }

    float o[16][4];
#pragma unroll
    for (int n = 0; n < 16; n++)
#pragma unroll
        for (int j = 0; j < 4; j++) o[n][j] = 0.0f;
    float m0 = -1e30f, m1 = -1e30f, l0 = 0.0f, l1 = 0.0f;

    for (int kt = 0; kt <= qt; kt++) {
        if (kt) __syncthreads();
#pragma unroll
        for (int i = 0; i < 16; i++) {
            int li = tid + i * 128;
            int row = li >> 5, c4 = li & 31;
            size_t gsrc = ((size_t)b * SEQ + kt * 64 + row) * 4096 + h * 128 + c4 * 4;
            float4 kv = *(const float4*)&Kg[gsrc];
            float4 vv = *(const float4*)&Vg[gsrc];
            uint4 kb = make_uint4(to_tf32(kv.x), to_tf32(kv.y), to_tf32(kv.z), to_tf32(kv.w));
            uint4 vb = make_uint4(to_tf32(vv.x), to_tf32(vv.y), to_tf32(vv.z), to_tf32(vv.w));
            *(uint4*)&Ks[row * KS_STRIDE + c4 * 4] = kb;
            *(uint4*)&Vs[row * KS_STRIDE + c4 * 4] = vb;
        }
        __syncthreads();

        float sreg[8][4];
#pragma unroll
        for (int j = 0; j < 8; j++) {
            sreg[j][0] = sreg[j][1] = sreg[j][2] = sreg[j][3] = 0.0f;
            const uint32_t* krow = (const uint32_t*)&Ks[(j * 8 + g) * KS_STRIDE];
#pragma unroll
            for (int kc = 0; kc < 16; kc++)
                mma_tf32(sreg[j], qa[kc], krow[kc * 8 + qc], krow[kc * 8 + qc + 4]);
        }

        if (kt == qt) {
            const int kb = kt * 64;
#pragma unroll
            for (int j = 0; j < 8; j++) {
                int key0 = kb + j * 8 + 2 * qc;
                if (key0     > q0 + g)     sreg[j][0] = -1e30f;
                if (key0 + 1 > q0 + g)     sreg[j][1] = -1e30f;
                if (key0     > q0 + g + 8) sreg[j][2] = -1e30f;
                if (key0 + 1 > q0 + g + 8) sreg[j][3] = -1e30f;
            }
        }

        float mx0 = -1e30f, mx1 = -1e30f;
#pragma unroll
        for (int j = 0; j < 8; j++) {
            mx0 = fmaxf(mx0, fmaxf(sreg[j][0], sreg[j][1]));
            mx1 = fmaxf(mx1, fmaxf(sreg[j][2], sreg[j][3]));
        }
        mx0 = fmaxf(mx0, __shfl_xor_sync(0xffffffffu, mx0, 1));
        mx0 = fmaxf(mx0, __shfl_xor_sync(0xffffffffu, mx0, 2));
        mx1 = fmaxf(mx1, __shfl_xor_sync(0xffffffffu, mx1, 1));
        mx1 = fmaxf(mx1, __shfl_xor_sync(0xffffffffu, mx1, 2));
        float mn0 = fmaxf(m0, mx0), mn1 = fmaxf(m1, mx1);
        float f0 = __expf(m0 - mn0), f1 = __expf(m1 - mn1);
        m0 = mn0; m1 = mn1;

        float sum0 = 0.0f, sum1 = 0.0f;
        uint32_t* PwU = (uint32_t*)Pw;
#pragma unroll
        for (int j = 0; j < 8; j++) {
            float p0 = __expf(sreg[j][0] - mn0);
            float p1 = __expf(sreg[j][1] - mn0);
            float p2 = __expf(sreg[j][2] - mn1);
            float p3 = __expf(sreg[j][3] - mn1);
            sum0 += p0 + p1;
            sum1 += p2 + p3;
            PwU[g * PS_STRIDE       + j * 8 + 2 * qc]     = to_tf32(p0);
            PwU[g * PS_STRIDE       + j * 8 + 2 * qc + 1] = to_tf32(p1);
            PwU[(g + 8) * PS_STRIDE + j * 8 + 2 * qc]     = to_tf32(p2);
            PwU[(g + 8) * PS_STRIDE + j * 8 + 2 * qc + 1] = to_tf32(p3);
        }
        sum0 += __shfl_xor_sync(0xffffffffu, sum0, 1);
        sum0 += __shfl_xor_sync(0xffffffffu, sum0, 2);
        sum1 += __shfl_xor_sync(0xffffffffu, sum1, 1);
        sum1 += __shfl_xor_sync(0xffffffffu, sum1, 2);
        l0 = l0 * f0 + sum0;
        l1 = l1 * f1 + sum1;

#pragma unroll
        for (int n = 0; n < 16; n++) {
            o[n][0] *= f0; o[n][1] *= f0;
            o[n][2] *= f1; o[n][3] *= f1;
        }
        __syncwarp();

        uint32_t pa[8][4];
#pragma unroll
        for (int kc = 0; kc < 8; kc++) {
            pa[kc][0] = PwU[g * PS_STRIDE       + kc * 8 + qc];
            pa[kc][1] = PwU[(g + 8) * PS_STRIDE + kc * 8 + qc];
            pa[kc][2] = PwU[g * PS_STRIDE       + kc * 8 + qc + 4];
            pa[kc][3] = PwU[(g + 8) * PS_STRIDE + kc * 8 + qc + 4];
        }

#pragma unroll
        for (int n = 0; n < 16; n++) {
#pragma unroll
            for (int kc = 0; kc < 8; kc++) {
                uint32_t b0 = ((const uint32_t*)Vs)[(kc * 8 + qc)     * KS_STRIDE + n * 8 + g];
                uint32_t b1 = ((const uint32_t*)Vs)[(kc * 8 + qc + 4) * KS_STRIDE + n * 8 + g];
                mma_tf32(o[n], pa[kc], b0, b1);
            }
        }
    }

    // epilogue: normalize, emit bf16 hi + e4m3 hi8/lo8 (act scales: 1, 2^9)
    const float inv0 = 1.0f / l0;
    const float inv1 = 1.0f / l1;
    const size_t base0 = ((size_t)b * SEQ + q0 + g)     * 4096 + h * 128;
    const size_t base1 = ((size_t)b * SEQ + q0 + g + 8) * 4096 + h * 128;
#pragma unroll
    for (int n = 0; n < 16; n++) {
        float v00 = o[n][0] * inv0, v01 = o[n][1] * inv0;
        float v10 = o[n][2] * inv1, v11 = o[n][3] * inv1;
        __nv_bfloat162 h0 = __floats2bfloat162_rn(v00, v01);
        __nv_bfloat162 h1 = __floats2bfloat162_rn(v10, v11);
        float2 r0 = __bfloat1622float2(h0);
        float2 r1 = __bfloat1622float2(h1);
        *(__nv_bfloat162*)&Ohi[base0 + n * 8 + 2 * qc] = h0;
        *(__nv_bfloat162*)&Ohi[base1 + n * 8 + 2 * qc] = h1;
        *(uint16_t*)&O8h[base0 + n * 8 + 2 * qc] = cvt2_e4m3(v01, v00);
        *(uint16_t*)&O8h[base1 + n * 8 + 2 * qc] = cvt2_e4m3(v11, v10);
        *(uint16_t*)&O8l[base0 + n * 8 + 2 * qc] =
            cvt2_e4m3((v01 - r0.y) * 512.f, (v00 - r0.x) * 512.f);
        *(uint16_t*)&O8l[base1 + n * 8 + 2 * qc] =
            cvt2_e4m3((v11 - r1.y) * 512.f, (v10 - r1.x) * 512.f);
    }
}

// ---------------------------------------------------------------------------
extern "C" void kernel_launch(void* const* d_in, const int* in_sizes, int n_in,
                              void* d_out, int out_size)
{
    const float* x = (const float*)d_in[0];
    int off = (n_in >= 6 && in_sizes[1] <= 4) ? 2 : 1;
    const float* wq = (const float*)d_in[off + 0];
    const float* wk = (const float*)d_in[off + 1];
    const float* wv = (const float*)d_in[off + 2];
    const float* wo = (const float*)d_in[off + 3];
    float* out = (float*)d_out;

    float *q, *k, *v, *ct, *st;
    cudaGetSymbolAddress((void**)&q,  g_q);
    cudaGetSymbolAddress((void**)&k,  g_k);
    cudaGetSymbolAddress((void**)&v,  g_v);
    cudaGetSymbolAddress((void**)&ct, g_cos);
    cudaGetSymbolAddress((void**)&st, g_sin);

    __nv_bfloat16 *xhi, *wqhi, *wkhi, *wvhi, *wohi, *ahi;
    uint8_t *x8h, *x8l, *wq8h, *wq8l, *wk8h, *wk8l, *wv8h, *wv8l, *wo8h, *wo8l, *a8h, *a8l;
    cudaGetSymbolAddress((void**)&xhi,  g_xhi);
    cudaGetSymbolAddress((void**)&x8h,  g_x8h);   cudaGetSymbolAddress((void**)&x8l,  g_x8l);
    cudaGetSymbolAddress((void**)&wqhi, g_wqhi);
    cudaGetSymbolAddress((void**)&wq8h, g_wq8h);  cudaGetSymbolAddress((void**)&wq8l, g_wq8l);
    cudaGetSymbolAddress((void**)&wkhi, g_wkhi);
    cudaGetSymbolAddress((void**)&wk8h, g_wk8h);  cudaGetSymbolAddress((void**)&wk8l, g_wk8l);
    cudaGetSymbolAddress((void**)&wvhi, g_wvhi);
    cudaGetSymbolAddress((void**)&wv8h, g_wv8h);  cudaGetSymbolAddress((void**)&wv8l, g_wv8l);
    cudaGetSymbolAddress((void**)&wohi, g_wohi);
    cudaGetSymbolAddress((void**)&wo8h, g_wo8h);  cudaGetSymbolAddress((void**)&wo8l, g_wo8l);
    cudaGetSymbolAddress((void**)&ahi,  g_ahi);
    cudaGetSymbolAddress((void**)&a8h,  g_a8h);   cudaGetSymbolAddress((void**)&a8l,  g_a8l);

    cudaFuncSetAttribute(gemm_mma, cudaFuncAttributeMaxDynamicSharedMemorySize, 196608);
    cudaFuncSetAttribute(attn_tc,  cudaFuncAttributeMaxDynamicSharedMemorySize, ATTN_SMEM);

    const int n4 = DIM * DIM / 4;
    const int cgrid = (n4 + 255) / 256;
    dim3 gg(DIM / 128, DIM / 128);

    split_act<<<cgrid, 256>>>(x,  xhi, x8h, x8l, n4);
    split_wt<<<cgrid, 256>>>(wq, wqhi, wq8h, wq8l, n4);
    split_wt<<<cgrid, 256>>>(wk, wkhi, wk8h, wk8l, n4);
    split_wt<<<cgrid, 256>>>(wv, wvhi, wv8h, wv8l, n4);
    split_wt<<<cgrid, 256>>>(wo, wohi, wo8h, wo8l, n4);

    gemm_mma<<<gg, 256, 196608>>>(xhi, x8h, x8l, wqhi, wq8h, wq8l, q);
    gemm_mma<<<gg, 256, 196608>>>(xhi, x8h, x8l, wkhi, wk8h, wk8l, k);
    gemm_mma<<<gg, 256, 196608>>>(xhi, x8h, x8l, wvhi, wv8h, wv8l, v);

    rope_table<<<(SEQ * (HD / 2) + 255) / 256, 256>>>(ct, st);
    rope_apply<<<(BSZ * SEQ * NH * (HD / 2) + 255) / 256, 256>>>(q, k, ct, st);

    attn_tc<<<dim3(SEQ / 64, NH, BSZ), 128, ATTN_SMEM>>>(q, k, v, ahi, a8h, a8l);

    gemm_mma<<<gg, 256, 196608>>>(ahi, a8h, a8l, wohi, wo8h, wo8l, out);
}

// round 8
// speedup vs baseline: 1.5652x; 1.5652x over previous
#include <cuda_runtime.h>
#include <cuda_fp16.h>
#include <cstdint>
#include <math.h>

#define DIM   4096
#define NH    32
#define HD    128
#define BSZ   2
#define SEQ   2048

// ---------------- scratch (__device__ globals; no allocs allowed) ----------
__device__ float g_q[BSZ*SEQ*DIM];
__device__ float g_k[BSZ*SEQ*DIM];
__device__ float g_v[BSZ*SEQ*DIM];
__device__ float g_cos[SEQ*(HD/2)];
__device__ float g_sin[SEQ*(HD/2)];

// fp16 buffers: activations single, weights hi/lo (scaled x64)
__device__ __half g_x16[DIM*DIM];
__device__ __half g_wqh[DIM*DIM], g_wql[DIM*DIM];
__device__ __half g_wkh[DIM*DIM], g_wkl[DIM*DIM];
__device__ __half g_wvh[DIM*DIM], g_wvl[DIM*DIM];
__device__ __half g_woh[DIM*DIM], g_wol[DIM*DIM];
__device__ __half g_a16[DIM*DIM];

// ---------------- base-ISA helpers (compute_103-safe) ----------------------
__device__ __forceinline__ uint32_t smem_u32(const void* p) {
    uint32_t a;
    asm("{ .reg .u64 t; cvta.to.shared.u64 t, %1; cvt.u32.u64 %0, t; }" : "=r"(a) : "l"(p));
    return a;
}
__device__ __forceinline__ void cpa16(uint32_t saddr, const void* g) {
    asm volatile("cp.async.cg.shared.global [%0], [%1], 16;" :: "r"(saddr), "l"(g));
}
__device__ __forceinline__ void ldsm4(uint32_t* r, uint32_t addr) {
    asm volatile("ldmatrix.sync.aligned.m8n8.x4.shared.b16 {%0,%1,%2,%3}, [%4];"
        : "=r"(r[0]), "=r"(r[1]), "=r"(r[2]), "=r"(r[3]) : "r"(addr));
}
__device__ __forceinline__ void mma_f16(float* c, const uint32_t* a,
                                        uint32_t b0, uint32_t b1) {
    asm volatile("mma.sync.aligned.m16n8k16.row.col.f32.f16.f16.f32 "
        "{%0,%1,%2,%3}, {%4,%5,%6,%7}, {%8,%9}, {%0,%1,%2,%3};"
        : "+f"(c[0]), "+f"(c[1]), "+f"(c[2]), "+f"(c[3])
        : "r"(a[0]), "r"(a[1]), "r"(a[2]), "r"(a[3]), "r"(b0), "r"(b1));
}
__device__ __forceinline__ void mma_tf32(float* c, const uint32_t* a,
                                         uint32_t b0, uint32_t b1) {
    asm volatile("mma.sync.aligned.m16n8k8.row.col.f32.tf32.tf32.f32 "
        "{%0,%1,%2,%3}, {%4,%5,%6,%7}, {%8,%9}, {%0,%1,%2,%3};"
        : "+f"(c[0]), "+f"(c[1]), "+f"(c[2]), "+f"(c[3])
        : "r"(a[0]), "r"(a[1]), "r"(a[2]), "r"(a[3]), "r"(b0), "r"(b1));
}
__device__ __forceinline__ uint32_t to_tf32(float x) {
    uint32_t r;
    asm("cvt.rna.tf32.f32 %0, %1;" : "=r"(r) : "f"(x));
    return r;
}
__device__ __forceinline__ uint32_t sw128(uint32_t off) {
    return off ^ ((off >> 3) & 0x70);
}

// ---------------------------------------------------------------------------
// splits
// ---------------------------------------------------------------------------
__global__ void split_act(const float* __restrict__ in, __half* __restrict__ o, int n4)
{
    int i = blockIdx.x * 256 + threadIdx.x;
    if (i >= n4) return;
    float4 v = ((const float4*)in)[i];
    ((__half2*)o)[2*i]   = __floats2half2_rn(v.x, v.y);
    ((__half2*)o)[2*i+1] = __floats2half2_rn(v.z, v.w);
}

// weights: wh = rn16(64w), wl = rn16(64w - wh)
__global__ void split_wt(const float* __restrict__ in,
                         __half* __restrict__ hi, __half* __restrict__ lo, int n4)
{
    int i = blockIdx.x * 256 + threadIdx.x;
    if (i >= n4) return;
    float4 v = ((const float4*)in)[i];
    v.x *= 64.f; v.y *= 64.f; v.z *= 64.f; v.w *= 64.f;
    __half2 h01 = __floats2half2_rn(v.x, v.y);
    __half2 h23 = __floats2half2_rn(v.z, v.w);
    float2 f01 = __half22float2(h01);
    float2 f23 = __half22float2(h23);
    ((__half2*)hi)[2*i]   = h01;
    ((__half2*)hi)[2*i+1] = h23;
    ((__half2*)lo)[2*i]   = __floats2half2_rn(v.x - f01.x, v.y - f01.y);
    ((__half2*)lo)[2*i+1] = __floats2half2_rn(v.z - f23.x, v.w - f23.y);
}

// ---------------------------------------------------------------------------
// fp16 2-product tensor-core GEMM (NT): C = 2^-6 * A16*(Bh + Bl), 4096^3.
// CTA 128x128, BK=64 (128B rows, SW128), 8 warps (4Mx2N), warp tile 32x64,
// 3-stage cp.async pipeline + fragment double-buffering.
// ---------------------------------------------------------------------------
#define STAGE_SZ 49152
__global__ void __launch_bounds__(256, 1)
gemm_mma(const __half* __restrict__ A16,
         const __half* __restrict__ Bh16, const __half* __restrict__ Bl16,
         float* __restrict__ C)
{
    extern __shared__ char sm[];
    const uint32_t s0 = smem_u32(sm);

    const int tid  = threadIdx.x;
    const int wid  = tid >> 5;
    const int lane = tid & 31;
    const int bx = blockIdx.x;
    const int by = blockIdx.y;
    const int warp_m = wid >> 1;   // 0..3 (32 rows each)
    const int warp_n = wid & 1;    // 0..1 (64 cols each)

    float acc[2][8][4];
#pragma unroll
    for (int t = 0; t < 2; t++)
#pragma unroll
        for (int n = 0; n < 8; n++)
#pragma unroll
            for (int j = 0; j < 4; j++) acc[t][n][j] = 0.0f;

    // stage: A 16K | Bh 16K | Bl 16K
    auto load_stage = [&](int kt, int stage) {
        uint32_t sb = s0 + stage * STAGE_SZ;
#pragma unroll
        for (int i = 0; i < 4; i++) {
            int li = tid + i * 256;           // 0..1023
            int r = li >> 3, c = li & 7;
            uint32_t off = sw128((uint32_t)(r * 128 + c * 16));
            cpa16(sb + off,         A16  + (size_t)(by * 128 + r) * 4096 + kt * 64 + c * 8);
            cpa16(sb + 16384 + off, Bh16 + (size_t)(bx * 128 + r) * 4096 + kt * 64 + c * 8);
            cpa16(sb + 32768 + off, Bl16 + (size_t)(bx * 128 + r) * 4096 + kt * 64 + c * 8);
        }
        asm volatile("cp.async.commit_group;" ::: "memory");
    };

    const int lrow  = (lane & 7) + ((lane >> 3) & 1) * 8;
    const int khalf = (lane >> 4) * 16;

    uint32_t ah[2][2][4], bh[2][4][4], bl[2][4][4];

    auto ldfr = [&](int buf, int s, uint32_t sbase) {
#pragma unroll
        for (int t = 0; t < 2; t++) {
            uint32_t off = sw128((uint32_t)((warp_m * 32 + t * 16 + lrow) * 128
                                            + khalf + s * 32));
            ldsm4(ah[buf][t], sbase + off);
        }
#pragma unroll
        for (int u = 0; u < 4; u++) {
            uint32_t off = sw128((uint32_t)((warp_n * 64 + u * 16 + lrow) * 128
                                            + khalf + s * 32));
            ldsm4(bh[buf][u], sbase + 16384 + off);
            ldsm4(bl[buf][u], sbase + 32768 + off);
        }
    };

    auto do_mma = [&](int buf) {
#pragma unroll
        for (int t = 0; t < 2; t++)
#pragma unroll
            for (int u = 0; u < 4; u++)
#pragma unroll
                for (int j = 0; j < 2; j++) {
                    float* c = acc[t][u * 2 + j];
                    mma_f16(c, ah[buf][t], bh[buf][u][j], bh[buf][u][j + 2]);
                    mma_f16(c, ah[buf][t], bl[buf][u][j], bl[buf][u][j + 2]);
                }
    };

    const int NT = 4096 / 64;   // 64 k-tiles

    load_stage(0, 0);
    load_stage(1, 1);

    for (int kt = 0; kt < NT; kt++) {
        if (kt < NT - 1) asm volatile("cp.async.wait_group 1;" ::: "memory");
        else             asm volatile("cp.async.wait_group 0;" ::: "memory");
        __syncthreads();

        const uint32_t sbase = s0 + (kt % 3) * STAGE_SZ;
        ldfr(0, 0, sbase);
        if (kt + 2 < NT) load_stage(kt + 2, (kt + 2) % 3);

#pragma unroll
        for (int s = 0; s < 4; s++) {
            if (s < 3) ldfr((s + 1) & 1, s + 1, sbase);
            do_mma(s & 1);
        }
    }

    const float SC = 0.015625f;   // 2^-6 (weights were scaled x64)
    const int g  = lane >> 2;
    const int qc = lane & 3;
#pragma unroll
    for (int t = 0; t < 2; t++) {
        const int row = by * 128 + warp_m * 32 + t * 16 + g;
#pragma unroll
        for (int n = 0; n < 8; n++) {
            const int col = bx * 128 + warp_n * 64 + n * 8 + qc * 2;
            *(float2*)&C[(size_t)row * 4096 + col] =
                make_float2(acc[t][n][0] * SC, acc[t][n][1] * SC);
            *(float2*)&C[(size_t)(row + 8) * 4096 + col] =
                make_float2(acc[t][n][2] * SC, acc[t][n][3] * SC);
        }
    }
}

// ---------------------------------------------------------------------------
// RoPE
// ---------------------------------------------------------------------------
__global__ void rope_table(float* ct, float* st)
{
    int idx = blockIdx.x * 256 + threadIdx.x;
    if (idx >= SEQ * (HD / 2)) return;
    int s = idx >> 6;
    int j = idx & 63;
    double inv = pow(10000.0, -(double)(2 * j) / 128.0);
    double a = (double)s * inv;
    ct[idx] = (float)cos(a);
    st[idx] = (float)sin(a);
}

__global__ void rope_apply(float* __restrict__ q, float* __restrict__ k,
                           const float* __restrict__ ct, const float* __restrict__ st)
{
    int idx = blockIdx.x * 256 + threadIdx.x;
    if (idx >= BSZ * SEQ * NH * (HD / 2)) return;
    int j = idx & 63;
    int h = (idx >> 6) & 31;
    int s = (idx >> 11) & 2047;
    int b = idx >> 22;
    size_t base = (((size_t)(b * SEQ + s) * NH + h) << 7) + 2 * j;
    float c  = ct[s * 64 + j];
    float sn = st[s * 64 + j];
    float2 xq = *(float2*)&q[base];
    float2 xk = *(float2*)&k[base];
    float2 oq, ok;
    oq.x = xq.x * c - xq.y * sn;
    oq.y = xq.x * sn + xq.y * c;
    ok.x = xk.x * c - xk.y * sn;
    ok.y = xk.x * sn + xk.y * c;
    *(float2*)&q[base] = oq;
    *(float2*)&k[base] = ok;
}

// ---------------------------------------------------------------------------
// Tensor-core causal flash attention (tf32 mma.m16n8k8).
// Epilogue writes fp16 activations for the wo GEMM.
// ---------------------------------------------------------------------------
#define KS_STRIDE 132
#define PS_STRIDE 68
#define ATTN_SMEM ((2*64*KS_STRIDE + 4*16*PS_STRIDE) * 4)

__global__ void __launch_bounds__(128)
attn_tc(const float* __restrict__ Q, const float* __restrict__ Kg,
        const float* __restrict__ Vg, __half* __restrict__ O16)
{
    extern __shared__ float smf[];
    float* Ks = smf;
    float* Vs = smf + 64 * KS_STRIDE;
    float* Ps = smf + 2 * 64 * KS_STRIDE;

    const int tid  = threadIdx.x;
    const int w    = tid >> 5;
    const int lane = tid & 31;
    const int qt = blockIdx.x;
    const int h  = blockIdx.y;
    const int b  = blockIdx.z;
    const int g  = lane >> 2;
    const int qc = lane & 3;
    float* Pw = Ps + w * 16 * PS_STRIDE;

    const float scale = 0.08838834764831845f;
    const int q0 = qt * 64 + w * 16;

    uint32_t qa[16][4];
    {
        const float* q_r0 = Q + ((size_t)b * SEQ + q0 + g)     * 4096 + h * 128;
        const float* q_r1 = Q + ((size_t)b * SEQ + q0 + g + 8) * 4096 + h * 128;
#pragma unroll
        for (int kc = 0; kc < 16; kc++) {
            qa[kc][0] = to_tf32(q_r0[kc * 8 + qc]     * scale);
            qa[kc][1] = to_tf32(q_r1[kc * 8 + qc]     * scale);
            qa[kc][2] = to_tf32(q_r0[kc * 8 + qc + 4] * scale);
            qa[kc][3] = to_tf32(q_r1[kc * 8 + qc + 4] * scale);
        }
    }

    float o[16][4];
#pragma unroll
    for (int n = 0; n < 16; n++)
#pragma unroll
        for (int j = 0; j < 4; j++) o[n][j] = 0.0f;
    float m0 = -1e30f, m1 = -1e30f, l0 = 0.0f, l1 = 0.0f;

    for (int kt = 0; kt <= qt; kt++) {
        if (kt) __syncthreads();
#pragma unroll
        for (int i = 0; i < 16; i++) {
            int li = tid + i * 128;
            int row = li >> 5, c4 = li & 31;
            size_t gsrc = ((size_t)b * SEQ + kt * 64 + row) * 4096 + h * 128 + c4 * 4;
            float4 kv = *(const float4*)&Kg[gsrc];
            float4 vv = *(const float4*)&Vg[gsrc];
            uint4 kb = make_uint4(to_tf32(kv.x), to_tf32(kv.y), to_tf32(kv.z), to_tf32(kv.w));
            uint4 vb = make_uint4(to_tf32(vv.x), to_tf32(vv.y), to_tf32(vv.z), to_tf32(vv.w));
            *(uint4*)&Ks[row * KS_STRIDE + c4 * 4] = kb;
            *(uint4*)&Vs[row * KS_STRIDE + c4 * 4] = vb;
        }
        __syncthreads();

        float sreg[8][4];
#pragma unroll
        for (int j = 0; j < 8; j++) {
            sreg[j][0] = sreg[j][1] = sreg[j][2] = sreg[j][3] = 0.0f;
            const uint32_t* krow = (const uint32_t*)&Ks[(j * 8 + g) * KS_STRIDE];
#pragma unroll
            for (int kc = 0; kc < 16; kc++)
                mma_tf32(sreg[j], qa[kc], krow[kc * 8 + qc], krow[kc * 8 + qc + 4]);
        }

        if (kt == qt) {
            const int kb = kt * 64;
#pragma unroll
            for (int j = 0; j < 8; j++) {
                int key0 = kb + j * 8 + 2 * qc;
                if (key0     > q0 + g)     sreg[j][0] = -1e30f;
                if (key0 + 1 > q0 + g)     sreg[j][1] = -1e30f;
                if (key0     > q0 + g + 8) sreg[j][2] = -1e30f;
                if (key0 + 1 > q0 + g + 8) sreg[j][3] = -1e30f;
            }
        }

        float mx0 = -1e30f, mx1 = -1e30f;
#pragma unroll
        for (int j = 0; j < 8; j++) {
            mx0 = fmaxf(mx0, fmaxf(sreg[j][0], sreg[j][1]));
            mx1 = fmaxf(mx1, fmaxf(sreg[j][2], sreg[j][3]));
        }
        mx0 = fmaxf(mx0, __shfl_xor_sync(0xffffffffu, mx0, 1));
        mx0 = fmaxf(mx0, __shfl_xor_sync(0xffffffffu, mx0, 2));
        mx1 = fmaxf(mx1, __shfl_xor_sync(0xffffffffu, mx1, 1));
        mx1 = fmaxf(mx1, __shfl_xor_sync(0xffffffffu, mx1, 2));
        float mn0 = fmaxf(m0, mx0), mn1 = fmaxf(m1, mx1);
        float f0 = __expf(m0 - mn0), f1 = __expf(m1 - mn1);
        m0 = mn0; m1 = mn1;

        float sum0 = 0.0f, sum1 = 0.0f;
        uint32_t* PwU = (uint32_t*)Pw;
#pragma unroll
        for (int j = 0; j < 8; j++) {
            float p0 = __expf(sreg[j][0] - mn0);
            float p1 = __expf(sreg[j][1] - mn0);
            float p2 = __expf(sreg[j][2] - mn1);
            float p3 = __expf(sreg[j][3] - mn1);
            sum0 += p0 + p1;
            sum1 += p2 + p3;
            PwU[g * PS_STRIDE       + j * 8 + 2 * qc]     = to_tf32(p0);
            PwU[g * PS_STRIDE       + j * 8 + 2 * qc + 1] = to_tf32(p1);
            PwU[(g + 8) * PS_STRIDE + j * 8 + 2 * qc]     = to_tf32(p2);
            PwU[(g + 8) * PS_STRIDE + j * 8 + 2 * qc + 1] = to_tf32(p3);
        }
        sum0 += __shfl_xor_sync(0xffffffffu, sum0, 1);
        sum0 += __shfl_xor_sync(0xffffffffu, sum0, 2);
        sum1 += __shfl_xor_sync(0xffffffffu, sum1, 1);
        sum1 += __shfl_xor_sync(0xffffffffu, sum1, 2);
        l0 = l0 * f0 + sum0;
        l1 = l1 * f1 + sum1;

#pragma unroll
        for (int n = 0; n < 16; n++) {
            o[n][0] *= f0; o[n][1] *= f0;
            o[n][2] *= f1; o[n][3] *= f1;
        }
        __syncwarp();

        uint32_t pa[8][4];
#pragma unroll
        for (int kc = 0; kc < 8; kc++) {
            pa[kc][0] = PwU[g * PS_STRIDE       + kc * 8 + qc];
            pa[kc][1] = PwU[(g + 8) * PS_STRIDE + kc * 8 + qc];
            pa[kc][2] = PwU[g * PS_STRIDE       + kc * 8 + qc + 4];
            pa[kc][3] = PwU[(g + 8) * PS_STRIDE + kc * 8 + qc + 4];
        }

#pragma unroll
        for (int n = 0; n < 16; n++) {
#pragma unroll
            for (int kc = 0; kc < 8; kc++) {
                uint32_t b0 = ((const uint32_t*)Vs)[(kc * 8 + qc)     * KS_STRIDE + n * 8 + g];
                uint32_t b1 = ((const uint32_t*)Vs)[(kc * 8 + qc + 4) * KS_STRIDE + n * 8 + g];
                mma_tf32(o[n], pa[kc], b0, b1);
            }
        }
    }

    const float inv0 = 1.0f / l0;
    const float inv1 = 1.0f / l1;
    const size_t base0 = ((size_t)b * SEQ + q0 + g)     * 4096 + h * 128;
    const size_t base1 = ((size_t)b * SEQ + q0 + g + 8) * 4096 + h * 128;
#pragma unroll
    for (int n = 0; n < 16; n++) {
        *(__half2*)&O16[base0 + n * 8 + 2 * qc] =
            __floats2half2_rn(o[n][0] * inv0, o[n][1] * inv0);
        *(__half2*)&O16[base1 + n * 8 + 2 * qc] =
            __floats2half2_rn(o[n][2] * inv1, o[n][3] * inv1);
    }
}

// ---------------------------------------------------------------------------
extern "C" void kernel_launch(void* const* d_in, const int* in_sizes, int n_in,
                              void* d_out, int out_size)
{
    const float* x = (const float*)d_in[0];
    int off = (n_in >= 6 && in_sizes[1] <= 4) ? 2 : 1;
    const float* wq = (const float*)d_in[off + 0];
    const float* wk = (const float*)d_in[off + 1];
    const float* wv = (const float*)d_in[off + 2];
    const float* wo = (const float*)d_in[off + 3];
    float* out = (float*)d_out;

    float *q, *k, *v, *ct, *st;
    cudaGetSymbolAddress((void**)&q,  g_q);
    cudaGetSymbolAddress((void**)&k,  g_k);
    cudaGetSymbolAddress((void**)&v,  g_v);
    cudaGetSymbolAddress((void**)&ct, g_cos);
    cudaGetSymbolAddress((void**)&st, g_sin);

    __half *x16, *wqh, *wql, *wkh, *wkl, *wvh, *wvl, *woh, *wol, *a16;
    cudaGetSymbolAddress((void**)&x16, g_x16);
    cudaGetSymbolAddress((void**)&wqh, g_wqh);  cudaGetSymbolAddress((void**)&wql, g_wql);
    cudaGetSymbolAddress((void**)&wkh, g_wkh);  cudaGetSymbolAddress((void**)&wkl, g_wkl);
    cudaGetSymbolAddress((void**)&wvh, g_wvh);  cudaGetSymbolAddress((void**)&wvl, g_wvl);
    cudaGetSymbolAddress((void**)&woh, g_woh);  cudaGetSymbolAddress((void**)&wol, g_wol);
    cudaGetSymbolAddress((void**)&a16, g_a16);

    cudaFuncSetAttribute(gemm_mma, cudaFuncAttributeMaxDynamicSharedMemorySize, 3 * STAGE_SZ);
    cudaFuncSetAttribute(attn_tc,  cudaFuncAttributeMaxDynamicSharedMemorySize, ATTN_SMEM);

    const int n4 = DIM * DIM / 4;
    const int cgrid = (n4 + 255) / 256;
    dim3 gg(DIM / 128, DIM / 128);

    split_act<<<cgrid, 256>>>(x, x16, n4);
    split_wt<<<cgrid, 256>>>(wq, wqh, wql, n4);
    split_wt<<<cgrid, 256>>>(wk, wkh, wkl, n4);
    split_wt<<<cgrid, 256>>>(wv, wvh, wvl, n4);
    split_wt<<<cgrid, 256>>>(wo, woh, wol, n4);

    gemm_mma<<<gg, 256, 3 * STAGE_SZ>>>(x16, wqh, wql, q);
    gemm_mma<<<gg, 256, 3 * STAGE_SZ>>>(x16, wkh, wkl, k);
    gemm_mma<<<gg, 256, 3 * STAGE_SZ>>>(x16, wvh, wvl, v);

    rope_table<<<(SEQ * (HD / 2) + 255) / 256, 256>>>(ct, st);
    rope_apply<<<(BSZ * SEQ * NH * (HD / 2) + 255) / 256, 256>>>(q, k, ct, st);

    attn_tc<<<dim3(SEQ / 64, NH, BSZ), 128, ATTN_SMEM>>>(q, k, v, a16);

    gemm_mma<<<gg, 256, 3 * STAGE_SZ>>>(a16, woh, wol, out);
}

// round 9
// speedup vs baseline: 1.6077x; 1.0272x over previous
#include <cuda_runtime.h>
#include <cuda_fp16.h>
#include <cstdint>
#include <math.h>

#define DIM   4096
#define NH    32
#define HD    128
#define BSZ   2
#define SEQ   2048

// ---------------- scratch (__device__ globals; no allocs allowed) ----------
__device__ __half g_q[BSZ*SEQ*DIM];
__device__ __half g_k[BSZ*SEQ*DIM];
__device__ __half g_v[BSZ*SEQ*DIM];
__device__ float  g_cos[SEQ*(HD/2)];
__device__ float  g_sin[SEQ*(HD/2)];

// fp16 buffers: activations single, weights hi/lo (scaled x64)
__device__ __half g_x16[DIM*DIM];
__device__ __half g_wqh[DIM*DIM], g_wql[DIM*DIM];
__device__ __half g_wkh[DIM*DIM], g_wkl[DIM*DIM];
__device__ __half g_wvh[DIM*DIM], g_wvl[DIM*DIM];
__device__ __half g_woh[DIM*DIM], g_wol[DIM*DIM];
__device__ __half g_a16[DIM*DIM];

// ---------------- base-ISA helpers (compute_103-safe) ----------------------
__device__ __forceinline__ uint32_t smem_u32(const void* p) {
    uint32_t a;
    asm("{ .reg .u64 t; cvta.to.shared.u64 t, %1; cvt.u32.u64 %0, t; }" : "=r"(a) : "l"(p));
    return a;
}
__device__ __forceinline__ void cpa16(uint32_t saddr, const void* g) {
    asm volatile("cp.async.cg.shared.global [%0], [%1], 16;" :: "r"(saddr), "l"(g));
}
__device__ __forceinline__ void ldsm4(uint32_t* r, uint32_t addr) {
    asm volatile("ldmatrix.sync.aligned.m8n8.x4.shared.b16 {%0,%1,%2,%3}, [%4];"
        : "=r"(r[0]), "=r"(r[1]), "=r"(r[2]), "=r"(r[3]) : "r"(addr));
}
__device__ __forceinline__ void mma_f16(float* c, const uint32_t* a,
                                        uint32_t b0, uint32_t b1) {
    asm volatile("mma.sync.aligned.m16n8k16.row.col.f32.f16.f16.f32 "
        "{%0,%1,%2,%3}, {%4,%5,%6,%7}, {%8,%9}, {%0,%1,%2,%3};"
        : "+f"(c[0]), "+f"(c[1]), "+f"(c[2]), "+f"(c[3])
        : "r"(a[0]), "r"(a[1]), "r"(a[2]), "r"(a[3]), "r"(b0), "r"(b1));
}
__device__ __forceinline__ void mma_tf32(float* c, const uint32_t* a,
                                         uint32_t b0, uint32_t b1) {
    asm volatile("mma.sync.aligned.m16n8k8.row.col.f32.tf32.tf32.f32 "
        "{%0,%1,%2,%3}, {%4,%5,%6,%7}, {%8,%9}, {%0,%1,%2,%3};"
        : "+f"(c[0]), "+f"(c[1]), "+f"(c[2]), "+f"(c[3])
        : "r"(a[0]), "r"(a[1]), "r"(a[2]), "r"(a[3]), "r"(b0), "r"(b1));
}
__device__ __forceinline__ uint32_t to_tf32(float x) {
    uint32_t r;
    asm("cvt.rna.tf32.f32 %0, %1;" : "=r"(r) : "f"(x));
    return r;
}
__device__ __forceinline__ uint32_t sw128(uint32_t off) {
    return off ^ ((off >> 3) & 0x70);
}

// ---------------------------------------------------------------------------
// splits
// ---------------------------------------------------------------------------
__global__ void split_act(const float* __restrict__ in, __half* __restrict__ o, int n4)
{
    int i = blockIdx.x * 256 + threadIdx.x;
    if (i >= n4) return;
    float4 v = ((const float4*)in)[i];
    ((__half2*)o)[2*i]   = __floats2half2_rn(v.x, v.y);
    ((__half2*)o)[2*i+1] = __floats2half2_rn(v.z, v.w);
}

// weights: wh = rn16(64w), wl = rn16(64w - wh)
__global__ void split_wt(const float* __restrict__ in,
                         __half* __restrict__ hi, __half* __restrict__ lo, int n4)
{
    int i = blockIdx.x * 256 + threadIdx.x;
    if (i >= n4) return;
    float4 v = ((const float4*)in)[i];
    v.x *= 64.f; v.y *= 64.f; v.z *= 64.f; v.w *= 64.f;
    __half2 h01 = __floats2half2_rn(v.x, v.y);
    __half2 h23 = __floats2half2_rn(v.z, v.w);
    float2 f01 = __half22float2(h01);
    float2 f23 = __half22float2(h23);
    ((__half2*)hi)[2*i]   = h01;
    ((__half2*)hi)[2*i+1] = h23;
    ((__half2*)lo)[2*i]   = __floats2half2_rn(v.x - f01.x, v.y - f01.y);
    ((__half2*)lo)[2*i+1] = __floats2half2_rn(v.z - f23.x, v.w - f23.y);
}

// ---------------------------------------------------------------------------
// fp16 2-product GEMM (NT): C = sc * A16*(Bh + Bl), 4096^3.
// CTA 128x128, BK=64 (SW128), 8 warps (4Mx2N), warp tile 32x64,
// 3-stage cp.async + fragment double-buffering; mma in 2 independent passes.
// Output fp16 (q/k/v) or fp32 (final), selected by Ch != nullptr.
// ---------------------------------------------------------------------------
#define STAGE_SZ 49152
__global__ void __launch_bounds__(256, 1)
gemm_mma(const __half* __restrict__ A16,
         const __half* __restrict__ Bh16, const __half* __restrict__ Bl16,
         __half* __restrict__ Ch, float* __restrict__ Cf, float sc)
{
    extern __shared__ char sm[];
    const uint32_t s0 = smem_u32(sm);

    const int tid  = threadIdx.x;
    const int wid  = tid >> 5;
    const int lane = tid & 31;
    const int bx = blockIdx.x;
    const int by = blockIdx.y;
    const int warp_m = wid >> 1;
    const int warp_n = wid & 1;

    float acc[2][8][4];
#pragma unroll
    for (int t = 0; t < 2; t++)
#pragma unroll
        for (int n = 0; n < 8; n++)
#pragma unroll
            for (int j = 0; j < 4; j++) acc[t][n][j] = 0.0f;

    auto load_stage = [&](int kt, int stage) {
        uint32_t sb = s0 + stage * STAGE_SZ;
#pragma unroll
        for (int i = 0; i < 4; i++) {
            int li = tid + i * 256;
            int r = li >> 3, c = li & 7;
            uint32_t off = sw128((uint32_t)(r * 128 + c * 16));
            cpa16(sb + off,         A16  + (size_t)(by * 128 + r) * 4096 + kt * 64 + c * 8);
            cpa16(sb + 16384 + off, Bh16 + (size_t)(bx * 128 + r) * 4096 + kt * 64 + c * 8);
            cpa16(sb + 32768 + off, Bl16 + (size_t)(bx * 128 + r) * 4096 + kt * 64 + c * 8);
        }
        asm volatile("cp.async.commit_group;" ::: "memory");
    };

    const int lrow  = (lane & 7) + ((lane >> 3) & 1) * 8;
    const int khalf = (lane >> 4) * 16;

    uint32_t ah[2][2][4], bh[2][4][4], bl[2][4][4];

    auto ldfr = [&](int buf, int s, uint32_t sbase) {
#pragma unroll
        for (int t = 0; t < 2; t++) {
            uint32_t off = sw128((uint32_t)((warp_m * 32 + t * 16 + lrow) * 128
                                            + khalf + s * 32));
            ldsm4(ah[buf][t], sbase + off);
        }
#pragma unroll
        for (int u = 0; u < 4; u++) {
            uint32_t off = sw128((uint32_t)((warp_n * 64 + u * 16 + lrow) * 128
                                            + khalf + s * 32));
            ldsm4(bh[buf][u], sbase + 16384 + off);
            ldsm4(bl[buf][u], sbase + 32768 + off);
        }
    };

    auto do_mma = [&](int buf) {
        // pass 1: all hi products (16 independent accumulators)
#pragma unroll
        for (int t = 0; t < 2; t++)
#pragma unroll
            for (int u = 0; u < 4; u++)
#pragma unroll
                for (int j = 0; j < 2; j++)
                    mma_f16(acc[t][u * 2 + j], ah[buf][t], bh[buf][u][j], bh[buf][u][j + 2]);
        // pass 2: all lo products
#pragma unroll
        for (int t = 0; t < 2; t++)
#pragma unroll
            for (int u = 0; u < 4; u++)
#pragma unroll
                for (int j = 0; j < 2; j++)
                    mma_f16(acc[t][u * 2 + j], ah[buf][t], bl[buf][u][j], bl[buf][u][j + 2]);
    };

    const int NT = 4096 / 64;

    load_stage(0, 0);
    load_stage(1, 1);

    for (int kt = 0; kt < NT; kt++) {
        if (kt < NT - 1) asm volatile("cp.async.wait_group 1;" ::: "memory");
        else             asm volatile("cp.async.wait_group 0;" ::: "memory");
        __syncthreads();

        const uint32_t sbase = s0 + (kt % 3) * STAGE_SZ;
        ldfr(0, 0, sbase);
        if (kt + 2 < NT) load_stage(kt + 2, (kt + 2) % 3);

#pragma unroll
        for (int s = 0; s < 4; s++) {
            if (s < 3) ldfr((s + 1) & 1, s + 1, sbase);
            do_mma(s & 1);
        }
    }

    const int g  = lane >> 2;
    const int qc = lane & 3;
    if (Ch) {
#pragma unroll
        for (int t = 0; t < 2; t++) {
            const int row = by * 128 + warp_m * 32 + t * 16 + g;
#pragma unroll
            for (int n = 0; n < 8; n++) {
                const int col = bx * 128 + warp_n * 64 + n * 8 + qc * 2;
                *(__half2*)&Ch[(size_t)row * 4096 + col] =
                    __floats2half2_rn(acc[t][n][0] * sc, acc[t][n][1] * sc);
                *(__half2*)&Ch[(size_t)(row + 8) * 4096 + col] =
                    __floats2half2_rn(acc[t][n][2] * sc, acc[t][n][3] * sc);
            }
        }
    } else {
#pragma unroll
        for (int t = 0; t < 2; t++) {
            const int row = by * 128 + warp_m * 32 + t * 16 + g;
#pragma unroll
            for (int n = 0; n < 8; n++) {
                const int col = bx * 128 + warp_n * 64 + n * 8 + qc * 2;
                *(float2*)&Cf[(size_t)row * 4096 + col] =
                    make_float2(acc[t][n][0] * sc, acc[t][n][1] * sc);
                *(float2*)&Cf[(size_t)(row + 8) * 4096 + col] =
                    make_float2(acc[t][n][2] * sc, acc[t][n][3] * sc);
            }
        }
    }
}

// ---------------------------------------------------------------------------
// RoPE (fp16 q/k)
// ---------------------------------------------------------------------------
__global__ void rope_table(float* ct, float* st)
{
    int idx = blockIdx.x * 256 + threadIdx.x;
    if (idx >= SEQ * (HD / 2)) return;
    int s = idx >> 6;
    int j = idx & 63;
    double inv = pow(10000.0, -(double)(2 * j) / 128.0);
    double a = (double)s * inv;
    ct[idx] = (float)cos(a);
    st[idx] = (float)sin(a);
}

__global__ void rope_apply(__half* __restrict__ q, __half* __restrict__ k,
                           const float* __restrict__ ct, const float* __restrict__ st)
{
    int idx = blockIdx.x * 256 + threadIdx.x;
    if (idx >= BSZ * SEQ * NH * (HD / 2)) return;
    int j = idx & 63;
    int h = (idx >> 6) & 31;
    int s = (idx >> 11) & 2047;
    int b = idx >> 22;
    size_t base = (((size_t)(b * SEQ + s) * NH + h) << 7) + 2 * j;
    float c  = ct[s * 64 + j];
    float sn = st[s * 64 + j];
    float2 xq = __half22float2(*(__half2*)&q[base]);
    float2 xk = __half22float2(*(__half2*)&k[base]);
    *(__half2*)&q[base] = __floats2half2_rn(xq.x * c - xq.y * sn, xq.x * sn + xq.y * c);
    *(__half2*)&k[base] = __floats2half2_rn(xk.x * c - xk.y * sn, xk.x * sn + xk.y * c);
}

// ---------------------------------------------------------------------------
// Causal flash attention: fp16 QK^T (m16n8k16), tf32 PV (m16n8k8).
// Block = 128 threads (4 warps); Q tile 64 rows, K tile 64 keys.
// 1/sqrt(128) pre-folded into q by the q-GEMM.
// ---------------------------------------------------------------------------
#define KSW 68                      // K tile row stride in uint32 (half2)
#define VSW 132                     // V tile row stride in floats (tf32)
#define PSW 68                      // P row stride in uint32 (tf32)
#define ATTN_SMEM ((64*KSW + 64*VSW + 4*16*PSW) * 4)

__global__ void __launch_bounds__(128)
attn_tc(const __half* __restrict__ Qh, const __half* __restrict__ Kh,
        const __half* __restrict__ Vh, __half* __restrict__ O16)
{
    extern __shared__ uint32_t smu[];
    uint32_t* KsU = smu;                       // [64][KSW] fp16 pairs
    float*    Vs  = (float*)(smu + 64 * KSW);  // [64][VSW] tf32
    uint32_t* Ps  = smu + 64 * KSW + 64 * VSW; // per warp [16][PSW] tf32

    const int tid  = threadIdx.x;
    const int w    = tid >> 5;
    const int lane = tid & 31;
    const int qt = blockIdx.x;
    const int h  = blockIdx.y;
    const int b  = blockIdx.z;
    const int g  = lane >> 2;
    const int qc = lane & 3;
    uint32_t* PwU = Ps + w * 16 * PSW;

    const int q0 = qt * 64 + w * 16;

    // Q a-fragments (fp16, already scaled by 1/sqrt(128) in the q-GEMM)
    uint32_t qa[8][4];
    {
        const uint32_t* q_r0 = (const uint32_t*)(Qh + ((size_t)b * SEQ + q0 + g)     * 4096 + h * 128);
        const uint32_t* q_r1 = (const uint32_t*)(Qh + ((size_t)b * SEQ + q0 + g + 8) * 4096 + h * 128);
#pragma unroll
        for (int kc = 0; kc < 8; kc++) {
            qa[kc][0] = q_r0[kc * 8 + qc];
            qa[kc][1] = q_r1[kc * 8 + qc];
            qa[kc][2] = q_r0[kc * 8 + qc + 4];
            qa[kc][3] = q_r1[kc * 8 + qc + 4];
        }
    }

    float o[16][4];
#pragma unroll
    for (int n = 0; n < 16; n++)
#pragma unroll
        for (int j = 0; j < 4; j++) o[n][j] = 0.0f;
    float m0 = -1e30f, m1 = -1e30f, l0 = 0.0f, l1 = 0.0f;

    for (int kt = 0; kt <= qt; kt++) {
        if (kt) __syncthreads();
        // stage K (fp16 copy) + V (cvt to tf32)
#pragma unroll
        for (int i = 0; i < 8; i++) {
            int li = tid + i * 128;
            int row = li >> 4, c = li & 15;        // 16 x uint4 (8 halves) per row
            size_t gsrc = ((size_t)b * SEQ + kt * 64 + row) * 4096 + h * 128 + c * 8;
            uint4 kw = *(const uint4*)(Kh + gsrc);
            *(uint4*)&KsU[row * KSW + c * 4] = kw;
            uint4 vw = *(const uint4*)(Vh + gsrc);
            float2 f0 = __half22float2(*(__half2*)&vw.x);
            float2 f1 = __half22float2(*(__half2*)&vw.y);
            float2 f2 = __half22float2(*(__half2*)&vw.z);
            float2 f3 = __half22float2(*(__half2*)&vw.w);
            uint4 o0 = make_uint4(to_tf32(f0.x), to_tf32(f0.y), to_tf32(f1.x), to_tf32(f1.y));
            uint4 o1 = make_uint4(to_tf32(f2.x), to_tf32(f2.y), to_tf32(f3.x), to_tf32(f3.y));
            *(uint4*)&Vs[row * VSW + c * 8]     = o0;
            *(uint4*)&Vs[row * VSW + c * 8 + 4] = o1;
        }
        __syncthreads();

        // S = Q K^T (fp16 mma, kc outer -> 8 independent accumulators)
        float sreg[8][4];
#pragma unroll
        for (int j = 0; j < 8; j++) {
            sreg[j][0] = sreg[j][1] = sreg[j][2] = sreg[j][3] = 0.0f;
        }
#pragma unroll
        for (int kc = 0; kc < 8; kc++) {
#pragma unroll
            for (int j = 0; j < 8; j++) {
                const uint32_t* krow = &KsU[(j * 8 + g) * KSW];
                mma_f16(sreg[j], qa[kc], krow[kc * 8 + qc], krow[kc * 8 + qc + 4]);
            }
        }

        if (kt == qt) {
            const int kb = kt * 64;
#pragma unroll
            for (int j = 0; j < 8; j++) {
                int key0 = kb + j * 8 + 2 * qc;
                if (key0     > q0 + g)     sreg[j][0] = -1e30f;
                if (key0 + 1 > q0 + g)     sreg[j][1] = -1e30f;
                if (key0     > q0 + g + 8) sreg[j][2] = -1e30f;
                if (key0 + 1 > q0 + g + 8) sreg[j][3] = -1e30f;
            }
        }

        float mx0 = -1e30f, mx1 = -1e30f;
#pragma unroll
        for (int j = 0; j < 8; j++) {
            mx0 = fmaxf(mx0, fmaxf(sreg[j][0], sreg[j][1]));
            mx1 = fmaxf(mx1, fmaxf(sreg[j][2], sreg[j][3]));
        }
        mx0 = fmaxf(mx0, __shfl_xor_sync(0xffffffffu, mx0, 1));
        mx0 = fmaxf(mx0, __shfl_xor_sync(0xffffffffu, mx0, 2));
        mx1 = fmaxf(mx1, __shfl_xor_sync(0xffffffffu, mx1, 1));
        mx1 = fmaxf(mx1, __shfl_xor_sync(0xffffffffu, mx1, 2));
        float mn0 = fmaxf(m0, mx0), mn1 = fmaxf(m1, mx1);
        float f0 = __expf(m0 - mn0), f1 = __expf(m1 - mn1);
        m0 = mn0; m1 = mn1;

        float sum0 = 0.0f, sum1 = 0.0f;
#pragma unroll
        for (int j = 0; j < 8; j++) {
            float p0 = __expf(sreg[j][0] - mn0);
            float p1 = __expf(sreg[j][1] - mn0);
            float p2 = __expf(sreg[j][2] - mn1);
            float p3 = __expf(sreg[j][3] - mn1);
            sum0 += p0 + p1;
            sum1 += p2 + p3;
            PwU[g * PSW       + j * 8 + 2 * qc]     = to_tf32(p0);
            PwU[g * PSW       + j * 8 + 2 * qc + 1] = to_tf32(p1);
            PwU[(g + 8) * PSW + j * 8 + 2 * qc]     = to_tf32(p2);
            PwU[(g + 8) * PSW + j * 8 + 2 * qc + 1] = to_tf32(p3);
        }
        sum0 += __shfl_xor_sync(0xffffffffu, sum0, 1);
        sum0 += __shfl_xor_sync(0xffffffffu, sum0, 2);
        sum1 += __shfl_xor_sync(0xffffffffu, sum1, 1);
        sum1 += __shfl_xor_sync(0xffffffffu, sum1, 2);
        l0 = l0 * f0 + sum0;
        l1 = l1 * f1 + sum1;

#pragma unroll
        for (int n = 0; n < 16; n++) {
            o[n][0] *= f0; o[n][1] *= f0;
            o[n][2] *= f1; o[n][3] *= f1;
        }
        __syncwarp();

        // O += P V (tf32, kc outer -> 16 independent accumulators)
#pragma unroll
        for (int kc = 0; kc < 8; kc++) {
            uint32_t pa[4];
            pa[0] = PwU[g * PSW       + kc * 8 + qc];
            pa[1] = PwU[(g + 8) * PSW + kc * 8 + qc];
            pa[2] = PwU[g * PSW       + kc * 8 + qc + 4];
            pa[3] = PwU[(g + 8) * PSW + kc * 8 + qc + 4];
            const uint32_t* v0 = (const uint32_t*)&Vs[(kc * 8 + qc)     * VSW];
            const uint32_t* v1 = (const uint32_t*)&Vs[(kc * 8 + qc + 4) * VSW];
#pragma unroll
            for (int n = 0; n < 16; n++)
                mma_tf32(o[n], pa, v0[n * 8 + g], v1[n * 8 + g]);
        }
    }

    const float inv0 = 1.0f / l0;
    const float inv1 = 1.0f / l1;
    const size_t base0 = ((size_t)b * SEQ + q0 + g)     * 4096 + h * 128;
    const size_t base1 = ((size_t)b * SEQ + q0 + g + 8) * 4096 + h * 128;
#pragma unroll
    for (int n = 0; n < 16; n++) {
        *(__half2*)&O16[base0 + n * 8 + 2 * qc] =
            __floats2half2_rn(o[n][0] * inv0, o[n][1] * inv0);
        *(__half2*)&O16[base1 + n * 8 + 2 * qc] =
            __floats2half2_rn(o[n][2] * inv1, o[n][3] * inv1);
    }
}

// ---------------------------------------------------------------------------
extern "C" void kernel_launch(void* const* d_in, const int* in_sizes, int n_in,
                              void* d_out, int out_size)
{
    const float* x = (const float*)d_in[0];
    int off = (n_in >= 6 && in_sizes[1] <= 4) ? 2 : 1;
    const float* wq = (const float*)d_in[off + 0];
    const float* wk = (const float*)d_in[off + 1];
    const float* wv = (const float*)d_in[off + 2];
    const float* wo = (const float*)d_in[off + 3];
    float* out = (float*)d_out;

    __half *q, *k, *v;
    float *ct, *st;
    cudaGetSymbolAddress((void**)&q,  g_q);
    cudaGetSymbolAddress((void**)&k,  g_k);
    cudaGetSymbolAddress((void**)&v,  g_v);
    cudaGetSymbolAddress((void**)&ct, g_cos);
    cudaGetSymbolAddress((void**)&st, g_sin);

    __half *x16, *wqh, *wql, *wkh, *wkl, *wvh, *wvl, *woh, *wol, *a16;
    cudaGetSymbolAddress((void**)&x16, g_x16);
    cudaGetSymbolAddress((void**)&wqh, g_wqh);  cudaGetSymbolAddress((void**)&wql, g_wql);
    cudaGetSymbolAddress((void**)&wkh, g_wkh);  cudaGetSymbolAddress((void**)&wkl, g_wkl);
    cudaGetSymbolAddress((void**)&wvh, g_wvh);  cudaGetSymbolAddress((void**)&wvl, g_wvl);
    cudaGetSymbolAddress((void**)&woh, g_woh);  cudaGetSymbolAddress((void**)&wol, g_wol);
    cudaGetSymbolAddress((void**)&a16, g_a16);

    cudaFuncSetAttribute(gemm_mma, cudaFuncAttributeMaxDynamicSharedMemorySize, 3 * STAGE_SZ);
    cudaFuncSetAttribute(attn_tc,  cudaFuncAttributeMaxDynamicSharedMemorySize, ATTN_SMEM);

    const int n4 = DIM * DIM / 4;
    const int cgrid = (n4 + 255) / 256;
    dim3 gg(DIM / 128, DIM / 128);

    const float SC   = 0.015625f;                        // 2^-6 (weights x64)
    const float SC_Q = SC * 0.08838834764831845f;        // fold 1/sqrt(128) into q

    // launch order: gemm_q at index 3 (profiler captures launch #3)
    split_act<<<cgrid, 256>>>(x, x16, n4);                               // 0
    split_wt<<<cgrid, 256>>>(wq, wqh, wql, n4);                          // 1
    split_wt<<<cgrid, 256>>>(wk, wkh, wkl, n4);                          // 2
    gemm_mma<<<gg, 256, 3 * STAGE_SZ>>>(x16, wqh, wql, q, nullptr, SC_Q); // 3
    split_wt<<<cgrid, 256>>>(wv, wvh, wvl, n4);                          // 4
    gemm_mma<<<gg, 256, 3 * STAGE_SZ>>>(x16, wkh, wkl, k, nullptr, SC);   // 5
    split_wt<<<cgrid, 256>>>(wo, woh, wol, n4);                          // 6
    gemm_mma<<<gg, 256, 3 * STAGE_SZ>>>(x16, wvh, wvl, v, nullptr, SC);   // 7

    rope_table<<<(SEQ * (HD / 2) + 255) / 256, 256>>>(ct, st);           // 8
    rope_apply<<<(BSZ * SEQ * NH * (HD / 2) + 255) / 256, 256>>>(q, k, ct, st); // 9

    attn_tc<<<dim3(SEQ / 64, NH, BSZ), 128, ATTN_SMEM>>>(q, k, v, a16);  // 10

    gemm_mma<<<gg, 256, 3 * STAGE_SZ>>>(a16, woh, wol, nullptr, out, SC); // 11
}

// round 10
// speedup vs baseline: 1.7308x; 1.0766x over previous
#include <cuda_runtime.h>
#include <cuda_fp16.h>
#include <cstdint>
#include <math.h>

#define DIM   4096
#define NH    32
#define HD    128
#define BSZ   2
#define SEQ   2048

// ---------------- scratch (__device__ globals; no allocs allowed) ----------
__device__ __half g_q[BSZ*SEQ*DIM];
__device__ __half g_k[BSZ*SEQ*DIM];
__device__ __half g_v[BSZ*SEQ*DIM];
__device__ float  g_cos[SEQ*(HD/2)];
__device__ float  g_sin[SEQ*(HD/2)];

// fp16 buffers: activations single, weights hi/lo (scaled x64)
__device__ __half g_x16[DIM*DIM];
__device__ __half g_wqh[DIM*DIM], g_wql[DIM*DIM];
__device__ __half g_wkh[DIM*DIM], g_wkl[DIM*DIM];
__device__ __half g_wvh[DIM*DIM], g_wvl[DIM*DIM];
__device__ __half g_woh[DIM*DIM], g_wol[DIM*DIM];
__device__ __half g_a16[DIM*DIM];

// ---------------- base-ISA helpers (compute_103-safe) ----------------------
__device__ __forceinline__ uint32_t smem_u32(const void* p) {
    uint32_t a;
    asm("{ .reg .u64 t; cvta.to.shared.u64 t, %1; cvt.u32.u64 %0, t; }" : "=r"(a) : "l"(p));
    return a;
}
__device__ __forceinline__ void cpa16(uint32_t saddr, const void* g) {
    asm volatile("cp.async.cg.shared.global [%0], [%1], 16;" :: "r"(saddr), "l"(g));
}
__device__ __forceinline__ void ldsm4(uint32_t* r, uint32_t addr) {
    asm volatile("ldmatrix.sync.aligned.m8n8.x4.shared.b16 {%0,%1,%2,%3}, [%4];"
        : "=r"(r[0]), "=r"(r[1]), "=r"(r[2]), "=r"(r[3]) : "r"(addr));
}
__device__ __forceinline__ void mma_f16(float* c, const uint32_t* a,
                                        uint32_t b0, uint32_t b1) {
    asm volatile("mma.sync.aligned.m16n8k16.row.col.f32.f16.f16.f32 "
        "{%0,%1,%2,%3}, {%4,%5,%6,%7}, {%8,%9}, {%0,%1,%2,%3};"
        : "+f"(c[0]), "+f"(c[1]), "+f"(c[2]), "+f"(c[3])
        : "r"(a[0]), "r"(a[1]), "r"(a[2]), "r"(a[3]), "r"(b0), "r"(b1));
}
__device__ __forceinline__ void mma_tf32(float* c, const uint32_t* a,
                                         uint32_t b0, uint32_t b1) {
    asm volatile("mma.sync.aligned.m16n8k8.row.col.f32.tf32.tf32.f32 "
        "{%0,%1,%2,%3}, {%4,%5,%6,%7}, {%8,%9}, {%0,%1,%2,%3};"
        : "+f"(c[0]), "+f"(c[1]), "+f"(c[2]), "+f"(c[3])
        : "r"(a[0]), "r"(a[1]), "r"(a[2]), "r"(a[3]), "r"(b0), "r"(b1));
}
__device__ __forceinline__ uint32_t to_tf32(float x) {
    uint32_t r;
    asm("cvt.rna.tf32.f32 %0, %1;" : "=r"(r) : "f"(x));
    return r;
}
__device__ __forceinline__ uint32_t sw128(uint32_t off) {
    return off ^ ((off >> 3) & 0x70);
}

// ---------------------------------------------------------------------------
// splits
// ---------------------------------------------------------------------------
__global__ void split_act(const float* __restrict__ in, __half* __restrict__ o, int n4)
{
    int i = blockIdx.x * 256 + threadIdx.x;
    if (i >= n4) return;
    float4 v = ((const float4*)in)[i];
    ((__half2*)o)[2*i]   = __floats2half2_rn(v.x, v.y);
    ((__half2*)o)[2*i+1] = __floats2half2_rn(v.z, v.w);
}

// weights: wh = rn16(64w), wl = rn16(64w - wh)
__global__ void split_wt(const float* __restrict__ in,
                         __half* __restrict__ hi, __half* __restrict__ lo, int n4)
{
    int i = blockIdx.x * 256 + threadIdx.x;
    if (i >= n4) return;
    float4 v = ((const float4*)in)[i];
    v.x *= 64.f; v.y *= 64.f; v.z *= 64.f; v.w *= 64.f;
    __half2 h01 = __floats2half2_rn(v.x, v.y);
    __half2 h23 = __floats2half2_rn(v.z, v.w);
    float2 f01 = __half22float2(h01);
    float2 f23 = __half22float2(h23);
    ((__half2*)hi)[2*i]   = h01;
    ((__half2*)hi)[2*i+1] = h23;
    ((__half2*)lo)[2*i]   = __floats2half2_rn(v.x - f01.x, v.y - f01.y);
    ((__half2*)lo)[2*i+1] = __floats2half2_rn(v.z - f23.x, v.w - f23.y);
}

// ---------------------------------------------------------------------------
// fp16 2-product GEMM (NT): C = sc * A16*(Bh + Bl), 4096^3.
// CTA 128x128, BK=64 (SW128), 8 warps (4Mx2N), warp tile 32x64,
// 2-stage cp.async pipeline, 2 CTAs/SM (barrier bubbles covered by co-CTA).
// ---------------------------------------------------------------------------
#define STAGE_SZ 49152
__global__ void __launch_bounds__(256, 2)
gemm_mma(const __half* __restrict__ A16,
         const __half* __restrict__ Bh16, const __half* __restrict__ Bl16,
         __half* __restrict__ Ch, float* __restrict__ Cf, float sc)
{
    extern __shared__ char sm[];
    const uint32_t s0 = smem_u32(sm);

    const int tid  = threadIdx.x;
    const int wid  = tid >> 5;
    const int lane = tid & 31;
    const int bx = blockIdx.x;
    const int by = blockIdx.y;
    const int warp_m = wid >> 1;
    const int warp_n = wid & 1;

    float acc[2][8][4];
#pragma unroll
    for (int t = 0; t < 2; t++)
#pragma unroll
        for (int n = 0; n < 8; n++)
#pragma unroll
            for (int j = 0; j < 4; j++) acc[t][n][j] = 0.0f;

    auto load_stage = [&](int kt, int stage) {
        uint32_t sb = s0 + stage * STAGE_SZ;
#pragma unroll
        for (int i = 0; i < 4; i++) {
            int li = tid + i * 256;
            int r = li >> 3, c = li & 7;
            uint32_t off = sw128((uint32_t)(r * 128 + c * 16));
            cpa16(sb + off,         A16  + (size_t)(by * 128 + r) * 4096 + kt * 64 + c * 8);
            cpa16(sb + 16384 + off, Bh16 + (size_t)(bx * 128 + r) * 4096 + kt * 64 + c * 8);
            cpa16(sb + 32768 + off, Bl16 + (size_t)(bx * 128 + r) * 4096 + kt * 64 + c * 8);
        }
        asm volatile("cp.async.commit_group;" ::: "memory");
    };

    const int lrow  = (lane & 7) + ((lane >> 3) & 1) * 8;
    const int khalf = (lane >> 4) * 16;

    const int NT = 4096 / 64;

    load_stage(0, 0);

    for (int kt = 0; kt < NT; kt++) {
        asm volatile("cp.async.wait_group 0;" ::: "memory");
        __syncthreads();

        const uint32_t sbase = s0 + (kt & 1) * STAGE_SZ;
        if (kt + 1 < NT) load_stage(kt + 1, (kt + 1) & 1);

#pragma unroll
        for (int s = 0; s < 4; s++) {
            uint32_t ah[2][4], bh[4][4], bl[4][4];
#pragma unroll
            for (int t = 0; t < 2; t++) {
                uint32_t off = sw128((uint32_t)((warp_m * 32 + t * 16 + lrow) * 128
                                                + khalf + s * 32));
                ldsm4(ah[t], sbase + off);
            }
#pragma unroll
            for (int u = 0; u < 4; u++) {
                uint32_t off = sw128((uint32_t)((warp_n * 64 + u * 16 + lrow) * 128
                                                + khalf + s * 32));
                ldsm4(bh[u], sbase + 16384 + off);
                ldsm4(bl[u], sbase + 32768 + off);
            }
            // pass 1: all hi products (16 independent accumulators)
#pragma unroll
            for (int t = 0; t < 2; t++)
#pragma unroll
                for (int u = 0; u < 4; u++)
#pragma unroll
                    for (int j = 0; j < 2; j++)
                        mma_f16(acc[t][u * 2 + j], ah[t], bh[u][j], bh[u][j + 2]);
            // pass 2: all lo products
#pragma unroll
            for (int t = 0; t < 2; t++)
#pragma unroll
                for (int u = 0; u < 4; u++)
#pragma unroll
                    for (int j = 0; j < 2; j++)
                        mma_f16(acc[t][u * 2 + j], ah[t], bl[u][j], bl[u][j + 2]);
        }
    }

    const int g  = lane >> 2;
    const int qc = lane & 3;
    if (Ch) {
#pragma unroll
        for (int t = 0; t < 2; t++) {
            const int row = by * 128 + warp_m * 32 + t * 16 + g;
#pragma unroll
            for (int n = 0; n < 8; n++) {
                const int col = bx * 128 + warp_n * 64 + n * 8 + qc * 2;
                *(__half2*)&Ch[(size_t)row * 4096 + col] =
                    __floats2half2_rn(acc[t][n][0] * sc, acc[t][n][1] * sc);
                *(__half2*)&Ch[(size_t)(row + 8) * 4096 + col] =
                    __floats2half2_rn(acc[t][n][2] * sc, acc[t][n][3] * sc);
            }
        }
    } else {
#pragma unroll
        for (int t = 0; t < 2; t++) {
            const int row = by * 128 + warp_m * 32 + t * 16 + g;
#pragma unroll
            for (int n = 0; n < 8; n++) {
                const int col = bx * 128 + warp_n * 64 + n * 8 + qc * 2;
                *(float2*)&Cf[(size_t)row * 4096 + col] =
                    make_float2(acc[t][n][0] * sc, acc[t][n][1] * sc);
                *(float2*)&Cf[(size_t)(row + 8) * 4096 + col] =
                    make_float2(acc[t][n][2] * sc, acc[t][n][3] * sc);
            }
        }
    }
}

// ---------------------------------------------------------------------------
// RoPE (fp16 q/k)
// ---------------------------------------------------------------------------
__global__ void rope_table(float* ct, float* st)
{
    int idx = blockIdx.x * 256 + threadIdx.x;
    if (idx >= SEQ * (HD / 2)) return;
    int s = idx >> 6;
    int j = idx & 63;
    double inv = pow(10000.0, -(double)(2 * j) / 128.0);
    double a = (double)s * inv;
    ct[idx] = (float)cos(a);
    st[idx] = (float)sin(a);
}

__global__ void rope_apply(__half* __restrict__ q, __half* __restrict__ k,
                           const float* __restrict__ ct, const float* __restrict__ st)
{
    int idx = blockIdx.x * 256 + threadIdx.x;
    if (idx >= BSZ * SEQ * NH * (HD / 2)) return;
    int j = idx & 63;
    int h = (idx >> 6) & 31;
    int s = (idx >> 11) & 2047;
    int b = idx >> 22;
    size_t base = (((size_t)(b * SEQ + s) * NH + h) << 7) + 2 * j;
    float c  = ct[s * 64 + j];
    float sn = st[s * 64 + j];
    float2 xq = __half22float2(*(__half2*)&q[base]);
    float2 xk = __half22float2(*(__half2*)&k[base]);
    *(__half2*)&q[base] = __floats2half2_rn(xq.x * c - xq.y * sn, xq.x * sn + xq.y * c);
    *(__half2*)&k[base] = __floats2half2_rn(xk.x * c - xk.y * sn, xk.x * sn + xk.y * c);
}

// ---------------------------------------------------------------------------
// Causal flash attention: fp16 QK^T (m16n8k16), tf32 PV (m16n8k8).
// ---------------------------------------------------------------------------
#define KSW 68
#define VSW 132
#define PSW 68
#define ATTN_SMEM ((64*KSW + 64*VSW + 4*16*PSW) * 4)

__global__ void __launch_bounds__(128)
attn_tc(const __half* __restrict__ Qh, const __half* __restrict__ Kh,
        const __half* __restrict__ Vh, __half* __restrict__ O16)
{
    extern __shared__ uint32_t smu[];
    uint32_t* KsU = smu;
    float*    Vs  = (float*)(smu + 64 * KSW);
    uint32_t* Ps  = smu + 64 * KSW + 64 * VSW;

    const int tid  = threadIdx.x;
    const int w    = tid >> 5;
    const int lane = tid & 31;
    const int qt = blockIdx.x;
    const int h  = blockIdx.y;
    const int b  = blockIdx.z;
    const int g  = lane >> 2;
    const int qc = lane & 3;
    uint32_t* PwU = Ps + w * 16 * PSW;

    const int q0 = qt * 64 + w * 16;

    uint32_t qa[8][4];
    {
        const uint32_t* q_r0 = (const uint32_t*)(Qh + ((size_t)b * SEQ + q0 + g)     * 4096 + h * 128);
        const uint32_t* q_r1 = (const uint32_t*)(Qh + ((size_t)b * SEQ + q0 + g + 8) * 4096 + h * 128);
#pragma unroll
        for (int kc = 0; kc < 8; kc++) {
            qa[kc][0] = q_r0[kc * 8 + qc];
            qa[kc][1] = q_r1[kc * 8 + qc];
            qa[kc][2] = q_r0[kc * 8 + qc + 4];
            qa[kc][3] = q_r1[kc * 8 + qc + 4];
        }
    }

    float o[16][4];
#pragma unroll
    for (int n = 0; n < 16; n++)
#pragma unroll
        for (int j = 0; j < 4; j++) o[n][j] = 0.0f;
    float m0 = -1e30f, m1 = -1e30f, l0 = 0.0f, l1 = 0.0f;

    for (int kt = 0; kt <= qt; kt++) {
        if (kt) __syncthreads();
#pragma unroll
        for (int i = 0; i < 8; i++) {
            int li = tid + i * 128;
            int row = li >> 4, c = li & 15;
            size_t gsrc = ((size_t)b * SEQ + kt * 64 + row) * 4096 + h * 128 + c * 8;
            uint4 kw = *(const uint4*)(Kh + gsrc);
            *(uint4*)&KsU[row * KSW + c * 4] = kw;
            uint4 vw = *(const uint4*)(Vh + gsrc);
            float2 f0 = __half22float2(*(__half2*)&vw.x);
            float2 f1 = __half22float2(*(__half2*)&vw.y);
            float2 f2 = __half22float2(*(__half2*)&vw.z);
            float2 f3 = __half22float2(*(__half2*)&vw.w);
            uint4 o0 = make_uint4(to_tf32(f0.x), to_tf32(f0.y), to_tf32(f1.x), to_tf32(f1.y));
            uint4 o1 = make_uint4(to_tf32(f2.x), to_tf32(f2.y), to_tf32(f3.x), to_tf32(f3.y));
            *(uint4*)&Vs[row * VSW + c * 8]     = o0;
            *(uint4*)&Vs[row * VSW + c * 8 + 4] = o1;
        }
        __syncthreads();

        float sreg[8][4];
#pragma unroll
        for (int j = 0; j < 8; j++) {
            sreg[j][0] = sreg[j][1] = sreg[j][2] = sreg[j][3] = 0.0f;
        }
#pragma unroll
        for (int kc = 0; kc < 8; kc++) {
#pragma unroll
            for (int j = 0; j < 8; j++) {
                const uint32_t* krow = &KsU[(j * 8 + g) * KSW];
                mma_f16(sreg[j], qa[kc], krow[kc * 8 + qc], krow[kc * 8 + qc + 4]);
            }
        }

        if (kt == qt) {
            const int kb = kt * 64;
#pragma unroll
            for (int j = 0; j < 8; j++) {
                int key0 = kb + j * 8 + 2 * qc;
                if (key0     > q0 + g)     sreg[j][0] = -1e30f;
                if (key0 + 1 > q0 + g)     sreg[j][1] = -1e30f;
                if (key0     > q0 + g + 8) sreg[j][2] = -1e30f;
                if (key0 + 1 > q0 + g + 8) sreg[j][3] = -1e30f;
            }
        }

        float mx0 = -1e30f, mx1 = -1e30f;
#pragma unroll
        for (int j = 0; j < 8; j++) {
            mx0 = fmaxf(mx0, fmaxf(sreg[j][0], sreg[j][1]));
            mx1 = fmaxf(mx1, fmaxf(sreg[j][2], sreg[j][3]));
        }
        mx0 = fmaxf(mx0, __shfl_xor_sync(0xffffffffu, mx0, 1));
        mx0 = fmaxf(mx0, __shfl_xor_sync(0xffffffffu, mx0, 2));
        mx1 = fmaxf(mx1, __shfl_xor_sync(0xffffffffu, mx1, 1));
        mx1 = fmaxf(mx1, __shfl_xor_sync(0xffffffffu, mx1, 2));
        float mn0 = fmaxf(m0, mx0), mn1 = fmaxf(m1, mx1);
        float f0 = __expf(m0 - mn0), f1 = __expf(m1 - mn1);
        m0 = mn0; m1 = mn1;

        float sum0 = 0.0f, sum1 = 0.0f;
#pragma unroll
        for (int j = 0; j < 8; j++) {
            float p0 = __expf(sreg[j][0] - mn0);
            float p1 = __expf(sreg[j][1] - mn0);
            float p2 = __expf(sreg[j][2] - mn1);
            float p3 = __expf(sreg[j][3] - mn1);
            sum0 += p0 + p1;
            sum1 += p2 + p3;
            PwU[g * PSW       + j * 8 + 2 * qc]     = to_tf32(p0);
            PwU[g * PSW       + j * 8 + 2 * qc + 1] = to_tf32(p1);
            PwU[(g + 8) * PSW + j * 8 + 2 * qc]     = to_tf32(p2);
            PwU[(g + 8) * PSW + j * 8 + 2 * qc + 1] = to_tf32(p3);
        }
        sum0 += __shfl_xor_sync(0xffffffffu, sum0, 1);
        sum0 += __shfl_xor_sync(0xffffffffu, sum0, 2);
        sum1 += __shfl_xor_sync(0xffffffffu, sum1, 1);
        sum1 += __shfl_xor_sync(0xffffffffu, sum1, 2);
        l0 = l0 * f0 + sum0;
        l1 = l1 * f1 + sum1;

#pragma unroll
        for (int n = 0; n < 16; n++) {
            o[n][0] *= f0; o[n][1] *= f0;
            o[n][2] *= f1; o[n][3] *= f1;
        }
        __syncwarp();

#pragma unroll
        for (int kc = 0; kc < 8; kc++) {
            uint32_t pa[4];
            pa[0] = PwU[g * PSW       + kc * 8 + qc];
            pa[1] = PwU[(g + 8) * PSW + kc * 8 + qc];
            pa[2] = PwU[g * PSW       + kc * 8 + qc + 4];
            pa[3] = PwU[(g + 8) * PSW + kc * 8 + qc + 4];
            const uint32_t* v0 = (const uint32_t*)&Vs[(kc * 8 + qc)     * VSW];
            const uint32_t* v1 = (const uint32_t*)&Vs[(kc * 8 + qc + 4) * VSW];
#pragma unroll
            for (int n = 0; n < 16; n++)
                mma_tf32(o[n], pa, v0[n * 8 + g], v1[n * 8 + g]);
        }
    }

    const float inv0 = 1.0f / l0;
    const float inv1 = 1.0f / l1;
    const size_t base0 = ((size_t)b * SEQ + q0 + g)     * 4096 + h * 128;
    const size_t base1 = ((size_t)b * SEQ + q0 + g + 8) * 4096 + h * 128;
#pragma unroll
    for (int n = 0; n < 16; n++) {
        *(__half2*)&O16[base0 + n * 8 + 2 * qc] =
            __floats2half2_rn(o[n][0] * inv0, o[n][1] * inv0);
        *(__half2*)&O16[base1 + n * 8 + 2 * qc] =
            __floats2half2_rn(o[n][2] * inv1, o[n][3] * inv1);
    }
}

// ---------------------------------------------------------------------------
extern "C" void kernel_launch(void* const* d_in, const int* in_sizes, int n_in,
                              void* d_out, int out_size)
{
    const float* x = (const float*)d_in[0];
    int off = (n_in >= 6 && in_sizes[1] <= 4) ? 2 : 1;
    const float* wq = (const float*)d_in[off + 0];
    const float* wk = (const float*)d_in[off + 1];
    const float* wv = (const float*)d_in[off + 2];
    const float* wo = (const float*)d_in[off + 3];
    float* out = (float*)d_out;

    __half *q, *k, *v;
    float *ct, *st;
    cudaGetSymbolAddress((void**)&q,  g_q);
    cudaGetSymbolAddress((void**)&k,  g_k);
    cudaGetSymbolAddress((void**)&v,  g_v);
    cudaGetSymbolAddress((void**)&ct, g_cos);
    cudaGetSymbolAddress((void**)&st, g_sin);

    __half *x16, *wqh, *wql, *wkh, *wkl, *wvh, *wvl, *woh, *wol, *a16;
    cudaGetSymbolAddress((void**)&x16, g_x16);
    cudaGetSymbolAddress((void**)&wqh, g_wqh);  cudaGetSymbolAddress((void**)&wql, g_wql);
    cudaGetSymbolAddress((void**)&wkh, g_wkh);  cudaGetSymbolAddress((void**)&wkl, g_wkl);
    cudaGetSymbolAddress((void**)&wvh, g_wvh);  cudaGetSymbolAddress((void**)&wvl, g_wvl);
    cudaGetSymbolAddress((void**)&woh, g_woh);  cudaGetSymbolAddress((void**)&wol, g_wol);
    cudaGetSymbolAddress((void**)&a16, g_a16);

    cudaFuncSetAttribute(gemm_mma, cudaFuncAttributeMaxDynamicSharedMemorySize, 2 * STAGE_SZ);
    cudaFuncSetAttribute(attn_tc,  cudaFuncAttributeMaxDynamicSharedMemorySize, ATTN_SMEM);

    const int n4 = DIM * DIM / 4;
    const int cgrid = (n4 + 255) / 256;
    dim3 gg(DIM / 128, DIM / 128);

    const float SC   = 0.015625f;                        // 2^-6 (weights x64)
    const float SC_Q = SC * 0.08838834764831845f;        // fold 1/sqrt(128) into q

    // gemm_q at launch index 3 (profiler captures launch #3)
    split_act<<<cgrid, 256>>>(x, x16, n4);                               // 0
    split_wt<<<cgrid, 256>>>(wq, wqh, wql, n4);                          // 1
    split_wt<<<cgrid, 256>>>(wk, wkh, wkl, n4);                          // 2
    gemm_mma<<<gg, 256, 2 * STAGE_SZ>>>(x16, wqh, wql, q, nullptr, SC_Q); // 3
    split_wt<<<cgrid, 256>>>(wv, wvh, wvl, n4);                          // 4
    gemm_mma<<<gg, 256, 2 * STAGE_SZ>>>(x16, wkh, wkl, k, nullptr, SC);   // 5
    split_wt<<<cgrid, 256>>>(wo, woh, wol, n4);                          // 6
    gemm_mma<<<gg, 256, 2 * STAGE_SZ>>>(x16, wvh, wvl, v, nullptr, SC);   // 7

    rope_table<<<(SEQ * (HD / 2) + 255) / 256, 256>>>(ct, st);           // 8
    rope_apply<<<(BSZ * SEQ * NH * (HD / 2) + 255) / 256, 256>>>(q, k, ct, st); // 9

    attn_tc<<<dim3(SEQ / 64, NH, BSZ), 128, ATTN_SMEM>>>(q, k, v, a16);  // 10

    gemm_mma<<<gg, 256, 2 * STAGE_SZ>>>(a16, woh, wol, nullptr, out, SC); // 11
}

// round 11
// speedup vs baseline: 1.8962x; 1.0955x over previous
#include <cuda_runtime.h>
#include <cuda_fp16.h>
#include <cstdint>
#include <math.h>

#define DIM   4096
#define NH    32
#define HD    128
#define BSZ   2
#define SEQ   2048

// ---------------- scratch (__device__ globals; no allocs allowed) ----------
__device__ __half g_q[BSZ*SEQ*DIM];
__device__ __half g_k[BSZ*SEQ*DIM];
__device__ __half g_v[BSZ*SEQ*DIM];
__device__ float  g_cos[SEQ*(HD/2)];
__device__ float  g_sin[SEQ*(HD/2)];

__device__ __half g_x16[DIM*DIM];
__device__ __half g_wqh[DIM*DIM], g_wql[DIM*DIM];
__device__ __half g_wkh[DIM*DIM], g_wkl[DIM*DIM];
__device__ __half g_wvh[DIM*DIM], g_wvl[DIM*DIM];
__device__ __half g_woh[DIM*DIM], g_wol[DIM*DIM];
__device__ __half g_a16[DIM*DIM];

// ---------------- base-ISA helpers (compute_103-safe) ----------------------
__device__ __forceinline__ uint32_t smem_u32(const void* p) {
    uint32_t a;
    asm("{ .reg .u64 t; cvta.to.shared.u64 t, %1; cvt.u32.u64 %0, t; }" : "=r"(a) : "l"(p));
    return a;
}
__device__ __forceinline__ void cpa16(uint32_t saddr, const void* g) {
    asm volatile("cp.async.cg.shared.global [%0], [%1], 16;" :: "r"(saddr), "l"(g));
}
__device__ __forceinline__ void ldsm4(uint32_t* r, uint32_t addr) {
    asm volatile("ldmatrix.sync.aligned.m8n8.x4.shared.b16 {%0,%1,%2,%3}, [%4];"
        : "=r"(r[0]), "=r"(r[1]), "=r"(r[2]), "=r"(r[3]) : "r"(addr));
}
__device__ __forceinline__ void ldsm4t(uint32_t* r, uint32_t addr) {
    asm volatile("ldmatrix.sync.aligned.m8n8.x4.trans.shared.b16 {%0,%1,%2,%3}, [%4];"
        : "=r"(r[0]), "=r"(r[1]), "=r"(r[2]), "=r"(r[3]) : "r"(addr));
}
__device__ __forceinline__ void mma_f16(float* c, const uint32_t* a,
                                        uint32_t b0, uint32_t b1) {
    asm volatile("mma.sync.aligned.m16n8k16.row.col.f32.f16.f16.f32 "
        "{%0,%1,%2,%3}, {%4,%5,%6,%7}, {%8,%9}, {%0,%1,%2,%3};"
        : "+f"(c[0]), "+f"(c[1]), "+f"(c[2]), "+f"(c[3])
        : "r"(a[0]), "r"(a[1]), "r"(a[2]), "r"(a[3]), "r"(b0), "r"(b1));
}
__device__ __forceinline__ uint32_t pack_h2(float a, float b) {
    __half2 h = __floats2half2_rn(a, b);
    return *(uint32_t*)&h;
}
__device__ __forceinline__ uint32_t sw128(uint32_t off) {
    return off ^ ((off >> 3) & 0x70);
}

// ---------------------------------------------------------------------------
// splits
// ---------------------------------------------------------------------------
__global__ void split_act(const float* __restrict__ in, __half* __restrict__ o, int n4)
{
    int i = blockIdx.x * 256 + threadIdx.x;
    if (i >= n4) return;
    float4 v = ((const float4*)in)[i];
    ((__half2*)o)[2*i]   = __floats2half2_rn(v.x, v.y);
    ((__half2*)o)[2*i+1] = __floats2half2_rn(v.z, v.w);
}

__global__ void split_wt(const float* __restrict__ in,
                         __half* __restrict__ hi, __half* __restrict__ lo, int n4)
{
    int i = blockIdx.x * 256 + threadIdx.x;
    if (i >= n4) return;
    float4 v = ((const float4*)in)[i];
    v.x *= 64.f; v.y *= 64.f; v.z *= 64.f; v.w *= 64.f;
    __half2 h01 = __floats2half2_rn(v.x, v.y);
    __half2 h23 = __floats2half2_rn(v.z, v.w);
    float2 f01 = __half22float2(h01);
    float2 f23 = __half22float2(h23);
    ((__half2*)hi)[2*i]   = h01;
    ((__half2*)hi)[2*i+1] = h23;
    ((__half2*)lo)[2*i]   = __floats2half2_rn(v.x - f01.x, v.y - f01.y);
    ((__half2*)lo)[2*i+1] = __floats2half2_rn(v.z - f23.x, v.w - f23.y);
}

// ---------------------------------------------------------------------------
// fp16 2-product GEMM (NT): C = sc * A16*(Bh + Bl), 4096^3.
// 2-stage cp.async, 2 CTAs/SM. Optional fused interleaved RoPE in the
// fp16 epilogue (Ct/St non-null): rotates column pairs (2j,2j+1) per token.
// ---------------------------------------------------------------------------
#define STAGE_SZ 49152
__global__ void __launch_bounds__(256, 2)
gemm_mma(const __half* __restrict__ A16,
         const __half* __restrict__ Bh16, const __half* __restrict__ Bl16,
         __half* __restrict__ Ch, float* __restrict__ Cf, float sc,
         const float* __restrict__ Ct, const float* __restrict__ St)
{
    extern __shared__ char sm[];
    const uint32_t s0 = smem_u32(sm);

    const int tid  = threadIdx.x;
    const int wid  = tid >> 5;
    const int lane = tid & 31;
    const int bx = blockIdx.x;
    const int by = blockIdx.y;
    const int warp_m = wid >> 1;
    const int warp_n = wid & 1;

    float acc[2][8][4];
#pragma unroll
    for (int t = 0; t < 2; t++)
#pragma unroll
        for (int n = 0; n < 8; n++)
#pragma unroll
            for (int j = 0; j < 4; j++) acc[t][n][j] = 0.0f;

    auto load_stage = [&](int kt, int stage) {
        uint32_t sb = s0 + stage * STAGE_SZ;
#pragma unroll
        for (int i = 0; i < 4; i++) {
            int li = tid + i * 256;
            int r = li >> 3, c = li & 7;
            uint32_t off = sw128((uint32_t)(r * 128 + c * 16));
            cpa16(sb + off,         A16  + (size_t)(by * 128 + r) * 4096 + kt * 64 + c * 8);
            cpa16(sb + 16384 + off, Bh16 + (size_t)(bx * 128 + r) * 4096 + kt * 64 + c * 8);
            cpa16(sb + 32768 + off, Bl16 + (size_t)(bx * 128 + r) * 4096 + kt * 64 + c * 8);
        }
        asm volatile("cp.async.commit_group;" ::: "memory");
    };

    const int lrow  = (lane & 7) + ((lane >> 3) & 1) * 8;
    const int khalf = (lane >> 4) * 16;

    const int NT = 4096 / 64;

    load_stage(0, 0);

    for (int kt = 0; kt < NT; kt++) {
        asm volatile("cp.async.wait_group 0;" ::: "memory");
        __syncthreads();

        const uint32_t sbase = s0 + (kt & 1) * STAGE_SZ;
        if (kt + 1 < NT) load_stage(kt + 1, (kt + 1) & 1);

#pragma unroll
        for (int s = 0; s < 4; s++) {
            uint32_t ah[2][4], bh[4][4], bl[4][4];
#pragma unroll
            for (int t = 0; t < 2; t++) {
                uint32_t off = sw128((uint32_t)((warp_m * 32 + t * 16 + lrow) * 128
                                                + khalf + s * 32));
                ldsm4(ah[t], sbase + off);
            }
#pragma unroll
            for (int u = 0; u < 4; u++) {
                uint32_t off = sw128((uint32_t)((warp_n * 64 + u * 16 + lrow) * 128
                                                + khalf + s * 32));
                ldsm4(bh[u], sbase + 16384 + off);
                ldsm4(bl[u], sbase + 32768 + off);
            }
#pragma unroll
            for (int t = 0; t < 2; t++)
#pragma unroll
                for (int u = 0; u < 4; u++)
#pragma unroll
                    for (int j = 0; j < 2; j++)
                        mma_f16(acc[t][u * 2 + j], ah[t], bh[u][j], bh[u][j + 2]);
#pragma unroll
            for (int t = 0; t < 2; t++)
#pragma unroll
                for (int u = 0; u < 4; u++)
#pragma unroll
                    for (int j = 0; j < 2; j++)
                        mma_f16(acc[t][u * 2 + j], ah[t], bl[u][j], bl[u][j + 2]);
        }
    }

    const int g  = lane >> 2;
    const int qc = lane & 3;
    if (Ch) {
#pragma unroll
        for (int t = 0; t < 2; t++) {
            const int row = by * 128 + warp_m * 32 + t * 16 + g;
#pragma unroll
            for (int n = 0; n < 8; n++) {
                const int col = bx * 128 + warp_n * 64 + n * 8 + qc * 2;
                float x0 = acc[t][n][0] * sc, x1 = acc[t][n][1] * sc;
                float y0 = acc[t][n][2] * sc, y1 = acc[t][n][3] * sc;
                if (Ct) {   // fused interleaved RoPE
                    const int jj = (col & 127) >> 1;
                    float c0 = Ct[(row & 2047) * 64 + jj];
                    float s0 = St[(row & 2047) * 64 + jj];
                    float c1 = Ct[((row + 8) & 2047) * 64 + jj];
                    float s1 = St[((row + 8) & 2047) * 64 + jj];
                    float nx0 = x0 * c0 - x1 * s0, nx1 = x0 * s0 + x1 * c0;
                    float ny0 = y0 * c1 - y1 * s1, ny1 = y0 * s1 + y1 * c1;
                    x0 = nx0; x1 = nx1; y0 = ny0; y1 = ny1;
                }
                *(__half2*)&Ch[(size_t)row * 4096 + col] = __floats2half2_rn(x0, x1);
                *(__half2*)&Ch[(size_t)(row + 8) * 4096 + col] = __floats2half2_rn(y0, y1);
            }
        }
    } else {
#pragma unroll
        for (int t = 0; t < 2; t++) {
            const int row = by * 128 + warp_m * 32 + t * 16 + g;
#pragma unroll
            for (int n = 0; n < 8; n++) {
                const int col = bx * 128 + warp_n * 64 + n * 8 + qc * 2;
                *(float2*)&Cf[(size_t)row * 4096 + col] =
                    make_float2(acc[t][n][0] * sc, acc[t][n][1] * sc);
                *(float2*)&Cf[(size_t)(row + 8) * 4096 + col] =
                    make_float2(acc[t][n][2] * sc, acc[t][n][3] * sc);
            }
        }
    }
}

// ---------------------------------------------------------------------------
// RoPE table
// ---------------------------------------------------------------------------
__global__ void rope_table(float* ct, float* st)
{
    int idx = blockIdx.x * 256 + threadIdx.x;
    if (idx >= SEQ * (HD / 2)) return;
    int s = idx >> 6;
    int j = idx & 63;
    double inv = pow(10000.0, -(double)(2 * j) / 128.0);
    double a = (double)s * inv;
    ct[idx] = (float)cos(a);
    st[idx] = (float)sin(a);
}

// ---------------------------------------------------------------------------
// Causal flash attention, all-fp16 mma + ldmatrix.
// Block 128 threads (4 warps); Q tile 64 rows (16/warp), K tile 64 keys.
// K/V staged fp16, padded rows (272B stride). P kept in registers.
// ---------------------------------------------------------------------------
#define KVW 68   // row stride in uint32 (272 bytes: 256B data + 16B pad)
#define ATTN_SMEM (2 * 64 * KVW * 4)

__global__ void __launch_bounds__(128)
attn_tc(const __half* __restrict__ Qh, const __half* __restrict__ Kh,
        const __half* __restrict__ Vh, __half* __restrict__ O16)
{
    extern __shared__ uint32_t smu[];
    uint32_t* KsU = smu;                 // [64][KVW]
    uint32_t* VsU = smu + 64 * KVW;      // [64][KVW]

    const int tid  = threadIdx.x;
    const int w    = tid >> 5;
    const int lane = tid & 31;
    const int qt = blockIdx.x;
    const int h  = blockIdx.y;
    const int b  = blockIdx.z;
    const int g  = lane >> 2;
    const int qc = lane & 3;

    const uint32_t kS = smem_u32(KsU);
    const uint32_t vS = smem_u32(VsU);

    // ldmatrix per-lane address components
    const uint32_t k_row = (lane & 7) + ((lane >> 4) & 1) * 8;   // QK: keys
    const uint32_t k_db  = ((lane >> 3) & 1) * 16;               // QK: d-half
    const uint32_t v_row = (lane & 7) + ((lane >> 3) & 1) * 8;   // PV: keys
    const uint32_t v_db  = ((lane >> 4) & 1) * 16;               // PV: d-half

    const int q0 = qt * 64 + w * 16;

    // Q a-fragments (fp16, roped + 1/sqrt(128)-scaled by the q-GEMM)
    uint32_t qa[8][4];
    {
        const uint32_t* q_r0 = (const uint32_t*)(Qh + ((size_t)b * SEQ + q0 + g)     * 4096 + h * 128);
        const uint32_t* q_r1 = (const uint32_t*)(Qh + ((size_t)b * SEQ + q0 + g + 8) * 4096 + h * 128);
#pragma unroll
        for (int kc = 0; kc < 8; kc++) {
            qa[kc][0] = q_r0[kc * 8 + qc];
            qa[kc][1] = q_r1[kc * 8 + qc];
            qa[kc][2] = q_r0[kc * 8 + qc + 4];
            qa[kc][3] = q_r1[kc * 8 + qc + 4];
        }
    }

    float o[16][4];
#pragma unroll
    for (int n = 0; n < 16; n++)
#pragma unroll
        for (int j = 0; j < 4; j++) o[n][j] = 0.0f;
    float m0 = -1e30f, m1 = -1e30f, l0 = 0.0f, l1 = 0.0f;

    for (int kt = 0; kt <= qt; kt++) {
        if (kt) __syncthreads();
        // stage K,V (straight fp16 copies, padded rows)
#pragma unroll
        for (int i = 0; i < 8; i++) {
            int li = tid + i * 128;
            int row = li >> 4, c = li & 15;
            size_t gsrc = ((size_t)b * SEQ + kt * 64 + row) * 4096 + h * 128 + c * 8;
            *(uint4*)&KsU[row * KVW + c * 4] = *(const uint4*)(Kh + gsrc);
            *(uint4*)&VsU[row * KVW + c * 4] = *(const uint4*)(Vh + gsrc);
        }
        __syncthreads();

        // S = Q K^T via ldmatrix B-fragments (fp16 mma)
        float sreg[8][4];
#pragma unroll
        for (int j = 0; j < 8; j++)
            sreg[j][0] = sreg[j][1] = sreg[j][2] = sreg[j][3] = 0.0f;
#pragma unroll
        for (int kc = 0; kc < 8; kc++) {
#pragma unroll
            for (int j2 = 0; j2 < 4; j2++) {
                uint32_t r[4];
                ldsm4(r, kS + (j2 * 16 + k_row) * 272 + kc * 32 + k_db);
                mma_f16(sreg[2 * j2],     qa[kc], r[0], r[1]);
                mma_f16(sreg[2 * j2 + 1], qa[kc], r[2], r[3]);
            }
        }

        if (kt == qt) {
            const int kb = kt * 64;
#pragma unroll
            for (int j = 0; j < 8; j++) {
                int key0 = kb + j * 8 + 2 * qc;
                if (key0     > q0 + g)     sreg[j][0] = -1e30f;
                if (key0 + 1 > q0 + g)     sreg[j][1] = -1e30f;
                if (key0     > q0 + g + 8) sreg[j][2] = -1e30f;
                if (key0 + 1 > q0 + g + 8) sreg[j][3] = -1e30f;
            }
        }

        float mx0 = -1e30f, mx1 = -1e30f;
#pragma unroll
        for (int j = 0; j < 8; j++) {
            mx0 = fmaxf(mx0, fmaxf(sreg[j][0], sreg[j][1]));
            mx1 = fmaxf(mx1, fmaxf(sreg[j][2], sreg[j][3]));
        }
        mx0 = fmaxf(mx0, __shfl_xor_sync(0xffffffffu, mx0, 1));
        mx0 = fmaxf(mx0, __shfl_xor_sync(0xffffffffu, mx0, 2));
        mx1 = fmaxf(mx1, __shfl_xor_sync(0xffffffffu, mx1, 1));
        mx1 = fmaxf(mx1, __shfl_xor_sync(0xffffffffu, mx1, 2));
        float mn0 = fmaxf(m0, mx0), mn1 = fmaxf(m1, mx1);
        float f0 = __expf(m0 - mn0), f1 = __expf(m1 - mn1);
        m0 = mn0; m1 = mn1;

        float sum0 = 0.0f, sum1 = 0.0f;
#pragma unroll
        for (int j = 0; j < 8; j++) {
            sreg[j][0] = __expf(sreg[j][0] - mn0);
            sreg[j][1] = __expf(sreg[j][1] - mn0);
            sreg[j][2] = __expf(sreg[j][2] - mn1);
            sreg[j][3] = __expf(sreg[j][3] - mn1);
            sum0 += sreg[j][0] + sreg[j][1];
            sum1 += sreg[j][2] + sreg[j][3];
        }
        sum0 += __shfl_xor_sync(0xffffffffu, sum0, 1);
        sum0 += __shfl_xor_sync(0xffffffffu, sum0, 2);
        sum1 += __shfl_xor_sync(0xffffffffu, sum1, 1);
        sum1 += __shfl_xor_sync(0xffffffffu, sum1, 2);
        l0 = l0 * f0 + sum0;
        l1 = l1 * f1 + sum1;

#pragma unroll
        for (int n = 0; n < 16; n++) {
            o[n][0] *= f0; o[n][1] *= f0;
            o[n][2] *= f1; o[n][3] *= f1;
        }

        // P a-fragments built in registers (matches m16n8k16 A layout)
        uint32_t pa[4][4];
#pragma unroll
        for (int kc = 0; kc < 4; kc++) {
            pa[kc][0] = pack_h2(sreg[2 * kc][0],     sreg[2 * kc][1]);
            pa[kc][1] = pack_h2(sreg[2 * kc][2],     sreg[2 * kc][3]);
            pa[kc][2] = pack_h2(sreg[2 * kc + 1][0], sreg[2 * kc + 1][1]);
            pa[kc][3] = pack_h2(sreg[2 * kc + 1][2], sreg[2 * kc + 1][3]);
        }

        // O += P V via ldmatrix.trans (fp16 mma)
#pragma unroll
        for (int kc = 0; kc < 4; kc++) {
#pragma unroll
            for (int d0 = 0; d0 < 8; d0++) {
                uint32_t r[4];
                ldsm4t(r, vS + (kc * 16 + v_row) * 272 + d0 * 32 + v_db);
                mma_f16(o[2 * d0],     pa[kc], r[0], r[1]);
                mma_f16(o[2 * d0 + 1], pa[kc], r[2], r[3]);
            }
        }
    }

    const float inv0 = 1.0f / l0;
    const float inv1 = 1.0f / l1;
    const size_t base0 = ((size_t)b * SEQ + q0 + g)     * 4096 + h * 128;
    const size_t base1 = ((size_t)b * SEQ + q0 + g + 8) * 4096 + h * 128;
#pragma unroll
    for (int n = 0; n < 16; n++) {
        *(__half2*)&O16[base0 + n * 8 + 2 * qc] =
            __floats2half2_rn(o[n][0] * inv0, o[n][1] * inv0);
        *(__half2*)&O16[base1 + n * 8 + 2 * qc] =
            __floats2half2_rn(o[n][2] * inv1, o[n][3] * inv1);
    }
}

// ---------------------------------------------------------------------------
extern "C" void kernel_launch(void* const* d_in, const int* in_sizes, int n_in,
                              void* d_out, int out_size)
{
    const float* x = (const float*)d_in[0];
    int off = (n_in >= 6 && in_sizes[1] <= 4) ? 2 : 1;
    const float* wq = (const float*)d_in[off + 0];
    const float* wk = (const float*)d_in[off + 1];
    const float* wv = (const float*)d_in[off + 2];
    const float* wo = (const float*)d_in[off + 3];
    float* out = (float*)d_out;

    __half *q, *k, *v;
    float *ct, *st;
    cudaGetSymbolAddress((void**)&q,  g_q);
    cudaGetSymbolAddress((void**)&k,  g_k);
    cudaGetSymbolAddress((void**)&v,  g_v);
    cudaGetSymbolAddress((void**)&ct, g_cos);
    cudaGetSymbolAddress((void**)&st, g_sin);

    __half *x16, *wqh, *wql, *wkh, *wkl, *wvh, *wvl, *woh, *wol, *a16;
    cudaGetSymbolAddress((void**)&x16, g_x16);
    cudaGetSymbolAddress((void**)&wqh, g_wqh);  cudaGetSymbolAddress((void**)&wql, g_wql);
    cudaGetSymbolAddress((void**)&wkh, g_wkh);  cudaGetSymbolAddress((void**)&wkl, g_wkl);
    cudaGetSymbolAddress((void**)&wvh, g_wvh);  cudaGetSymbolAddress((void**)&wvl, g_wvl);
    cudaGetSymbolAddress((void**)&woh, g_woh);  cudaGetSymbolAddress((void**)&wol, g_wol);
    cudaGetSymbolAddress((void**)&a16, g_a16);

    cudaFuncSetAttribute(gemm_mma, cudaFuncAttributeMaxDynamicSharedMemorySize, 2 * STAGE_SZ);
    cudaFuncSetAttribute(attn_tc,  cudaFuncAttributeMaxDynamicSharedMemorySize, ATTN_SMEM);

    const int n4 = DIM * DIM / 4;
    const int cgrid = (n4 + 255) / 256;
    dim3 gg(DIM / 128, DIM / 128);

    const float SC   = 0.015625f;                        // 2^-6 (weights x64)
    const float SC_Q = SC * 0.08838834764831845f;        // fold 1/sqrt(128) into q

    rope_table<<<(SEQ * (HD / 2) + 255) / 256, 256>>>(ct, st);                   // 0
    split_act<<<cgrid, 256>>>(x, x16, n4);                                       // 1
    split_wt<<<cgrid, 256>>>(wq, wqh, wql, n4);                                  // 2
    gemm_mma<<<gg, 256, 2 * STAGE_SZ>>>(x16, wqh, wql, q, nullptr, SC_Q, ct, st); // 3 (profiled)
    split_wt<<<cgrid, 256>>>(wk, wkh, wkl, n4);                                  // 4
    gemm_mma<<<gg, 256, 2 * STAGE_SZ>>>(x16, wkh, wkl, k, nullptr, SC, ct, st);   // 5
    split_wt<<<cgrid, 256>>>(wv, wvh, wvl, n4);                                  // 6
    gemm_mma<<<gg, 256, 2 * STAGE_SZ>>>(x16, wvh, wvl, v, nullptr, SC, nullptr, nullptr); // 7
    split_wt<<<cgrid, 256>>>(wo, woh, wol, n4);                                  // 8

    attn_tc<<<dim3(SEQ / 64, NH, BSZ), 128, ATTN_SMEM>>>(q, k, v, a16);          // 9

    gemm_mma<<<gg, 256, 2 * STAGE_SZ>>>(a16, woh, wol, nullptr, out, SC, nullptr, nullptr); // 10
}

// round 12
// speedup vs baseline: 3.1728x; 1.6732x over previous
#include <cuda_runtime.h>
#include <cuda_fp16.h>
#include <cstdint>
#include <math.h>

#define DIM   4096
#define NH    32
#define HD    128
#define BSZ   2
#define SEQ   2048

// ---------------- scratch (__device__ globals; no allocs allowed) ----------
__device__ __half g_q[BSZ*SEQ*DIM];
__device__ __half g_k[BSZ*SEQ*DIM];
__device__ __half g_v[BSZ*SEQ*DIM];
__device__ float  g_cos[SEQ*(HD/2)];
__device__ float  g_sin[SEQ*(HD/2)];

__device__ __half g_x16[DIM*DIM];
__device__ __half g_wq16[DIM*DIM];
__device__ __half g_wk16[DIM*DIM];
__device__ __half g_wv16[DIM*DIM];
__device__ __half g_wo16[DIM*DIM];
__device__ __half g_a16[DIM*DIM];

// ---------------- base-ISA helpers (compute_103-safe) ----------------------
__device__ __forceinline__ uint32_t smem_u32(const void* p) {
    uint32_t a;
    asm("{ .reg .u64 t; cvta.to.shared.u64 t, %1; cvt.u32.u64 %0, t; }" : "=r"(a) : "l"(p));
    return a;
}
__device__ __forceinline__ void cpa16(uint32_t saddr, const void* g) {
    asm volatile("cp.async.cg.shared.global [%0], [%1], 16;" :: "r"(saddr), "l"(g));
}
__device__ __forceinline__ void ldsm4(uint32_t* r, uint32_t addr) {
    asm volatile("ldmatrix.sync.aligned.m8n8.x4.shared.b16 {%0,%1,%2,%3}, [%4];"
        : "=r"(r[0]), "=r"(r[1]), "=r"(r[2]), "=r"(r[3]) : "r"(addr));
}
__device__ __forceinline__ void ldsm4t(uint32_t* r, uint32_t addr) {
    asm volatile("ldmatrix.sync.aligned.m8n8.x4.trans.shared.b16 {%0,%1,%2,%3}, [%4];"
        : "=r"(r[0]), "=r"(r[1]), "=r"(r[2]), "=r"(r[3]) : "r"(addr));
}
__device__ __forceinline__ void mma_f16(float* c, const uint32_t* a,
                                        uint32_t b0, uint32_t b1) {
    asm volatile("mma.sync.aligned.m16n8k16.row.col.f32.f16.f16.f32 "
        "{%0,%1,%2,%3}, {%4,%5,%6,%7}, {%8,%9}, {%0,%1,%2,%3};"
        : "+f"(c[0]), "+f"(c[1]), "+f"(c[2]), "+f"(c[3])
        : "r"(a[0]), "r"(a[1]), "r"(a[2]), "r"(a[3]), "r"(b0), "r"(b1));
}
__device__ __forceinline__ uint32_t pack_h2(float a, float b) {
    __half2 h = __floats2half2_rn(a, b);
    return *(uint32_t*)&h;
}
__device__ __forceinline__ uint32_t sw128(uint32_t off) {
    return off ^ ((off >> 3) & 0x70);
}

// ---------------------------------------------------------------------------
// casts
// ---------------------------------------------------------------------------
__global__ void split_act(const float* __restrict__ in, __half* __restrict__ o, int n4)
{
    int i = blockIdx.x * 256 + threadIdx.x;
    if (i >= n4) return;
    float4 v = ((const float4*)in)[i];
    ((__half2*)o)[2*i]   = __floats2half2_rn(v.x, v.y);
    ((__half2*)o)[2*i+1] = __floats2half2_rn(v.z, v.w);
}

// weights: w16 = rn16(64w)   (x64 keeps values in fp16 normal range)
__global__ void split_wt(const float* __restrict__ in, __half* __restrict__ o, int n4)
{
    int i = blockIdx.x * 256 + threadIdx.x;
    if (i >= n4) return;
    float4 v = ((const float4*)in)[i];
    ((__half2*)o)[2*i]   = __floats2half2_rn(v.x * 64.f, v.y * 64.f);
    ((__half2*)o)[2*i+1] = __floats2half2_rn(v.z * 64.f, v.w * 64.f);
}

// ---------------------------------------------------------------------------
// fp16 single-product GEMM (NT): C = sc * A16*B16, 4096^3.
// CTA 128x128, BK=64 (SW128), 8 warps (4Mx2N), warp tile 32x64,
// 3-stage cp.async pipeline, 2 CTAs/SM. Optional fused RoPE epilogue.
// ---------------------------------------------------------------------------
#define STAGE_SZ 32768
__global__ void __launch_bounds__(256, 2)
gemm_mma(const __half* __restrict__ A16, const __half* __restrict__ B16,
         __half* __restrict__ Ch, float* __restrict__ Cf, float sc,
         const float* __restrict__ Ct, const float* __restrict__ St)
{
    extern __shared__ char sm[];
    const uint32_t s0 = smem_u32(sm);

    const int tid  = threadIdx.x;
    const int wid  = tid >> 5;
    const int lane = tid & 31;
    const int bx = blockIdx.x;
    const int by = blockIdx.y;
    const int warp_m = wid >> 1;
    const int warp_n = wid & 1;

    float acc[2][8][4];
#pragma unroll
    for (int t = 0; t < 2; t++)
#pragma unroll
        for (int n = 0; n < 8; n++)
#pragma unroll
            for (int j = 0; j < 4; j++) acc[t][n][j] = 0.0f;

    auto load_stage = [&](int kt, int stage) {
        uint32_t sb = s0 + stage * STAGE_SZ;
#pragma unroll
        for (int i = 0; i < 4; i++) {
            int li = tid + i * 256;           // 0..1023
            int r = li >> 3, c = li & 7;
            uint32_t off = sw128((uint32_t)(r * 128 + c * 16));
            cpa16(sb + off,         A16 + (size_t)(by * 128 + r) * 4096 + kt * 64 + c * 8);
            cpa16(sb + 16384 + off, B16 + (size_t)(bx * 128 + r) * 4096 + kt * 64 + c * 8);
        }
        asm volatile("cp.async.commit_group;" ::: "memory");
    };

    const int lrow  = (lane & 7) + ((lane >> 3) & 1) * 8;
    const int khalf = (lane >> 4) * 16;

    const int NT = 4096 / 64;

    load_stage(0, 0);
    load_stage(1, 1);

    for (int kt = 0; kt < NT; kt++) {
        if (kt < NT - 1) asm volatile("cp.async.wait_group 1;" ::: "memory");
        else             asm volatile("cp.async.wait_group 0;" ::: "memory");
        __syncthreads();

        const uint32_t sbase = s0 + (kt % 3) * STAGE_SZ;
        if (kt + 2 < NT) load_stage(kt + 2, (kt + 2) % 3);

#pragma unroll
        for (int s = 0; s < 4; s++) {
            uint32_t ah[2][4], bh[4][4];
#pragma unroll
            for (int t = 0; t < 2; t++) {
                uint32_t off = sw128((uint32_t)((warp_m * 32 + t * 16 + lrow) * 128
                                                + khalf + s * 32));
                ldsm4(ah[t], sbase + off);
            }
#pragma unroll
            for (int u = 0; u < 4; u++) {
                uint32_t off = sw128((uint32_t)((warp_n * 64 + u * 16 + lrow) * 128
                                                + khalf + s * 32));
                ldsm4(bh[u], sbase + 16384 + off);
            }
#pragma unroll
            for (int t = 0; t < 2; t++)
#pragma unroll
                for (int u = 0; u < 4; u++)
#pragma unroll
                    for (int j = 0; j < 2; j++)
                        mma_f16(acc[t][u * 2 + j], ah[t], bh[u][j], bh[u][j + 2]);
        }
    }

    const int g  = lane >> 2;
    const int qc = lane & 3;
    if (Ch) {
#pragma unroll
        for (int t = 0; t < 2; t++) {
            const int row = by * 128 + warp_m * 32 + t * 16 + g;
#pragma unroll
            for (int n = 0; n < 8; n++) {
                const int col = bx * 128 + warp_n * 64 + n * 8 + qc * 2;
                float x0 = acc[t][n][0] * sc, x1 = acc[t][n][1] * sc;
                float y0 = acc[t][n][2] * sc, y1 = acc[t][n][3] * sc;
                if (Ct) {   // fused interleaved RoPE
                    const int jj = (col & 127) >> 1;
                    float c0 = Ct[(row & 2047) * 64 + jj];
                    float s0 = St[(row & 2047) * 64 + jj];
                    float c1 = Ct[((row + 8) & 2047) * 64 + jj];
                    float s1 = St[((row + 8) & 2047) * 64 + jj];
                    float nx0 = x0 * c0 - x1 * s0, nx1 = x0 * s0 + x1 * c0;
                    float ny0 = y0 * c1 - y1 * s1, ny1 = y0 * s1 + y1 * c1;
                    x0 = nx0; x1 = nx1; y0 = ny0; y1 = ny1;
                }
                *(__half2*)&Ch[(size_t)row * 4096 + col] = __floats2half2_rn(x0, x1);
                *(__half2*)&Ch[(size_t)(row + 8) * 4096 + col] = __floats2half2_rn(y0, y1);
            }
        }
    } else {
#pragma unroll
        for (int t = 0; t < 2; t++) {
            const int row = by * 128 + warp_m * 32 + t * 16 + g;
#pragma unroll
            for (int n = 0; n < 8; n++) {
                const int col = bx * 128 + warp_n * 64 + n * 8 + qc * 2;
                *(float2*)&Cf[(size_t)row * 4096 + col] =
                    make_float2(acc[t][n][0] * sc, acc[t][n][1] * sc);
                *(float2*)&Cf[(size_t)(row + 8) * 4096 + col] =
                    make_float2(acc[t][n][2] * sc, acc[t][n][3] * sc);
            }
        }
    }
}

// ---------------------------------------------------------------------------
// RoPE table
// ---------------------------------------------------------------------------
__global__ void rope_table(float* ct, float* st)
{
    int idx = blockIdx.x * 256 + threadIdx.x;
    if (idx >= SEQ * (HD / 2)) return;
    int s = idx >> 6;
    int j = idx & 63;
    double inv = pow(10000.0, -(double)(2 * j) / 128.0);
    double a = (double)s * inv;
    ct[idx] = (float)cos(a);
    st[idx] = (float)sin(a);
}

// ---------------------------------------------------------------------------
// Causal flash attention, all-fp16 mma + ldmatrix (unchanged from R11).
// ---------------------------------------------------------------------------
#define KVW 68
#define ATTN_SMEM (2 * 64 * KVW * 4)

__global__ void __launch_bounds__(128)
attn_tc(const __half* __restrict__ Qh, const __half* __restrict__ Kh,
        const __half* __restrict__ Vh, __half* __restrict__ O16)
{
    extern __shared__ uint32_t smu[];
    uint32_t* KsU = smu;
    uint32_t* VsU = smu + 64 * KVW;

    const int tid  = threadIdx.x;
    const int w    = tid >> 5;
    const int lane = tid & 31;
    const int qt = blockIdx.x;
    const int h  = blockIdx.y;
    const int b  = blockIdx.z;
    const int g  = lane >> 2;
    const int qc = lane & 3;

    const uint32_t kS = smem_u32(KsU);
    const uint32_t vS = smem_u32(VsU);

    const uint32_t k_row = (lane & 7) + ((lane >> 4) & 1) * 8;
    const uint32_t k_db  = ((lane >> 3) & 1) * 16;
    const uint32_t v_row = (lane & 7) + ((lane >> 3) & 1) * 8;
    const uint32_t v_db  = ((lane >> 4) & 1) * 16;

    const int q0 = qt * 64 + w * 16;

    uint32_t qa[8][4];
    {
        const uint32_t* q_r0 = (const uint32_t*)(Qh + ((size_t)b * SEQ + q0 + g)     * 4096 + h * 128);
        const uint32_t* q_r1 = (const uint32_t*)(Qh + ((size_t)b * SEQ + q0 + g + 8) * 4096 + h * 128);
#pragma unroll
        for (int kc = 0; kc < 8; kc++) {
            qa[kc][0] = q_r0[kc * 8 + qc];
            qa[kc][1] = q_r1[kc * 8 + qc];
            qa[kc][2] = q_r0[kc * 8 + qc + 4];
            qa[kc][3] = q_r1[kc * 8 + qc + 4];
        }
    }

    float o[16][4];
#pragma unroll
    for (int n = 0; n < 16; n++)
#pragma unroll
        for (int j = 0; j < 4; j++) o[n][j] = 0.0f;
    float m0 = -1e30f, m1 = -1e30f, l0 = 0.0f, l1 = 0.0f;

    for (int kt = 0; kt <= qt; kt++) {
        if (kt) __syncthreads();
#pragma unroll
        for (int i = 0; i < 8; i++) {
            int li = tid + i * 128;
            int row = li >> 4, c = li & 15;
            size_t gsrc = ((size_t)b * SEQ + kt * 64 + row) * 4096 + h * 128 + c * 8;
            *(uint4*)&KsU[row * KVW + c * 4] = *(const uint4*)(Kh + gsrc);
            *(uint4*)&VsU[row * KVW + c * 4] = *(const uint4*)(Vh + gsrc);
        }
        __syncthreads();

        float sreg[8][4];
#pragma unroll
        for (int j = 0; j < 8; j++)
            sreg[j][0] = sreg[j][1] = sreg[j][2] = sreg[j][3] = 0.0f;
#pragma unroll
        for (int kc = 0; kc < 8; kc++) {
#pragma unroll
            for (int j2 = 0; j2 < 4; j2++) {
                uint32_t r[4];
                ldsm4(r, kS + (j2 * 16 + k_row) * 272 + kc * 32 + k_db);
                mma_f16(sreg[2 * j2],     qa[kc], r[0], r[1]);
                mma_f16(sreg[2 * j2 + 1], qa[kc], r[2], r[3]);
            }
        }

        if (kt == qt) {
            const int kb = kt * 64;
#pragma unroll
            for (int j = 0; j < 8; j++) {
                int key0 = kb + j * 8 + 2 * qc;
                if (key0     > q0 + g)     sreg[j][0] = -1e30f;
                if (key0 + 1 > q0 + g)     sreg[j][1] = -1e30f;
                if (key0     > q0 + g + 8) sreg[j][2] = -1e30f;
                if (key0 + 1 > q0 + g + 8) sreg[j][3] = -1e30f;
            }
        }

        float mx0 = -1e30f, mx1 = -1e30f;
#pragma unroll
        for (int j = 0; j < 8; j++) {
            mx0 = fmaxf(mx0, fmaxf(sreg[j][0], sreg[j][1]));
            mx1 = fmaxf(mx1, fmaxf(sreg[j][2], sreg[j][3]));
        }
        mx0 = fmaxf(mx0, __shfl_xor_sync(0xffffffffu, mx0, 1));
        mx0 = fmaxf(mx0, __shfl_xor_sync(0xffffffffu, mx0, 2));
        mx1 = fmaxf(mx1, __shfl_xor_sync(0xffffffffu, mx1, 1));
        mx1 = fmaxf(mx1, __shfl_xor_sync(0xffffffffu, mx1, 2));
        float mn0 = fmaxf(m0, mx0), mn1 = fmaxf(m1, mx1);
        float f0 = __expf(m0 - mn0), f1 = __expf(m1 - mn1);
        m0 = mn0; m1 = mn1;

        float sum0 = 0.0f, sum1 = 0.0f;
#pragma unroll
        for (int j = 0; j < 8; j++) {
            sreg[j][0] = __expf(sreg[j][0] - mn0);
            sreg[j][1] = __expf(sreg[j][1] - mn0);
            sreg[j][2] = __expf(sreg[j][2] - mn1);
            sreg[j][3] = __expf(sreg[j][3] - mn1);
            sum0 += sreg[j][0] + sreg[j][1];
            sum1 += sreg[j][2] + sreg[j][3];
        }
        sum0 += __shfl_xor_sync(0xffffffffu, sum0, 1);
        sum0 += __shfl_xor_sync(0xffffffffu, sum0, 2);
        sum1 += __shfl_xor_sync(0xffffffffu, sum1, 1);
        sum1 += __shfl_xor_sync(0xffffffffu, sum1, 2);
        l0 = l0 * f0 + sum0;
        l1 = l1 * f1 + sum1;

#pragma unroll
        for (int n = 0; n < 16; n++) {
            o[n][0] *= f0; o[n][1] *= f0;
            o[n][2] *= f1; o[n][3] *= f1;
        }

        uint32_t pa[4][4];
#pragma unroll
        for (int kc = 0; kc < 4; kc++) {
            pa[kc][0] = pack_h2(sreg[2 * kc][0],     sreg[2 * kc][1]);
            pa[kc][1] = pack_h2(sreg[2 * kc][2],     sreg[2 * kc][3]);
            pa[kc][2] = pack_h2(sreg[2 * kc + 1][0], sreg[2 * kc + 1][1]);
            pa[kc][3] = pack_h2(sreg[2 * kc + 1][2], sreg[2 * kc + 1][3]);
        }

#pragma unroll
        for (int kc = 0; kc < 4; kc++) {
#pragma unroll
            for (int d0 = 0; d0 < 8; d0++) {
                uint32_t r[4];
                ldsm4t(r, vS + (kc * 16 + v_row) * 272 + d0 * 32 + v_db);
                mma_f16(o[2 * d0],     pa[kc], r[0], r[1]);
                mma_f16(o[2 * d0 + 1], pa[kc], r[2], r[3]);
            }
        }
    }

    const float inv0 = 1.0f / l0;
    const float inv1 = 1.0f / l1;
    const size_t base0 = ((size_t)b * SEQ + q0 + g)     * 4096 + h * 128;
    const size_t base1 = ((size_t)b * SEQ + q0 + g + 8) * 4096 + h * 128;
#pragma unroll
    for (int n = 0; n < 16; n++) {
        *(__half2*)&O16[base0 + n * 8 + 2 * qc] =
            __floats2half2_rn(o[n][0] * inv0, o[n][1] * inv0);
        *(__half2*)&O16[base1 + n * 8 + 2 * qc] =
            __floats2half2_rn(o[n][2] * inv1, o[n][3] * inv1);
    }
}

// ---------------------------------------------------------------------------
extern "C" void kernel_launch(void* const* d_in, const int* in_sizes, int n_in,
                              void* d_out, int out_size)
{
    const float* x = (const float*)d_in[0];
    int off = (n_in >= 6 && in_sizes[1] <= 4) ? 2 : 1;
    const float* wq = (const float*)d_in[off + 0];
    const float* wk = (const float*)d_in[off + 1];
    const float* wv = (const float*)d_in[off + 2];
    const float* wo = (const float*)d_in[off + 3];
    float* out = (float*)d_out;

    __half *q, *k, *v;
    float *ct, *st;
    cudaGetSymbolAddress((void**)&q,  g_q);
    cudaGetSymbolAddress((void**)&k,  g_k);
    cudaGetSymbolAddress((void**)&v,  g_v);
    cudaGetSymbolAddress((void**)&ct, g_cos);
    cudaGetSymbolAddress((void**)&st, g_sin);

    __half *x16, *wq16, *wk16, *wv16, *wo16, *a16;
    cudaGetSymbolAddress((void**)&x16,  g_x16);
    cudaGetSymbolAddress((void**)&wq16, g_wq16);
    cudaGetSymbolAddress((void**)&wk16, g_wk16);
    cudaGetSymbolAddress((void**)&wv16, g_wv16);
    cudaGetSymbolAddress((void**)&wo16, g_wo16);
    cudaGetSymbolAddress((void**)&a16,  g_a16);

    cudaFuncSetAttribute(gemm_mma, cudaFuncAttributeMaxDynamicSharedMemorySize, 3 * STAGE_SZ);
    cudaFuncSetAttribute(attn_tc,  cudaFuncAttributeMaxDynamicSharedMemorySize, ATTN_SMEM);

    const int n4 = DIM * DIM / 4;
    const int cgrid = (n4 + 255) / 256;
    dim3 gg(DIM / 128, DIM / 128);

    const float SC   = 0.015625f;                        // 2^-6 (weights x64)
    const float SC_Q = SC * 0.08838834764831845f;        // fold 1/sqrt(128) into q

    rope_table<<<(SEQ * (HD / 2) + 255) / 256, 256>>>(ct, st);                      // 0
    split_act<<<cgrid, 256>>>(x, x16, n4);                                          // 1
    split_wt<<<cgrid, 256>>>(wq, wq16, n4);                                         // 2
    gemm_mma<<<gg, 256, 3 * STAGE_SZ>>>(x16, wq16, q, nullptr, SC_Q, ct, st);       // 3 (profiled)
    split_wt<<<cgrid, 256>>>(wk, wk16, n4);                                         // 4
    gemm_mma<<<gg, 256, 3 * STAGE_SZ>>>(x16, wk16, k, nullptr, SC, ct, st);         // 5
    split_wt<<<cgrid, 256>>>(wv, wv16, n4);                                         // 6
    gemm_mma<<<gg, 256, 3 * STAGE_SZ>>>(x16, wv16, v, nullptr, SC, nullptr, nullptr); // 7
    split_wt<<<cgrid, 256>>>(wo, wo16, n4);                                         // 8

    attn_tc<<<dim3(SEQ / 64, NH, BSZ), 128, ATTN_SMEM>>>(q, k, v, a16);             // 9

    gemm_mma<<<gg, 256, 3 * STAGE_SZ>>>(a16, wo16, nullptr, out, SC, nullptr, nullptr); // 10
}

// round 13
// speedup vs baseline: 3.1851x; 1.0039x over previous
#include <cuda_runtime.h>
#include <cuda_fp16.h>
#include <cstdint>
#include <math.h>

#define DIM   4096
#define NH    32
#define HD    128
#define BSZ   2
#define SEQ   2048

// ---------------- scratch (__device__ globals; no allocs allowed) ----------
__device__ __half g_q[BSZ*SEQ*DIM];
__device__ __half g_k[BSZ*SEQ*DIM];
__device__ __half g_v[BSZ*SEQ*DIM];
__device__ float  g_cos[SEQ*(HD/2)];
__device__ float  g_sin[SEQ*(HD/2)];

__device__ __half g_x16[DIM*DIM];
__device__ __half g_wq16[DIM*DIM];
__device__ __half g_wk16[DIM*DIM];
__device__ __half g_wv16[DIM*DIM];
__device__ __half g_wo16[DIM*DIM];
__device__ __half g_a16[DIM*DIM];

// ---------------- base-ISA helpers (compute_103-safe) ----------------------
__device__ __forceinline__ uint32_t smem_u32(const void* p) {
    uint32_t a;
    asm("{ .reg .u64 t; cvta.to.shared.u64 t, %1; cvt.u32.u64 %0, t; }" : "=r"(a) : "l"(p));
    return a;
}
__device__ __forceinline__ void cpa16(uint32_t saddr, const void* g) {
    asm volatile("cp.async.cg.shared.global [%0], [%1], 16;" :: "r"(saddr), "l"(g));
}
__device__ __forceinline__ void ldsm4(uint32_t* r, uint32_t addr) {
    asm volatile("ldmatrix.sync.aligned.m8n8.x4.shared.b16 {%0,%1,%2,%3}, [%4];"
        : "=r"(r[0]), "=r"(r[1]), "=r"(r[2]), "=r"(r[3]) : "r"(addr));
}
__device__ __forceinline__ void ldsm4t(uint32_t* r, uint32_t addr) {
    asm volatile("ldmatrix.sync.aligned.m8n8.x4.trans.shared.b16 {%0,%1,%2,%3}, [%4];"
        : "=r"(r[0]), "=r"(r[1]), "=r"(r[2]), "=r"(r[3]) : "r"(addr));
}
__device__ __forceinline__ void mma_f16(float* c, const uint32_t* a,
                                        uint32_t b0, uint32_t b1) {
    asm volatile("mma.sync.aligned.m16n8k16.row.col.f32.f16.f16.f32 "
        "{%0,%1,%2,%3}, {%4,%5,%6,%7}, {%8,%9}, {%0,%1,%2,%3};"
        : "+f"(c[0]), "+f"(c[1]), "+f"(c[2]), "+f"(c[3])
        : "r"(a[0]), "r"(a[1]), "r"(a[2]), "r"(a[3]), "r"(b0), "r"(b1));
}
__device__ __forceinline__ uint32_t pack_h2(float a, float b) {
    __half2 h = __floats2half2_rn(a, b);
    return *(uint32_t*)&h;
}
__device__ __forceinline__ uint32_t sw128(uint32_t off) {
    return off ^ ((off >> 3) & 0x70);
}

// ---------------------------------------------------------------------------
// casts
// ---------------------------------------------------------------------------
__global__ void split_act(const float* __restrict__ in, __half* __restrict__ o, int n4)
{
    int i = blockIdx.x * 256 + threadIdx.x;
    if (i >= n4) return;
    float4 v = ((const float4*)in)[i];
    ((__half2*)o)[2*i]   = __floats2half2_rn(v.x, v.y);
    ((__half2*)o)[2*i+1] = __floats2half2_rn(v.z, v.w);
}

__global__ void split_wt(const float* __restrict__ in, __half* __restrict__ o, int n4)
{
    int i = blockIdx.x * 256 + threadIdx.x;
    if (i >= n4) return;
    float4 v = ((const float4*)in)[i];
    ((__half2*)o)[2*i]   = __floats2half2_rn(v.x * 64.f, v.y * 64.f);
    ((__half2*)o)[2*i+1] = __floats2half2_rn(v.z * 64.f, v.w * 64.f);
}

// ---------------------------------------------------------------------------
// fp16 single-product GEMM (NT): C = sc * A16*B16, 4096^3.
// CTA 128x128, 4 warps (2Mx2N), warp tile 64x64, BK=64 (SW128),
// 3-stage cp.async pipeline, 2 CTAs/SM. Optional fused RoPE epilogue.
// ---------------------------------------------------------------------------
#define STAGE_SZ 32768
__global__ void __launch_bounds__(128, 2)
gemm_mma(const __half* __restrict__ A16, const __half* __restrict__ B16,
         __half* __restrict__ Ch, float* __restrict__ Cf, float sc,
         const float* __restrict__ Ct, const float* __restrict__ St)
{
    extern __shared__ char sm[];
    const uint32_t s0 = smem_u32(sm);

    const int tid  = threadIdx.x;
    const int wid  = tid >> 5;
    const int lane = tid & 31;
    const int bx = blockIdx.x;
    const int by = blockIdx.y;
    const int warp_m = wid >> 1;   // 0..1 (64 rows)
    const int warp_n = wid & 1;    // 0..1 (64 cols)

    float acc[4][8][4];
#pragma unroll
    for (int t = 0; t < 4; t++)
#pragma unroll
        for (int n = 0; n < 8; n++)
#pragma unroll
            for (int j = 0; j < 4; j++) acc[t][n][j] = 0.0f;

    auto load_stage = [&](int kt, int stage) {
        uint32_t sb = s0 + stage * STAGE_SZ;
#pragma unroll
        for (int i = 0; i < 8; i++) {
            int li = tid + i * 128;           // 0..1023
            int r = li >> 3, c = li & 7;
            uint32_t off = sw128((uint32_t)(r * 128 + c * 16));
            cpa16(sb + off,         A16 + (size_t)(by * 128 + r) * 4096 + kt * 64 + c * 8);
            cpa16(sb + 16384 + off, B16 + (size_t)(bx * 128 + r) * 4096 + kt * 64 + c * 8);
        }
        asm volatile("cp.async.commit_group;" ::: "memory");
    };

    const int lrow  = (lane & 7) + ((lane >> 3) & 1) * 8;
    const int khalf = (lane >> 4) * 16;

    const int NT = 4096 / 64;

    load_stage(0, 0);
    load_stage(1, 1);

    for (int kt = 0; kt < NT; kt++) {
        if (kt < NT - 1) asm volatile("cp.async.wait_group 1;" ::: "memory");
        else             asm volatile("cp.async.wait_group 0;" ::: "memory");
        __syncthreads();

        const uint32_t sbase = s0 + (kt % 3) * STAGE_SZ;
        if (kt + 2 < NT) load_stage(kt + 2, (kt + 2) % 3);

#pragma unroll
        for (int s = 0; s < 4; s++) {
            uint32_t ah[4][4], bh[4][4];
#pragma unroll
            for (int t = 0; t < 4; t++) {
                uint32_t off = sw128((uint32_t)((warp_m * 64 + t * 16 + lrow) * 128
                                                + khalf + s * 32));
                ldsm4(ah[t], sbase + off);
            }
#pragma unroll
            for (int u = 0; u < 4; u++) {
                uint32_t off = sw128((uint32_t)((warp_n * 64 + u * 16 + lrow) * 128
                                                + khalf + s * 32));
                ldsm4(bh[u], sbase + 16384 + off);
            }
#pragma unroll
            for (int t = 0; t < 4; t++)
#pragma unroll
                for (int u = 0; u < 4; u++)
#pragma unroll
                    for (int j = 0; j < 2; j++)
                        mma_f16(acc[t][u * 2 + j], ah[t], bh[u][j], bh[u][j + 2]);
        }
    }

    const int g  = lane >> 2;
    const int qc = lane & 3;
    if (Ch) {
#pragma unroll
        for (int t = 0; t < 4; t++) {
            const int row = by * 128 + warp_m * 64 + t * 16 + g;
#pragma unroll
            for (int n = 0; n < 8; n++) {
                const int col = bx * 128 + warp_n * 64 + n * 8 + qc * 2;
                float x0 = acc[t][n][0] * sc, x1 = acc[t][n][1] * sc;
                float y0 = acc[t][n][2] * sc, y1 = acc[t][n][3] * sc;
                if (Ct) {   // fused interleaved RoPE
                    const int jj = (col & 127) >> 1;
                    float c0 = Ct[(row & 2047) * 64 + jj];
                    float s0 = St[(row & 2047) * 64 + jj];
                    float c1 = Ct[((row + 8) & 2047) * 64 + jj];
                    float s1 = St[((row + 8) & 2047) * 64 + jj];
                    float nx0 = x0 * c0 - x1 * s0, nx1 = x0 * s0 + x1 * c0;
                    float ny0 = y0 * c1 - y1 * s1, ny1 = y0 * s1 + y1 * c1;
                    x0 = nx0; x1 = nx1; y0 = ny0; y1 = ny1;
                }
                *(__half2*)&Ch[(size_t)row * 4096 + col] = __floats2half2_rn(x0, x1);
                *(__half2*)&Ch[(size_t)(row + 8) * 4096 + col] = __floats2half2_rn(y0, y1);
            }
        }
    } else {
#pragma unroll
        for (int t = 0; t < 4; t++) {
            const int row = by * 128 + warp_m * 64 + t * 16 + g;
#pragma unroll
            for (int n = 0; n < 8; n++) {
                const int col = bx * 128 + warp_n * 64 + n * 8 + qc * 2;
                *(float2*)&Cf[(size_t)row * 4096 + col] =
                    make_float2(acc[t][n][0] * sc, acc[t][n][1] * sc);
                *(float2*)&Cf[(size_t)(row + 8) * 4096 + col] =
                    make_float2(acc[t][n][2] * sc, acc[t][n][3] * sc);
            }
        }
    }
}

// ---------------------------------------------------------------------------
// RoPE table: fp64 inv_freq via per-block smem table, fp64 arg + fmod,
// fp32 sincos (error ~5e-7, negligible vs fp16 quantization)
// ---------------------------------------------------------------------------
__global__ void rope_table(float* ct, float* st)
{
    __shared__ double sinv[64];
    if (threadIdx.x < 64)
        sinv[threadIdx.x] = pow(10000.0, -(double)threadIdx.x / 64.0);
    __syncthreads();

    int idx = blockIdx.x * 256 + threadIdx.x;
    if (idx >= SEQ * (HD / 2)) return;
    int s = idx >> 6;
    int j = idx & 63;
    double a = fmod((double)s * sinv[j], 6.283185307179586477);
    float af = (float)a;
    float cf, sf;
    sincosf(af, &sf, &cf);
    ct[idx] = cf;
    st[idx] = sf;
}

// ---------------------------------------------------------------------------
// Causal flash attention, all-fp16 mma + ldmatrix (unchanged from R12).
// ---------------------------------------------------------------------------
#define KVW 68
#define ATTN_SMEM (2 * 64 * KVW * 4)

__global__ void __launch_bounds__(128)
attn_tc(const __half* __restrict__ Qh, const __half* __restrict__ Kh,
        const __half* __restrict__ Vh, __half* __restrict__ O16)
{
    extern __shared__ uint32_t smu[];
    uint32_t* KsU = smu;
    uint32_t* VsU = smu + 64 * KVW;

    const int tid  = threadIdx.x;
    const int w    = tid >> 5;
    const int lane = tid & 31;
    const int qt = blockIdx.x;
    const int h  = blockIdx.y;
    const int b  = blockIdx.z;
    const int g  = lane >> 2;
    const int qc = lane & 3;

    const uint32_t kS = smem_u32(KsU);
    const uint32_t vS = smem_u32(VsU);

    const uint32_t k_row = (lane & 7) + ((lane >> 4) & 1) * 8;
    const uint32_t k_db  = ((lane >> 3) & 1) * 16;
    const uint32_t v_row = (lane & 7) + ((lane >> 3) & 1) * 8;
    const uint32_t v_db  = ((lane >> 4) & 1) * 16;

    const int q0 = qt * 64 + w * 16;

    uint32_t qa[8][4];
    {
        const uint32_t* q_r0 = (const uint32_t*)(Qh + ((size_t)b * SEQ + q0 + g)     * 4096 + h * 128);
        const uint32_t* q_r1 = (const uint32_t*)(Qh + ((size_t)b * SEQ + q0 + g + 8) * 4096 + h * 128);
#pragma unroll
        for (int kc = 0; kc < 8; kc++) {
            qa[kc][0] = q_r0[kc * 8 + qc];
            qa[kc][1] = q_r1[kc * 8 + qc];
            qa[kc][2] = q_r0[kc * 8 + qc + 4];
            qa[kc][3] = q_r1[kc * 8 + qc + 4];
        }
    }

    float o[16][4];
#pragma unroll
    for (int n = 0; n < 16; n++)
#pragma unroll
        for (int j = 0; j < 4; j++) o[n][j] = 0.0f;
    float m0 = -1e30f, m1 = -1e30f, l0 = 0.0f, l1 = 0.0f;

    for (int kt = 0; kt <= qt; kt++) {
        if (kt) __syncthreads();
#pragma unroll
        for (int i = 0; i < 8; i++) {
            int li = tid + i * 128;
            int row = li >> 4, c = li & 15;
            size_t gsrc = ((size_t)b * SEQ + kt * 64 + row) * 4096 + h * 128 + c * 8;
            *(uint4*)&KsU[row * KVW + c * 4] = *(const uint4*)(Kh + gsrc);
            *(uint4*)&VsU[row * KVW + c * 4] = *(const uint4*)(Vh + gsrc);
        }
        __syncthreads();

        float sreg[8][4];
#pragma unroll
        for (int j = 0; j < 8; j++)
            sreg[j][0] = sreg[j][1] = sreg[j][2] = sreg[j][3] = 0.0f;
#pragma unroll
        for (int kc = 0; kc < 8; kc++) {
#pragma unroll
            for (int j2 = 0; j2 < 4; j2++) {
                uint32_t r[4];
                ldsm4(r, kS + (j2 * 16 + k_row) * 272 + kc * 32 + k_db);
                mma_f16(sreg[2 * j2],     qa[kc], r[0], r[1]);
                mma_f16(sreg[2 * j2 + 1], qa[kc], r[2], r[3]);
            }
        }

        if (kt == qt) {
            const int kb = kt * 64;
#pragma unroll
            for (int j = 0; j < 8; j++) {
                int key0 = kb + j * 8 + 2 * qc;
                if (key0     > q0 + g)     sreg[j][0] = -1e30f;
                if (key0 + 1 > q0 + g)     sreg[j][1] = -1e30f;
                if (key0     > q0 + g + 8) sreg[j][2] = -1e30f;
                if (key0 + 1 > q0 + g + 8) sreg[j][3] = -1e30f;
            }
        }

        float mx0 = -1e30f, mx1 = -1e30f;
#pragma unroll
        for (int j = 0; j < 8; j++) {
            mx0 = fmaxf(mx0, fmaxf(sreg[j][0], sreg[j][1]));
            mx1 = fmaxf(mx1, fmaxf(sreg[j][2], sreg[j][3]));
        }
        mx0 = fmaxf(mx0, __shfl_xor_sync(0xffffffffu, mx0, 1));
        mx0 = fmaxf(mx0, __shfl_xor_sync(0xffffffffu, mx0, 2));
        mx1 = fmaxf(mx1, __shfl_xor_sync(0xffffffffu, mx1, 1));
        mx1 = fmaxf(mx1, __shfl_xor_sync(0xffffffffu, mx1, 2));
        float mn0 = fmaxf(m0, mx0), mn1 = fmaxf(m1, mx1);
        float f0 = __expf(m0 - mn0), f1 = __expf(m1 - mn1);
        m0 = mn0; m1 = mn1;

        float sum0 = 0.0f, sum1 = 0.0f;
#pragma unroll
        for (int j = 0; j < 8; j++) {
            sreg[j][0] = __expf(sreg[j][0] - mn0);
            sreg[j][1] = __expf(sreg[j][1] - mn0);
            sreg[j][2] = __expf(sreg[j][2] - mn1);
            sreg[j][3] = __expf(sreg[j][3] - mn1);
            sum0 += sreg[j][0] + sreg[j][1];
            sum1 += sreg[j][2] + sreg[j][3];
        }
        sum0 += __shfl_xor_sync(0xffffffffu, sum0, 1);
        sum0 += __shfl_xor_sync(0xffffffffu, sum0, 2);
        sum1 += __shfl_xor_sync(0xffffffffu, sum1, 1);
        sum1 += __shfl_xor_sync(0xffffffffu, sum1, 2);
        l0 = l0 * f0 + sum0;
        l1 = l1 * f1 + sum1;

#pragma unroll
        for (int n = 0; n < 16; n++) {
            o[n][0] *= f0; o[n][1] *= f0;
            o[n][2] *= f1; o[n][3] *= f1;
        }

        uint32_t pa[4][4];
#pragma unroll
        for (int kc = 0; kc < 4; kc++) {
            pa[kc][0] = pack_h2(sreg[2 * kc][0],     sreg[2 * kc][1]);
            pa[kc][1] = pack_h2(sreg[2 * kc][2],     sreg[2 * kc][3]);
            pa[kc][2] = pack_h2(sreg[2 * kc + 1][0], sreg[2 * kc + 1][1]);
            pa[kc][3] = pack_h2(sreg[2 * kc + 1][2], sreg[2 * kc + 1][3]);
        }

#pragma unroll
        for (int kc = 0; kc < 4; kc++) {
#pragma unroll
            for (int d0 = 0; d0 < 8; d0++) {
                uint32_t r[4];
                ldsm4t(r, vS + (kc * 16 + v_row) * 272 + d0 * 32 + v_db);
                mma_f16(o[2 * d0],     pa[kc], r[0], r[1]);
                mma_f16(o[2 * d0 + 1], pa[kc], r[2], r[3]);
            }
        }
    }

    const float inv0 = 1.0f / l0;
    const float inv1 = 1.0f / l1;
    const size_t base0 = ((size_t)b * SEQ + q0 + g)     * 4096 + h * 128;
    const size_t base1 = ((size_t)b * SEQ + q0 + g + 8) * 4096 + h * 128;
#pragma unroll
    for (int n = 0; n < 16; n++) {
        *(__half2*)&O16[base0 + n * 8 + 2 * qc] =
            __floats2half2_rn(o[n][0] * inv0, o[n][1] * inv0);
        *(__half2*)&O16[base1 + n * 8 + 2 * qc] =
            __floats2half2_rn(o[n][2] * inv1, o[n][3] * inv1);
    }
}

// ---------------------------------------------------------------------------
extern "C" void kernel_launch(void* const* d_in, const int* in_sizes, int n_in,
                              void* d_out, int out_size)
{
    const float* x = (const float*)d_in[0];
    int off = (n_in >= 6 && in_sizes[1] <= 4) ? 2 : 1;
    const float* wq = (const float*)d_in[off + 0];
    const float* wk = (const float*)d_in[off + 1];
    const float* wv = (const float*)d_in[off + 2];
    const float* wo = (const float*)d_in[off + 3];
    float* out = (float*)d_out;

    __half *q, *k, *v;
    float *ct, *st;
    cudaGetSymbolAddress((void**)&q,  g_q);
    cudaGetSymbolAddress((void**)&k,  g_k);
    cudaGetSymbolAddress((void**)&v,  g_v);
    cudaGetSymbolAddress((void**)&ct, g_cos);
    cudaGetSymbolAddress((void**)&st, g_sin);

    __half *x16, *wq16, *wk16, *wv16, *wo16, *a16;
    cudaGetSymbolAddress((void**)&x16,  g_x16);
    cudaGetSymbolAddress((void**)&wq16, g_wq16);
    cudaGetSymbolAddress((void**)&wk16, g_wk16);
    cudaGetSymbolAddress((void**)&wv16, g_wv16);
    cudaGetSymbolAddress((void**)&wo16, g_wo16);
    cudaGetSymbolAddress((void**)&a16,  g_a16);

    cudaFuncSetAttribute(gemm_mma, cudaFuncAttributeMaxDynamicSharedMemorySize, 3 * STAGE_SZ);
    cudaFuncSetAttribute(attn_tc,  cudaFuncAttributeMaxDynamicSharedMemorySize, ATTN_SMEM);

    const int n4 = DIM * DIM / 4;
    const int cgrid = (n4 + 255) / 256;
    dim3 gg(DIM / 128, DIM / 128);

    const float SC   = 0.015625f;                        // 2^-6 (weights x64)
    const float SC_Q = SC * 0.08838834764831845f;        // fold 1/sqrt(128) into q

    rope_table<<<(SEQ * (HD / 2) + 255) / 256, 256>>>(ct, st);                      // 0
    split_act<<<cgrid, 256>>>(x, x16, n4);                                          // 1
    split_wt<<<cgrid, 256>>>(wq, wq16, n4);                                         // 2
    gemm_mma<<<gg, 128, 3 * STAGE_SZ>>>(x16, wq16, q, nullptr, SC_Q, ct, st);       // 3 (profiled)
    split_wt<<<cgrid, 256>>>(wk, wk16, n4);                                         // 4
    gemm_mma<<<gg, 128, 3 * STAGE_SZ>>>(x16, wk16, k, nullptr, SC, ct, st);         // 5
    split_wt<<<cgrid, 256>>>(wv, wv16, n4);                                         // 6
    gemm_mma<<<gg, 128, 3 * STAGE_SZ>>>(x16, wv16, v, nullptr, SC, nullptr, nullptr); // 7
    split_wt<<<cgrid, 256>>>(wo, wo16, n4);                                         // 8

    attn_tc<<<dim3(SEQ / 64, NH, BSZ), 128, ATTN_SMEM>>>(q, k, v, a16);             // 9

    gemm_mma<<<gg, 128, 3 * STAGE_SZ>>>(a16, wo16, nullptr, out, SC, nullptr, nullptr); // 10
}

// round 14
// speedup vs baseline: 3.3301x; 1.0455x over previous
#include <cuda_runtime.h>
#include <cuda_fp16.h>
#include <cstdint>
#include <math.h>

#define DIM   4096
#define NH    32
#define HD    128
#define BSZ   2
#define SEQ   2048

// ---------------- scratch (__device__ globals; no allocs allowed) ----------
__device__ __half g_q[BSZ*SEQ*DIM];
__device__ __half g_k[BSZ*SEQ*DIM];
__device__ __half g_v[BSZ*SEQ*DIM];
__device__ float  g_cos[SEQ*(HD/2)];
__device__ float  g_sin[SEQ*(HD/2)];

__device__ __half g_x16[DIM*DIM];
__device__ __half g_wq16[DIM*DIM];
__device__ __half g_wk16[DIM*DIM];
__device__ __half g_wv16[DIM*DIM];
__device__ __half g_wo16[DIM*DIM];
__device__ __half g_a16[DIM*DIM];

// ---------------- base-ISA helpers (compute_103-safe) ----------------------
__device__ __forceinline__ uint32_t smem_u32(const void* p) {
    uint32_t a;
    asm("{ .reg .u64 t; cvta.to.shared.u64 t, %1; cvt.u32.u64 %0, t; }" : "=r"(a) : "l"(p));
    return a;
}
__device__ __forceinline__ void cpa16(uint32_t saddr, const void* g) {
    asm volatile("cp.async.cg.shared.global [%0], [%1], 16;" :: "r"(saddr), "l"(g));
}
__device__ __forceinline__ void ldsm4(uint32_t* r, uint32_t addr) {
    asm volatile("ldmatrix.sync.aligned.m8n8.x4.shared.b16 {%0,%1,%2,%3}, [%4];"
        : "=r"(r[0]), "=r"(r[1]), "=r"(r[2]), "=r"(r[3]) : "r"(addr));
}
__device__ __forceinline__ void ldsm4t(uint32_t* r, uint32_t addr) {
    asm volatile("ldmatrix.sync.aligned.m8n8.x4.trans.shared.b16 {%0,%1,%2,%3}, [%4];"
        : "=r"(r[0]), "=r"(r[1]), "=r"(r[2]), "=r"(r[3]) : "r"(addr));
}
__device__ __forceinline__ void mma_f16(float* c, const uint32_t* a,
                                        uint32_t b0, uint32_t b1) {
    asm volatile("mma.sync.aligned.m16n8k16.row.col.f32.f16.f16.f32 "
        "{%0,%1,%2,%3}, {%4,%5,%6,%7}, {%8,%9}, {%0,%1,%2,%3};"
        : "+f"(c[0]), "+f"(c[1]), "+f"(c[2]), "+f"(c[3])
        : "r"(a[0]), "r"(a[1]), "r"(a[2]), "r"(a[3]), "r"(b0), "r"(b1));
}
__device__ __forceinline__ uint32_t pack_h2(float a, float b) {
    __half2 h = __floats2half2_rn(a, b);
    return *(uint32_t*)&h;
}
__device__ __forceinline__ uint32_t sw128(uint32_t off) {
    return off ^ ((off >> 3) & 0x70);
}

// ---------------------------------------------------------------------------
// casts
// ---------------------------------------------------------------------------
__global__ void split_act(const float* __restrict__ in, __half* __restrict__ o, int n4)
{
    int i = blockIdx.x * 256 + threadIdx.x;
    if (i >= n4) return;
    float4 v = ((const float4*)in)[i];
    ((__half2*)o)[2*i]   = __floats2half2_rn(v.x, v.y);
    ((__half2*)o)[2*i+1] = __floats2half2_rn(v.z, v.w);
}

__global__ void split_wt(const float* __restrict__ in, __half* __restrict__ o, int n4)
{
    int i = blockIdx.x * 256 + threadIdx.x;
    if (i >= n4) return;
    float4 v = ((const float4*)in)[i];
    ((__half2*)o)[2*i]   = __floats2half2_rn(v.x * 64.f, v.y * 64.f);
    ((__half2*)o)[2*i+1] = __floats2half2_rn(v.z * 64.f, v.w * 64.f);
}

// ---------------------------------------------------------------------------
// fp16 single-product GEMM (NT): C = sc * A16*B16, 4096^3.  (R12 config)
// CTA 128x128, 8 warps (4Mx2N), warp tile 32x64, BK=64 (SW128),
// 3-stage cp.async pipeline, 2 CTAs/SM. Optional fused RoPE epilogue.
// ---------------------------------------------------------------------------
#define STAGE_SZ 32768
__global__ void __launch_bounds__(256, 2)
gemm_mma(const __half* __restrict__ A16, const __half* __restrict__ B16,
         __half* __restrict__ Ch, float* __restrict__ Cf, float sc,
         const float* __restrict__ Ct, const float* __restrict__ St)
{
    extern __shared__ char sm[];
    const uint32_t s0 = smem_u32(sm);

    const int tid  = threadIdx.x;
    const int wid  = tid >> 5;
    const int lane = tid & 31;
    const int bx = blockIdx.x;
    const int by = blockIdx.y;
    const int warp_m = wid >> 1;
    const int warp_n = wid & 1;

    float acc[2][8][4];
#pragma unroll
    for (int t = 0; t < 2; t++)
#pragma unroll
        for (int n = 0; n < 8; n++)
#pragma unroll
            for (int j = 0; j < 4; j++) acc[t][n][j] = 0.0f;

    auto load_stage = [&](int kt, int stage) {
        uint32_t sb = s0 + stage * STAGE_SZ;
#pragma unroll
        for (int i = 0; i < 4; i++) {
            int li = tid + i * 256;
            int r = li >> 3, c = li & 7;
            uint32_t off = sw128((uint32_t)(r * 128 + c * 16));
            cpa16(sb + off,         A16 + (size_t)(by * 128 + r) * 4096 + kt * 64 + c * 8);
            cpa16(sb + 16384 + off, B16 + (size_t)(bx * 128 + r) * 4096 + kt * 64 + c * 8);
        }
        asm volatile("cp.async.commit_group;" ::: "memory");
    };

    const int lrow  = (lane & 7) + ((lane >> 3) & 1) * 8;
    const int khalf = (lane >> 4) * 16;

    const int NT = 4096 / 64;

    load_stage(0, 0);
    load_stage(1, 1);

    for (int kt = 0; kt < NT; kt++) {
        if (kt < NT - 1) asm volatile("cp.async.wait_group 1;" ::: "memory");
        else             asm volatile("cp.async.wait_group 0;" ::: "memory");
        __syncthreads();

        const uint32_t sbase = s0 + (kt % 3) * STAGE_SZ;
        if (kt + 2 < NT) load_stage(kt + 2, (kt + 2) % 3);

#pragma unroll
        for (int s = 0; s < 4; s++) {
            uint32_t ah[2][4], bh[4][4];
#pragma unroll
            for (int t = 0; t < 2; t++) {
                uint32_t off = sw128((uint32_t)((warp_m * 32 + t * 16 + lrow) * 128
                                                + khalf + s * 32));
                ldsm4(ah[t], sbase + off);
            }
#pragma unroll
            for (int u = 0; u < 4; u++) {
                uint32_t off = sw128((uint32_t)((warp_n * 64 + u * 16 + lrow) * 128
                                                + khalf + s * 32));
                ldsm4(bh[u], sbase + 16384 + off);
            }
#pragma unroll
            for (int t = 0; t < 2; t++)
#pragma unroll
                for (int u = 0; u < 4; u++)
#pragma unroll
                    for (int j = 0; j < 2; j++)
                        mma_f16(acc[t][u * 2 + j], ah[t], bh[u][j], bh[u][j + 2]);
        }
    }

    const int g  = lane >> 2;
    const int qc = lane & 3;
    if (Ch) {
#pragma unroll
        for (int t = 0; t < 2; t++) {
            const int row = by * 128 + warp_m * 32 + t * 16 + g;
#pragma unroll
            for (int n = 0; n < 8; n++) {
                const int col = bx * 128 + warp_n * 64 + n * 8 + qc * 2;
                float x0 = acc[t][n][0] * sc, x1 = acc[t][n][1] * sc;
                float y0 = acc[t][n][2] * sc, y1 = acc[t][n][3] * sc;
                if (Ct) {
                    const int jj = (col & 127) >> 1;
                    float c0 = Ct[(row & 2047) * 64 + jj];
                    float s0 = St[(row & 2047) * 64 + jj];
                    float c1 = Ct[((row + 8) & 2047) * 64 + jj];
                    float s1 = St[((row + 8) & 2047) * 64 + jj];
                    float nx0 = x0 * c0 - x1 * s0, nx1 = x0 * s0 + x1 * c0;
                    float ny0 = y0 * c1 - y1 * s1, ny1 = y0 * s1 + y1 * c1;
                    x0 = nx0; x1 = nx1; y0 = ny0; y1 = ny1;
                }
                *(__half2*)&Ch[(size_t)row * 4096 + col] = __floats2half2_rn(x0, x1);
                *(__half2*)&Ch[(size_t)(row + 8) * 4096 + col] = __floats2half2_rn(y0, y1);
            }
        }
    } else {
#pragma unroll
        for (int t = 0; t < 2; t++) {
            const int row = by * 128 + warp_m * 32 + t * 16 + g;
#pragma unroll
            for (int n = 0; n < 8; n++) {
                const int col = bx * 128 + warp_n * 64 + n * 8 + qc * 2;
                *(float2*)&Cf[(size_t)row * 4096 + col] =
                    make_float2(acc[t][n][0] * sc, acc[t][n][1] * sc);
                *(float2*)&Cf[(size_t)(row + 8) * 4096 + col] =
                    make_float2(acc[t][n][2] * sc, acc[t][n][3] * sc);
            }
        }
    }
}

// ---------------------------------------------------------------------------
// RoPE table
// ---------------------------------------------------------------------------
__global__ void rope_table(float* ct, float* st)
{
    __shared__ double sinv[64];
    if (threadIdx.x < 64)
        sinv[threadIdx.x] = pow(10000.0, -(double)threadIdx.x / 64.0);
    __syncthreads();

    int idx = blockIdx.x * 256 + threadIdx.x;
    if (idx >= SEQ * (HD / 2)) return;
    int s = idx >> 6;
    int j = idx & 63;
    double a = fmod((double)s * sinv[j], 6.283185307179586477);
    float cf, sf;
    sincosf((float)a, &sf, &cf);
    ct[idx] = cf;
    st[idx] = sf;
}

// ---------------------------------------------------------------------------
// Causal flash attention, all-fp16 mma + ldmatrix.
// Block 256 threads (8 warps); Q tile 128 rows (16/warp), K tile 64 keys.
// Halved K/V L2 traffic vs 64-row q tiles. Warps skip fully-future k tiles.
// ---------------------------------------------------------------------------
#define KVW 68
#define ATTN_SMEM (2 * 64 * KVW * 4)

__global__ void __launch_bounds__(256)
attn_tc(const __half* __restrict__ Qh, const __half* __restrict__ Kh,
        const __half* __restrict__ Vh, __half* __restrict__ O16)
{
    extern __shared__ uint32_t smu[];
    uint32_t* KsU = smu;
    uint32_t* VsU = smu + 64 * KVW;

    const int tid  = threadIdx.x;
    const int w    = tid >> 5;
    const int lane = tid & 31;
    const int qt = blockIdx.x;          // 128-row q tile
    const int h  = blockIdx.y;
    const int b  = blockIdx.z;
    const int g  = lane >> 2;
    const int qc = lane & 3;

    const uint32_t kS = smem_u32(KsU);
    const uint32_t vS = smem_u32(VsU);

    const uint32_t k_row = (lane & 7) + ((lane >> 4) & 1) * 8;
    const uint32_t k_db  = ((lane >> 3) & 1) * 16;
    const uint32_t v_row = (lane & 7) + ((lane >> 3) & 1) * 8;
    const uint32_t v_db  = ((lane >> 4) & 1) * 16;

    const int q0 = qt * 128 + w * 16;

    uint32_t qa[8][4];
    {
        const uint32_t* q_r0 = (const uint32_t*)(Qh + ((size_t)b * SEQ + q0 + g)     * 4096 + h * 128);
        const uint32_t* q_r1 = (const uint32_t*)(Qh + ((size_t)b * SEQ + q0 + g + 8) * 4096 + h * 128);
#pragma unroll
        for (int kc = 0; kc < 8; kc++) {
            qa[kc][0] = q_r0[kc * 8 + qc];
            qa[kc][1] = q_r1[kc * 8 + qc];
            qa[kc][2] = q_r0[kc * 8 + qc + 4];
            qa[kc][3] = q_r1[kc * 8 + qc + 4];
        }
    }

    float o[16][4];
#pragma unroll
    for (int n = 0; n < 16; n++)
#pragma unroll
        for (int j = 0; j < 4; j++) o[n][j] = 0.0f;
    float m0 = -1e30f, m1 = -1e30f, l0 = 0.0f, l1 = 0.0f;

    const int NKT = 2 * qt + 2;          // k tiles covering rows [0, 128qt+128)

    for (int kt = 0; kt < NKT; kt++) {
        const int kb = kt * 64;
        if (kt) __syncthreads();
        // stage K,V (256 threads, 4 iterations)
#pragma unroll
        for (int i = 0; i < 4; i++) {
            int li = tid + i * 256;
            int row = li >> 4, c = li & 15;
            size_t gsrc = ((size_t)b * SEQ + kb + row) * 4096 + h * 128 + c * 8;
            *(uint4*)&KsU[row * KVW + c * 4] = *(const uint4*)(Kh + gsrc);
            *(uint4*)&VsU[row * KVW + c * 4] = *(const uint4*)(Vh + gsrc);
        }
        __syncthreads();

        if (kb > q0 + 15) continue;      // tile entirely in this warp's future

        float sreg[8][4];
#pragma unroll
        for (int j = 0; j < 8; j++)
            sreg[j][0] = sreg[j][1] = sreg[j][2] = sreg[j][3] = 0.0f;
#pragma unroll
        for (int kc = 0; kc < 8; kc++) {
#pragma unroll
            for (int j2 = 0; j2 < 4; j2++) {
                uint32_t r[4];
                ldsm4(r, kS + (j2 * 16 + k_row) * 272 + kc * 32 + k_db);
                mma_f16(sreg[2 * j2],     qa[kc], r[0], r[1]);
                mma_f16(sreg[2 * j2 + 1], qa[kc], r[2], r[3]);
            }
        }

        if (kb + 63 > q0) {              // tile overlaps this warp's diagonal
#pragma unroll
            for (int j = 0; j < 8; j++) {
                int key0 = kb + j * 8 + 2 * qc;
                if (key0     > q0 + g)     sreg[j][0] = -1e30f;
                if (key0 + 1 > q0 + g)     sreg[j][1] = -1e30f;
                if (key0     > q0 + g + 8) sreg[j][2] = -1e30f;
                if (key0 + 1 > q0 + g + 8) sreg[j][3] = -1e30f;
            }
        }

        float mx0 = -1e30f, mx1 = -1e30f;
#pragma unroll
        for (int j = 0; j < 8; j++) {
            mx0 = fmaxf(mx0, fmaxf(sreg[j][0], sreg[j][1]));
            mx1 = fmaxf(mx1, fmaxf(sreg[j][2], sreg[j][3]));
        }
        mx0 = fmaxf(mx0, __shfl_xor_sync(0xffffffffu, mx0, 1));
        mx0 = fmaxf(mx0, __shfl_xor_sync(0xffffffffu, mx0, 2));
        mx1 = fmaxf(mx1, __shfl_xor_sync(0xffffffffu, mx1, 1));
        mx1 = fmaxf(mx1, __shfl_xor_sync(0xffffffffu, mx1, 2));
        float mn0 = fmaxf(m0, mx0), mn1 = fmaxf(m1, mx1);
        float f0 = __expf(m0 - mn0), f1 = __expf(m1 - mn1);
        m0 = mn0; m1 = mn1;

        float sum0 = 0.0f, sum1 = 0.0f;
#pragma unroll
        for (int j = 0; j < 8; j++) {
            sreg[j][0] = __expf(sreg[j][0] - mn0);
            sreg[j][1] = __expf(sreg[j][1] - mn0);
            sreg[j][2] = __expf(sreg[j][2] - mn1);
            sreg[j][3] = __expf(sreg[j][3] - mn1);
            sum0 += sreg[j][0] + sreg[j][1];
            sum1 += sreg[j][2] + sreg[j][3];
        }
        sum0 += __shfl_xor_sync(0xffffffffu, sum0, 1);
        sum0 += __shfl_xor_sync(0xffffffffu, sum0, 2);
        sum1 += __shfl_xor_sync(0xffffffffu, sum1, 1);
        sum1 += __shfl_xor_sync(0xffffffffu, sum1, 2);
        l0 = l0 * f0 + sum0;
        l1 = l1 * f1 + sum1;

#pragma unroll
        for (int n = 0; n < 16; n++) {
            o[n][0] *= f0; o[n][1] *= f0;
            o[n][2] *= f1; o[n][3] *= f1;
        }

        uint32_t pa[4][4];
#pragma unroll
        for (int kc = 0; kc < 4; kc++) {
            pa[kc][0] = pack_h2(sreg[2 * kc][0],     sreg[2 * kc][1]);
            pa[kc][1] = pack_h2(sreg[2 * kc][2],     sreg[2 * kc][3]);
            pa[kc][2] = pack_h2(sreg[2 * kc + 1][0], sreg[2 * kc + 1][1]);
            pa[kc][3] = pack_h2(sreg[2 * kc + 1][2], sreg[2 * kc + 1][3]);
        }

#pragma unroll
        for (int kc = 0; kc < 4; kc++) {
#pragma unroll
            for (int d0 = 0; d0 < 8; d0++) {
                uint32_t r[4];
                ldsm4t(r, vS + (kc * 16 + v_row) * 272 + d0 * 32 + v_db);
                mma_f16(o[2 * d0],     pa[kc], r[0], r[1]);
                mma_f16(o[2 * d0 + 1], pa[kc], r[2], r[3]);
            }
        }
    }

    const float inv0 = 1.0f / l0;
    const float inv1 = 1.0f / l1;
    const size_t base0 = ((size_t)b * SEQ + q0 + g)     * 4096 + h * 128;
    const size_t base1 = ((size_t)b * SEQ + q0 + g + 8) * 4096 + h * 128;
#pragma unroll
    for (int n = 0; n < 16; n++) {
        *(__half2*)&O16[base0 + n * 8 + 2 * qc] =
            __floats2half2_rn(o[n][0] * inv0, o[n][1] * inv0);
        *(__half2*)&O16[base1 + n * 8 + 2 * qc] =
            __floats2half2_rn(o[n][2] * inv1, o[n][3] * inv1);
    }
}

// ---------------------------------------------------------------------------
extern "C" void kernel_launch(void* const* d_in, const int* in_sizes, int n_in,
                              void* d_out, int out_size)
{
    const float* x = (const float*)d_in[0];
    int off = (n_in >= 6 && in_sizes[1] <= 4) ? 2 : 1;
    const float* wq = (const float*)d_in[off + 0];
    const float* wk = (const float*)d_in[off + 1];
    const float* wv = (const float*)d_in[off + 2];
    const float* wo = (const float*)d_in[off + 3];
    float* out = (float*)d_out;

    __half *q, *k, *v;
    float *ct, *st;
    cudaGetSymbolAddress((void**)&q,  g_q);
    cudaGetSymbolAddress((void**)&k,  g_k);
    cudaGetSymbolAddress((void**)&v,  g_v);
    cudaGetSymbolAddress((void**)&ct, g_cos);
    cudaGetSymbolAddress((void**)&st, g_sin);

    __half *x16, *wq16, *wk16, *wv16, *wo16, *a16;
    cudaGetSymbolAddress((void**)&x16,  g_x16);
    cudaGetSymbolAddress((void**)&wq16, g_wq16);
    cudaGetSymbolAddress((void**)&wk16, g_wk16);
    cudaGetSymbolAddress((void**)&wv16, g_wv16);
    cudaGetSymbolAddress((void**)&wo16, g_wo16);
    cudaGetSymbolAddress((void**)&a16,  g_a16);

    cudaFuncSetAttribute(gemm_mma, cudaFuncAttributeMaxDynamicSharedMemorySize, 3 * STAGE_SZ);
    cudaFuncSetAttribute(attn_tc,  cudaFuncAttributeMaxDynamicSharedMemorySize, ATTN_SMEM);

    const int n4 = DIM * DIM / 4;
    const int cgrid = (n4 + 255) / 256;
    dim3 gg(DIM / 128, DIM / 128);

    const float SC   = 0.015625f;                        // 2^-6 (weights x64)
    const float SC_Q = SC * 0.08838834764831845f;        // fold 1/sqrt(128) into q

    rope_table<<<(SEQ * (HD / 2) + 255) / 256, 256>>>(ct, st);                      // 0
    split_act<<<cgrid, 256>>>(x, x16, n4);                                          // 1
    split_wt<<<cgrid, 256>>>(wq, wq16, n4);                                         // 2
    gemm_mma<<<gg, 256, 3 * STAGE_SZ>>>(x16, wq16, q, nullptr, SC_Q, ct, st);       // 3 (profiled)
    split_wt<<<cgrid, 256>>>(wk, wk16, n4);                                         // 4
    gemm_mma<<<gg, 256, 3 * STAGE_SZ>>>(x16, wk16, k, nullptr, SC, ct, st);         // 5
    split_wt<<<cgrid, 256>>>(wv, wv16, n4);                                         // 6
    gemm_mma<<<gg, 256, 3 * STAGE_SZ>>>(x16, wv16, v, nullptr, SC, nullptr, nullptr); // 7
    split_wt<<<cgrid, 256>>>(wo, wo16, n4);                                         // 8

    attn_tc<<<dim3(SEQ / 128, NH, BSZ), 256, ATTN_SMEM>>>(q, k, v, a16);            // 9

    gemm_mma<<<gg, 256, 3 * STAGE_SZ>>>(a16, wo16, nullptr, out, SC, nullptr, nullptr); // 10
}

// round 15
// speedup vs baseline: 3.4102x; 1.0240x over previous
#include <cuda_runtime.h>
#include <cuda_fp16.h>
#include <cstdint>
#include <math.h>

#define DIM   4096
#define NH    32
#define HD    128
#define BSZ   2
#define SEQ   2048

// ---------------- scratch (__device__ globals; no allocs allowed) ----------
__device__ __half g_q[BSZ*SEQ*DIM];
__device__ __half g_k[BSZ*SEQ*DIM];
__device__ __half g_v[BSZ*SEQ*DIM];
__device__ float  g_cos[SEQ*(HD/2)];
__device__ float  g_sin[SEQ*(HD/2)];

__device__ __half g_x16[DIM*DIM];
__device__ __half g_wq16[DIM*DIM];
__device__ __half g_wk16[DIM*DIM];
__device__ __half g_wv16[DIM*DIM];
__device__ __half g_wo16[DIM*DIM];
__device__ __half g_a16[DIM*DIM];

// ---------------- base-ISA helpers (compute_103-safe) ----------------------
__device__ __forceinline__ uint32_t smem_u32(const void* p) {
    uint32_t a;
    asm("{ .reg .u64 t; cvta.to.shared.u64 t, %1; cvt.u32.u64 %0, t; }" : "=r"(a) : "l"(p));
    return a;
}
__device__ __forceinline__ void cpa16(uint32_t saddr, const void* g) {
    asm volatile("cp.async.cg.shared.global [%0], [%1], 16;" :: "r"(saddr), "l"(g));
}
__device__ __forceinline__ void ldsm4(uint32_t* r, uint32_t addr) {
    asm volatile("ldmatrix.sync.aligned.m8n8.x4.shared.b16 {%0,%1,%2,%3}, [%4];"
        : "=r"(r[0]), "=r"(r[1]), "=r"(r[2]), "=r"(r[3]) : "r"(addr));
}
__device__ __forceinline__ void ldsm4t(uint32_t* r, uint32_t addr) {
    asm volatile("ldmatrix.sync.aligned.m8n8.x4.trans.shared.b16 {%0,%1,%2,%3}, [%4];"
        : "=r"(r[0]), "=r"(r[1]), "=r"(r[2]), "=r"(r[3]) : "r"(addr));
}
__device__ __forceinline__ void mma_f16(float* c, const uint32_t* a,
                                        uint32_t b0, uint32_t b1) {
    asm volatile("mma.sync.aligned.m16n8k16.row.col.f32.f16.f16.f32 "
        "{%0,%1,%2,%3}, {%4,%5,%6,%7}, {%8,%9}, {%0,%1,%2,%3};"
        : "+f"(c[0]), "+f"(c[1]), "+f"(c[2]), "+f"(c[3])
        : "r"(a[0]), "r"(a[1]), "r"(a[2]), "r"(a[3]), "r"(b0), "r"(b1));
}
__device__ __forceinline__ uint32_t pack_h2(float a, float b) {
    __half2 h = __floats2half2_rn(a, b);
    return *(uint32_t*)&h;
}
__device__ __forceinline__ uint32_t sw128(uint32_t off) {
    return off ^ ((off >> 3) & 0x70);
}

// ---------------------------------------------------------------------------
// casts
// ---------------------------------------------------------------------------
__global__ void split_act(const float* __restrict__ in, __half* __restrict__ o, int n4)
{
    int i = blockIdx.x * 256 + threadIdx.x;
    if (i >= n4) return;
    float4 v = ((const float4*)in)[i];
    __half2 a = __floats2half2_rn(v.x, v.y);
    __half2 b = __floats2half2_rn(v.z, v.w);
    uint2 pkt = make_uint2(*(uint32_t*)&a, *(uint32_t*)&b);
    ((uint2*)o)[i] = pkt;
}

__global__ void split_wt(const float* __restrict__ in, __half* __restrict__ o, int n4)
{
    int i = blockIdx.x * 256 + threadIdx.x;
    if (i >= n4) return;
    float4 v = ((const float4*)in)[i];
    __half2 a = __floats2half2_rn(v.x * 64.f, v.y * 64.f);
    __half2 b = __floats2half2_rn(v.z * 64.f, v.w * 64.f);
    uint2 pkt = make_uint2(*(uint32_t*)&a, *(uint32_t*)&b);
    ((uint2*)o)[i] = pkt;
}

// ---------------------------------------------------------------------------
// fp16 single-product GEMM (NT): C = sc * A16*B16, 4096^3.
// CTA 128x128, 8 warps (4Mx2N), warp tile 32x64, BK=64 (SW128),
// 3-stage cp.async pipeline, 2 CTAs/SM. Optional fused RoPE epilogue.
// ---------------------------------------------------------------------------
#define STAGE_SZ 32768
__global__ void __launch_bounds__(256, 2)
gemm_mma(const __half* __restrict__ A16, const __half* __restrict__ B16,
         __half* __restrict__ Ch, float* __restrict__ Cf, float sc,
         const float* __restrict__ Ct, const float* __restrict__ St)
{
    extern __shared__ char sm[];
    const uint32_t s0 = smem_u32(sm);

    const int tid  = threadIdx.x;
    const int wid  = tid >> 5;
    const int lane = tid & 31;
    const int bx = blockIdx.x;
    const int by = blockIdx.y;
    const int warp_m = wid >> 1;
    const int warp_n = wid & 1;

    float acc[2][8][4];
#pragma unroll
    for (int t = 0; t < 2; t++)
#pragma unroll
        for (int n = 0; n < 8; n++)
#pragma unroll
            for (int j = 0; j < 4; j++) acc[t][n][j] = 0.0f;

    auto load_stage = [&](int kt, int stage) {
        uint32_t sb = s0 + stage * STAGE_SZ;
#pragma unroll
        for (int i = 0; i < 4; i++) {
            int li = tid + i * 256;
            int r = li >> 3, c = li & 7;
            uint32_t off = sw128((uint32_t)(r * 128 + c * 16));
            cpa16(sb + off,         A16 + (size_t)(by * 128 + r) * 4096 + kt * 64 + c * 8);
            cpa16(sb + 16384 + off, B16 + (size_t)(bx * 128 + r) * 4096 + kt * 64 + c * 8);
        }
        asm volatile("cp.async.commit_group;" ::: "memory");
    };

    const int lrow  = (lane & 7) + ((lane >> 3) & 1) * 8;
    const int khalf = (lane >> 4) * 16;

    const int NT = 4096 / 64;

    load_stage(0, 0);
    load_stage(1, 1);

    int cs = 0, ls = 2;                       // compute stage, load stage
    for (int kt = 0; kt < NT; kt++) {
        if (kt < NT - 1) asm volatile("cp.async.wait_group 1;" ::: "memory");
        else             asm volatile("cp.async.wait_group 0;" ::: "memory");
        __syncthreads();

        const uint32_t sbase = s0 + cs * STAGE_SZ;
        if (kt + 2 < NT) load_stage(kt + 2, ls);
        cs = (cs == 2) ? 0 : cs + 1;
        ls = (ls == 2) ? 0 : ls + 1;

#pragma unroll
        for (int s = 0; s < 4; s++) {
            uint32_t ah[2][4], bh[4][4];
#pragma unroll
            for (int t = 0; t < 2; t++) {
                uint32_t off = sw128((uint32_t)((warp_m * 32 + t * 16 + lrow) * 128
                                                + khalf + s * 32));
                ldsm4(ah[t], sbase + off);
            }
#pragma unroll
            for (int u = 0; u < 4; u++) {
                uint32_t off = sw128((uint32_t)((warp_n * 64 + u * 16 + lrow) * 128
                                                + khalf + s * 32));
                ldsm4(bh[u], sbase + 16384 + off);
            }
#pragma unroll
            for (int t = 0; t < 2; t++)
#pragma unroll
                for (int u = 0; u < 4; u++)
#pragma unroll
                    for (int j = 0; j < 2; j++)
                        mma_f16(acc[t][u * 2 + j], ah[t], bh[u][j], bh[u][j + 2]);
        }
    }

    const int g  = lane >> 2;
    const int qc = lane & 3;
    if (Ch) {
#pragma unroll
        for (int t = 0; t < 2; t++) {
            const int row = by * 128 + warp_m * 32 + t * 16 + g;
#pragma unroll
            for (int n = 0; n < 8; n++) {
                const int col = bx * 128 + warp_n * 64 + n * 8 + qc * 2;
                float x0 = acc[t][n][0] * sc, x1 = acc[t][n][1] * sc;
                float y0 = acc[t][n][2] * sc, y1 = acc[t][n][3] * sc;
                if (Ct) {
                    const int jj = (col & 127) >> 1;
                    float c0 = Ct[(row & 2047) * 64 + jj];
                    float s0 = St[(row & 2047) * 64 + jj];
                    float c1 = Ct[((row + 8) & 2047) * 64 + jj];
                    float s1 = St[((row + 8) & 2047) * 64 + jj];
                    float nx0 = x0 * c0 - x1 * s0, nx1 = x0 * s0 + x1 * c0;
                    float ny0 = y0 * c1 - y1 * s1, ny1 = y0 * s1 + y1 * c1;
                    x0 = nx0; x1 = nx1; y0 = ny0; y1 = ny1;
                }
                *(__half2*)&Ch[(size_t)row * 4096 + col] = __floats2half2_rn(x0, x1);
                *(__half2*)&Ch[(size_t)(row + 8) * 4096 + col] = __floats2half2_rn(y0, y1);
            }
        }
    } else {
#pragma unroll
        for (int t = 0; t < 2; t++) {
            const int row = by * 128 + warp_m * 32 + t * 16 + g;
#pragma unroll
            for (int n = 0; n < 8; n++) {
                const int col = bx * 128 + warp_n * 64 + n * 8 + qc * 2;
                *(float2*)&Cf[(size_t)row * 4096 + col] =
                    make_float2(acc[t][n][0] * sc, acc[t][n][1] * sc);
                *(float2*)&Cf[(size_t)(row + 8) * 4096 + col] =
                    make_float2(acc[t][n][2] * sc, acc[t][n][3] * sc);
            }
        }
    }
}

// ---------------------------------------------------------------------------
// RoPE table
// ---------------------------------------------------------------------------
__global__ void rope_table(float* ct, float* st)
{
    __shared__ double sinv[64];
    if (threadIdx.x < 64)
        sinv[threadIdx.x] = pow(10000.0, -(double)threadIdx.x / 64.0);
    __syncthreads();

    int idx = blockIdx.x * 256 + threadIdx.x;
    if (idx >= SEQ * (HD / 2)) return;
    int s = idx >> 6;
    int j = idx & 63;
    double a = fmod((double)s * sinv[j], 6.283185307179586477);
    float cf, sf;
    sincosf((float)a, &sf, &cf);
    ct[idx] = cf;
    st[idx] = sf;
}

// ---------------------------------------------------------------------------
// Causal flash attention, all-fp16 mma + ldmatrix (unchanged from R14).
// Block 256 threads (8 warps); Q tile 128 rows, K tile 64 keys.
// ---------------------------------------------------------------------------
#define KVW 68
#define ATTN_SMEM (2 * 64 * KVW * 4)

__global__ void __launch_bounds__(256)
attn_tc(const __half* __restrict__ Qh, const __half* __restrict__ Kh,
        const __half* __restrict__ Vh, __half* __restrict__ O16)
{
    extern __shared__ uint32_t smu[];
    uint32_t* KsU = smu;
    uint32_t* VsU = smu + 64 * KVW;

    const int tid  = threadIdx.x;
    const int w    = tid >> 5;
    const int lane = tid & 31;
    const int qt = blockIdx.x;
    const int h  = blockIdx.y;
    const int b  = blockIdx.z;
    const int g  = lane >> 2;
    const int qc = lane & 3;

    const uint32_t kS = smem_u32(KsU);
    const uint32_t vS = smem_u32(VsU);

    const uint32_t k_row = (lane & 7) + ((lane >> 4) & 1) * 8;
    const uint32_t k_db  = ((lane >> 3) & 1) * 16;
    const uint32_t v_row = (lane & 7) + ((lane >> 3) & 1) * 8;
    const uint32_t v_db  = ((lane >> 4) & 1) * 16;

    const int q0 = qt * 128 + w * 16;

    uint32_t qa[8][4];
    {
        const uint32_t* q_r0 = (const uint32_t*)(Qh + ((size_t)b * SEQ + q0 + g)     * 4096 + h * 128);
        const uint32_t* q_r1 = (const uint32_t*)(Qh + ((size_t)b * SEQ + q0 + g + 8) * 4096 + h * 128);
#pragma unroll
        for (int kc = 0; kc < 8; kc++) {
            qa[kc][0] = q_r0[kc * 8 + qc];
            qa[kc][1] = q_r1[kc * 8 + qc];
            qa[kc][2] = q_r0[kc * 8 + qc + 4];
            qa[kc][3] = q_r1[kc * 8 + qc + 4];
        }
    }

    float o[16][4];
#pragma unroll
    for (int n = 0; n < 16; n++)
#pragma unroll
        for (int j = 0; j < 4; j++) o[n][j] = 0.0f;
    float m0 = -1e30f, m1 = -1e30f, l0 = 0.0f, l1 = 0.0f;

    const int NKT = 2 * qt + 2;

    for (int kt = 0; kt < NKT; kt++) {
        const int kb = kt * 64;
        if (kt) __syncthreads();
#pragma unroll
        for (int i = 0; i < 4; i++) {
            int li = tid + i * 256;
            int row = li >> 4, c = li & 15;
            size_t gsrc = ((size_t)b * SEQ + kb + row) * 4096 + h * 128 + c * 8;
            *(uint4*)&KsU[row * KVW + c * 4] = *(const uint4*)(Kh + gsrc);
            *(uint4*)&VsU[row * KVW + c * 4] = *(const uint4*)(Vh + gsrc);
        }
        __syncthreads();

        if (kb > q0 + 15) continue;

        float sreg[8][4];
#pragma unroll
        for (int j = 0; j < 8; j++)
            sreg[j][0] = sreg[j][1] = sreg[j][2] = sreg[j][3] = 0.0f;
#pragma unroll
        for (int kc = 0; kc < 8; kc++) {
#pragma unroll
            for (int j2 = 0; j2 < 4; j2++) {
                uint32_t r[4];
                ldsm4(r, kS + (j2 * 16 + k_row) * 272 + kc * 32 + k_db);
                mma_f16(sreg[2 * j2],     qa[kc], r[0], r[1]);
                mma_f16(sreg[2 * j2 + 1], qa[kc], r[2], r[3]);
            }
        }

        if (kb + 63 > q0) {
#pragma unroll
            for (int j = 0; j < 8; j++) {
                int key0 = kb + j * 8 + 2 * qc;
                if (key0     > q0 + g)     sreg[j][0] = -1e30f;
                if (key0 + 1 > q0 + g)     sreg[j][1] = -1e30f;
                if (key0     > q0 + g + 8) sreg[j][2] = -1e30f;
                if (key0 + 1 > q0 + g + 8) sreg[j][3] = -1e30f;
            }
        }

        float mx0 = -1e30f, mx1 = -1e30f;
#pragma unroll
        for (int j = 0; j < 8; j++) {
            mx0 = fmaxf(mx0, fmaxf(sreg[j][0], sreg[j][1]));
            mx1 = fmaxf(mx1, fmaxf(sreg[j][2], sreg[j][3]));
        }
        mx0 = fmaxf(mx0, __shfl_xor_sync(0xffffffffu, mx0, 1));
        mx0 = fmaxf(mx0, __shfl_xor_sync(0xffffffffu, mx0, 2));
        mx1 = fmaxf(mx1, __shfl_xor_sync(0xffffffffu, mx1, 1));
        mx1 = fmaxf(mx1, __shfl_xor_sync(0xffffffffu, mx1, 2));
        float mn0 = fmaxf(m0, mx0), mn1 = fmaxf(m1, mx1);
        float f0 = __expf(m0 - mn0), f1 = __expf(m1 - mn1);
        m0 = mn0; m1 = mn1;

        float sum0 = 0.0f, sum1 = 0.0f;
#pragma unroll
        for (int j = 0; j < 8; j++) {
            sreg[j][0] = __expf(sreg[j][0] - mn0);
            sreg[j][1] = __expf(sreg[j][1] - mn0);
            sreg[j][2] = __expf(sreg[j][2] - mn1);
            sreg[j][3] = __expf(sreg[j][3] - mn1);
            sum0 += sreg[j][0] + sreg[j][1];
            sum1 += sreg[j][2] + sreg[j][3];
        }
        sum0 += __shfl_xor_sync(0xffffffffu, sum0, 1);
        sum0 += __shfl_xor_sync(0xffffffffu, sum0, 2);
        sum1 += __shfl_xor_sync(0xffffffffu, sum1, 1);
        sum1 += __shfl_xor_sync(0xffffffffu, sum1, 2);
        l0 = l0 * f0 + sum0;
        l1 = l1 * f1 + sum1;

#pragma unroll
        for (int n = 0; n < 16; n++) {
            o[n][0] *= f0; o[n][1] *= f0;
            o[n][2] *= f1; o[n][3] *= f1;
        }

        uint32_t pa[4][4];
#pragma unroll
        for (int kc = 0; kc < 4; kc++) {
            pa[kc][0] = pack_h2(sreg[2 * kc][0],     sreg[2 * kc][1]);
            pa[kc][1] = pack_h2(sreg[2 * kc][2],     sreg[2 * kc][3]);
            pa[kc][2] = pack_h2(sreg[2 * kc + 1][0], sreg[2 * kc + 1][1]);
            pa[kc][3] = pack_h2(sreg[2 * kc + 1][2], sreg[2 * kc + 1][3]);
        }

#pragma unroll
        for (int kc = 0; kc < 4; kc++) {
#pragma unroll
            for (int d0 = 0; d0 < 8; d0++) {
                uint32_t r[4];
                ldsm4t(r, vS + (kc * 16 + v_row) * 272 + d0 * 32 + v_db);
                mma_f16(o[2 * d0],     pa[kc], r[0], r[1]);
                mma_f16(o[2 * d0 + 1], pa[kc], r[2], r[3]);
            }
        }
    }

    const float inv0 = 1.0f / l0;
    const float inv1 = 1.0f / l1;
    const size_t base0 = ((size_t)b * SEQ + q0 + g)     * 4096 + h * 128;
    const size_t base1 = ((size_t)b * SEQ + q0 + g + 8) * 4096 + h * 128;
#pragma unroll
    for (int n = 0; n < 16; n++) {
        *(__half2*)&O16[base0 + n * 8 + 2 * qc] =
            __floats2half2_rn(o[n][0] * inv0, o[n][1] * inv0);
        *(__half2*)&O16[base1 + n * 8 + 2 * qc] =
            __floats2half2_rn(o[n][2] * inv1, o[n][3] * inv1);
    }
}

// ---------------------------------------------------------------------------
extern "C" void kernel_launch(void* const* d_in, const int* in_sizes, int n_in,
                              void* d_out, int out_size)
{
    const float* x = (const float*)d_in[0];
    int off = (n_in >= 6 && in_sizes[1] <= 4) ? 2 : 1;
    const float* wq = (const float*)d_in[off + 0];
    const float* wk = (const float*)d_in[off + 1];
    const float* wv = (const float*)d_in[off + 2];
    const float* wo = (const float*)d_in[off + 3];
    float* out = (float*)d_out;

    __half *q, *k, *v;
    float *ct, *st;
    cudaGetSymbolAddress((void**)&q,  g_q);
    cudaGetSymbolAddress((void**)&k,  g_k);
    cudaGetSymbolAddress((void**)&v,  g_v);
    cudaGetSymbolAddress((void**)&ct, g_cos);
    cudaGetSymbolAddress((void**)&st, g_sin);

    __half *x16, *wq16, *wk16, *wv16, *wo16, *a16;
    cudaGetSymbolAddress((void**)&x16,  g_x16);
    cudaGetSymbolAddress((void**)&wq16, g_wq16);
    cudaGetSymbolAddress((void**)&wk16, g_wk16);
    cudaGetSymbolAddress((void**)&wv16, g_wv16);
    cudaGetSymbolAddress((void**)&wo16, g_wo16);
    cudaGetSymbolAddress((void**)&a16,  g_a16);

    cudaFuncSetAttribute(gemm_mma, cudaFuncAttributeMaxDynamicSharedMemorySize, 3 * STAGE_SZ);
    cudaFuncSetAttribute(attn_tc,  cudaFuncAttributeMaxDynamicSharedMemorySize, ATTN_SMEM);

    const int n4 = DIM * DIM / 4;
    const int cgrid = (n4 + 255) / 256;
    dim3 gg(DIM / 128, DIM / 128);

    const float SC   = 0.015625f;                        // 2^-6 (weights x64)
    const float SC_Q = SC * 0.08838834764831845f;        // fold 1/sqrt(128) into q

    // --- side stream for weight splits / rope table (fork-join capture) ---
    // kernel_launch runs only for the correctness call + the capture call,
    // so creating (and not destroying) these per call is bounded.
    cudaStream_t s1;
    cudaStreamCreateWithFlags(&s1, cudaStreamNonBlocking);
    cudaEvent_t evF, evQ, evK, evV, evO;
    cudaEventCreateWithFlags(&evF, cudaEventDisableTiming);
    cudaEventCreateWithFlags(&evQ, cudaEventDisableTiming);
    cudaEventCreateWithFlags(&evK, cudaEventDisableTiming);
    cudaEventCreateWithFlags(&evV, cudaEventDisableTiming);
    cudaEventCreateWithFlags(&evO, cudaEventDisableTiming);

    // fork side stream off the (capturing) default stream
    cudaEventRecord(evF, 0);
    cudaStreamWaitEvent(s1, evF, 0);

    // side stream: rope table + all weight casts
    rope_table<<<(SEQ * (HD / 2) + 255) / 256, 256, 0, s1>>>(ct, st);
    split_wt<<<cgrid, 256, 0, s1>>>(wq, wq16, n4);
    cudaEventRecord(evQ, s1);
    split_wt<<<cgrid, 256, 0, s1>>>(wk, wk16, n4);
    cudaEventRecord(evK, s1);
    split_wt<<<cgrid, 256, 0, s1>>>(wv, wv16, n4);
    cudaEventRecord(evV, s1);
    split_wt<<<cgrid, 256, 0, s1>>>(wo, wo16, n4);
    cudaEventRecord(evO, s1);

    // main stream
    split_act<<<cgrid, 256>>>(x, x16, n4);

    cudaStreamWaitEvent(0, evQ, 0);
    gemm_mma<<<gg, 256, 3 * STAGE_SZ>>>(x16, wq16, q, nullptr, SC_Q, ct, st);
    cudaStreamWaitEvent(0, evK, 0);
    gemm_mma<<<gg, 256, 3 * STAGE_SZ>>>(x16, wk16, k, nullptr, SC, ct, st);
    cudaStreamWaitEvent(0, evV, 0);
    gemm_mma<<<gg, 256, 3 * STAGE_SZ>>>(x16, wv16, v, nullptr, SC, nullptr, nullptr);

    attn_tc<<<dim3(SEQ / 128, NH, BSZ), 256, ATTN_SMEM>>>(q, k, v, a16);

    cudaStreamWaitEvent(0, evO, 0);   // also joins the side branch into capture
    gemm_mma<<<gg, 256, 3 * STAGE_SZ>>>(a16, wo16, nullptr, out, SC, nullptr, nullptr);
}

// round 16
// speedup vs baseline: 3.4907x; 1.0236x over previous
#include <cuda_runtime.h>
#include <cuda_fp16.h>
#include <cstdint>
#include <math.h>

#define DIM   4096
#define NH    32
#define HD    128
#define BSZ   2
#define SEQ   2048

// ---------------- scratch (__device__ globals; no allocs allowed) ----------
__device__ __half g_q[BSZ*SEQ*DIM];
__device__ __half g_k[BSZ*SEQ*DIM];
__device__ __half g_v[BSZ*SEQ*DIM];
__device__ float  g_cos[SEQ*(HD/2)];
__device__ float  g_sin[SEQ*(HD/2)];

__device__ __half g_x16[DIM*DIM];
__device__ __half g_wq16[DIM*DIM];
__device__ __half g_wk16[DIM*DIM];
__device__ __half g_wv16[DIM*DIM];
__device__ __half g_wo16[DIM*DIM];
__device__ __half g_a16[DIM*DIM];

// ---------------- base-ISA helpers (compute_103-safe) ----------------------
__device__ __forceinline__ uint32_t smem_u32(const void* p) {
    uint32_t a;
    asm("{ .reg .u64 t; cvta.to.shared.u64 t, %1; cvt.u32.u64 %0, t; }" : "=r"(a) : "l"(p));
    return a;
}
__device__ __forceinline__ void cpa16(uint32_t saddr, const void* g) {
    asm volatile("cp.async.cg.shared.global [%0], [%1], 16;" :: "r"(saddr), "l"(g));
}
__device__ __forceinline__ void ldsm4(uint32_t* r, uint32_t addr) {
    asm volatile("ldmatrix.sync.aligned.m8n8.x4.shared.b16 {%0,%1,%2,%3}, [%4];"
        : "=r"(r[0]), "=r"(r[1]), "=r"(r[2]), "=r"(r[3]) : "r"(addr));
}
__device__ __forceinline__ void ldsm4t(uint32_t* r, uint32_t addr) {
    asm volatile("ldmatrix.sync.aligned.m8n8.x4.trans.shared.b16 {%0,%1,%2,%3}, [%4];"
        : "=r"(r[0]), "=r"(r[1]), "=r"(r[2]), "=r"(r[3]) : "r"(addr));
}
__device__ __forceinline__ void mma_f16(float* c, const uint32_t* a,
                                        uint32_t b0, uint32_t b1) {
    asm volatile("mma.sync.aligned.m16n8k16.row.col.f32.f16.f16.f32 "
        "{%0,%1,%2,%3}, {%4,%5,%6,%7}, {%8,%9}, {%0,%1,%2,%3};"
        : "+f"(c[0]), "+f"(c[1]), "+f"(c[2]), "+f"(c[3])
        : "r"(a[0]), "r"(a[1]), "r"(a[2]), "r"(a[3]), "r"(b0), "r"(b1));
}
__device__ __forceinline__ uint32_t pack_h2(float a, float b) {
    __half2 h = __floats2half2_rn(a, b);
    return *(uint32_t*)&h;
}
__device__ __forceinline__ uint32_t sw128(uint32_t off) {
    return off ^ ((off >> 3) & 0x70);
}

// ---------------------------------------------------------------------------
// casts
// ---------------------------------------------------------------------------
__global__ void split_act(const float* __restrict__ in, __half* __restrict__ o, int n4)
{
    int i = blockIdx.x * 256 + threadIdx.x;
    if (i >= n4) return;
    float4 v = ((const float4*)in)[i];
    __half2 a = __floats2half2_rn(v.x, v.y);
    __half2 b = __floats2half2_rn(v.z, v.w);
    uint2 pkt = make_uint2(*(uint32_t*)&a, *(uint32_t*)&b);
    ((uint2*)o)[i] = pkt;
}

__global__ void split_wt(const float* __restrict__ in, __half* __restrict__ o, int n4)
{
    int i = blockIdx.x * 256 + threadIdx.x;
    if (i >= n4) return;
    float4 v = ((const float4*)in)[i];
    __half2 a = __floats2half2_rn(v.x * 64.f, v.y * 64.f);
    __half2 b = __floats2half2_rn(v.z * 64.f, v.w * 64.f);
    uint2 pkt = make_uint2(*(uint32_t*)&a, *(uint32_t*)&b);
    ((uint2*)o)[i] = pkt;
}

// ---------------------------------------------------------------------------
// fp16 single-product GEMM (NT): C = sc * A16*B16, 4096^3.  (frozen config)
// ---------------------------------------------------------------------------
#define STAGE_SZ 32768
__global__ void __launch_bounds__(256, 2)
gemm_mma(const __half* __restrict__ A16, const __half* __restrict__ B16,
         __half* __restrict__ Ch, float* __restrict__ Cf, float sc,
         const float* __restrict__ Ct, const float* __restrict__ St)
{
    extern __shared__ char sm[];
    const uint32_t s0 = smem_u32(sm);

    const int tid  = threadIdx.x;
    const int wid  = tid >> 5;
    const int lane = tid & 31;
    const int bx = blockIdx.x;
    const int by = blockIdx.y;
    const int warp_m = wid >> 1;
    const int warp_n = wid & 1;

    float acc[2][8][4];
#pragma unroll
    for (int t = 0; t < 2; t++)
#pragma unroll
        for (int n = 0; n < 8; n++)
#pragma unroll
            for (int j = 0; j < 4; j++) acc[t][n][j] = 0.0f;

    auto load_stage = [&](int kt, int stage) {
        uint32_t sb = s0 + stage * STAGE_SZ;
#pragma unroll
        for (int i = 0; i < 4; i++) {
            int li = tid + i * 256;
            int r = li >> 3, c = li & 7;
            uint32_t off = sw128((uint32_t)(r * 128 + c * 16));
            cpa16(sb + off,         A16 + (size_t)(by * 128 + r) * 4096 + kt * 64 + c * 8);
            cpa16(sb + 16384 + off, B16 + (size_t)(bx * 128 + r) * 4096 + kt * 64 + c * 8);
        }
        asm volatile("cp.async.commit_group;" ::: "memory");
    };

    const int lrow  = (lane & 7) + ((lane >> 3) & 1) * 8;
    const int khalf = (lane >> 4) * 16;

    const int NT = 4096 / 64;

    load_stage(0, 0);
    load_stage(1, 1);

    int cs = 0, ls = 2;
    for (int kt = 0; kt < NT; kt++) {
        if (kt < NT - 1) asm volatile("cp.async.wait_group 1;" ::: "memory");
        else             asm volatile("cp.async.wait_group 0;" ::: "memory");
        __syncthreads();

        const uint32_t sbase = s0 + cs * STAGE_SZ;
        if (kt + 2 < NT) load_stage(kt + 2, ls);
        cs = (cs == 2) ? 0 : cs + 1;
        ls = (ls == 2) ? 0 : ls + 1;

#pragma unroll
        for (int s = 0; s < 4; s++) {
            uint32_t ah[2][4], bh[4][4];
#pragma unroll
            for (int t = 0; t < 2; t++) {
                uint32_t off = sw128((uint32_t)((warp_m * 32 + t * 16 + lrow) * 128
                                                + khalf + s * 32));
                ldsm4(ah[t], sbase + off);
            }
#pragma unroll
            for (int u = 0; u < 4; u++) {
                uint32_t off = sw128((uint32_t)((warp_n * 64 + u * 16 + lrow) * 128
                                                + khalf + s * 32));
                ldsm4(bh[u], sbase + 16384 + off);
            }
#pragma unroll
            for (int t = 0; t < 2; t++)
#pragma unroll
                for (int u = 0; u < 4; u++)
#pragma unroll
                    for (int j = 0; j < 2; j++)
                        mma_f16(acc[t][u * 2 + j], ah[t], bh[u][j], bh[u][j + 2]);
        }
    }

    const int g  = lane >> 2;
    const int qc = lane & 3;
    if (Ch) {
#pragma unroll
        for (int t = 0; t < 2; t++) {
            const int row = by * 128 + warp_m * 32 + t * 16 + g;
#pragma unroll
            for (int n = 0; n < 8; n++) {
                const int col = bx * 128 + warp_n * 64 + n * 8 + qc * 2;
                float x0 = acc[t][n][0] * sc, x1 = acc[t][n][1] * sc;
                float y0 = acc[t][n][2] * sc, y1 = acc[t][n][3] * sc;
                if (Ct) {
                    const int jj = (col & 127) >> 1;
                    float c0 = Ct[(row & 2047) * 64 + jj];
                    float s0 = St[(row & 2047) * 64 + jj];
                    float c1 = Ct[((row + 8) & 2047) * 64 + jj];
                    float s1 = St[((row + 8) & 2047) * 64 + jj];
                    float nx0 = x0 * c0 - x1 * s0, nx1 = x0 * s0 + x1 * c0;
                    float ny0 = y0 * c1 - y1 * s1, ny1 = y0 * s1 + y1 * c1;
                    x0 = nx0; x1 = nx1; y0 = ny0; y1 = ny1;
                }
                *(__half2*)&Ch[(size_t)row * 4096 + col] = __floats2half2_rn(x0, x1);
                *(__half2*)&Ch[(size_t)(row + 8) * 4096 + col] = __floats2half2_rn(y0, y1);
            }
        }
    } else {
#pragma unroll
        for (int t = 0; t < 2; t++) {
            const int row = by * 128 + warp_m * 32 + t * 16 + g;
#pragma unroll
            for (int n = 0; n < 8; n++) {
                const int col = bx * 128 + warp_n * 64 + n * 8 + qc * 2;
                *(float2*)&Cf[(size_t)row * 4096 + col] =
                    make_float2(acc[t][n][0] * sc, acc[t][n][1] * sc);
                *(float2*)&Cf[(size_t)(row + 8) * 4096 + col] =
                    make_float2(acc[t][n][2] * sc, acc[t][n][3] * sc);
            }
        }
    }
}

// ---------------------------------------------------------------------------
// RoPE table
// ---------------------------------------------------------------------------
__global__ void rope_table(float* ct, float* st)
{
    __shared__ double sinv[64];
    if (threadIdx.x < 64)
        sinv[threadIdx.x] = pow(10000.0, -(double)threadIdx.x / 64.0);
    __syncthreads();

    int idx = blockIdx.x * 256 + threadIdx.x;
    if (idx >= SEQ * (HD / 2)) return;
    int s = idx >> 6;
    int j = idx & 63;
    double a = fmod((double)s * sinv[j], 6.283185307179586477);
    float cf, sf;
    sincosf((float)a, &sf, &cf);
    ct[idx] = cf;
    st[idx] = sf;
}

// ---------------------------------------------------------------------------
// Causal flash attention, all-fp16 mma + ldmatrix.
// Block 256 threads (8 warps); Q tile 128 rows, K tile 64 keys.
// K/V staged via 2-stage cp.async double buffering (load(kt+1) || compute(kt)).
// ---------------------------------------------------------------------------
#define KVROW 272                    // bytes per K/V row (256B data + 16B pad)
#define KVMAT (64 * KVROW)           // 17408 B per matrix per stage
#define KVSTG (2 * KVMAT)            // 34816 B per stage (K + V)
#define ATTN_SMEM (2 * KVSTG)        // 69632 B

__global__ void __launch_bounds__(256)
attn_tc(const __half* __restrict__ Qh, const __half* __restrict__ Kh,
        const __half* __restrict__ Vh, __half* __restrict__ O16)
{
    extern __shared__ char smc[];
    const uint32_t s0 = smem_u32(smc);

    const int tid  = threadIdx.x;
    const int w    = tid >> 5;
    const int lane = tid & 31;
    const int qt = blockIdx.x;
    const int h  = blockIdx.y;
    const int b  = blockIdx.z;
    const int g  = lane >> 2;
    const int qc = lane & 3;

    const uint32_t k_row = (lane & 7) + ((lane >> 4) & 1) * 8;
    const uint32_t k_db  = ((lane >> 3) & 1) * 16;
    const uint32_t v_row = (lane & 7) + ((lane >> 3) & 1) * 8;
    const uint32_t v_db  = ((lane >> 4) & 1) * 16;

    const int q0 = qt * 128 + w * 16;
    const int NKT = 2 * qt + 2;

    // stage loader: 64 rows x 256B of K and V each -> cp.async 16B chunks
    auto load_kv = [&](int kt, int stage) {
        uint32_t sb = s0 + stage * KVSTG;
#pragma unroll
        for (int i = 0; i < 4; i++) {
            int li = tid + i * 256;             // 0..1023
            int row = li >> 4, c = li & 15;
            size_t gsrc = ((size_t)b * SEQ + kt * 64 + row) * 4096 + h * 128 + c * 8;
            uint32_t soff = (uint32_t)(row * KVROW + c * 16);
            cpa16(sb + soff,         Kh + gsrc);
            cpa16(sb + KVMAT + soff, Vh + gsrc);
        }
        asm volatile("cp.async.commit_group;" ::: "memory");
    };

    uint32_t qa[8][4];
    {
        const uint32_t* q_r0 = (const uint32_t*)(Qh + ((size_t)b * SEQ + q0 + g)     * 4096 + h * 128);
        const uint32_t* q_r1 = (const uint32_t*)(Qh + ((size_t)b * SEQ + q0 + g + 8) * 4096 + h * 128);
#pragma unroll
        for (int kc = 0; kc < 8; kc++) {
            qa[kc][0] = q_r0[kc * 8 + qc];
            qa[kc][1] = q_r1[kc * 8 + qc];
            qa[kc][2] = q_r0[kc * 8 + qc + 4];
            qa[kc][3] = q_r1[kc * 8 + qc + 4];
        }
    }

    float o[16][4];
#pragma unroll
    for (int n = 0; n < 16; n++)
#pragma unroll
        for (int j = 0; j < 4; j++) o[n][j] = 0.0f;
    float m0 = -1e30f, m1 = -1e30f, l0 = 0.0f, l1 = 0.0f;

    load_kv(0, 0);

    int buf = 0;
    for (int kt = 0; kt < NKT; kt++) {
        const int kb = kt * 64;
        asm volatile("cp.async.wait_group 0;" ::: "memory");
        __syncthreads();                        // stage `buf` ready; prior compute done

        if (kt + 1 < NKT) load_kv(kt + 1, buf ^ 1);

        const uint32_t kS = s0 + buf * KVSTG;
        const uint32_t vS = kS + KVMAT;
        buf ^= 1;

        if (kb > q0 + 15) continue;             // tile entirely in this warp's future

        float sreg[8][4];
#pragma unroll
        for (int j = 0; j < 8; j++)
            sreg[j][0] = sreg[j][1] = sreg[j][2] = sreg[j][3] = 0.0f;
#pragma unroll
        for (int kc = 0; kc < 8; kc++) {
#pragma unroll
            for (int j2 = 0; j2 < 4; j2++) {
                uint32_t r[4];
                ldsm4(r, kS + (j2 * 16 + k_row) * KVROW + kc * 32 + k_db);
                mma_f16(sreg[2 * j2],     qa[kc], r[0], r[1]);
                mma_f16(sreg[2 * j2 + 1], qa[kc], r[2], r[3]);
            }
        }

        if (kb + 63 > q0) {
#pragma unroll
            for (int j = 0; j < 8; j++) {
                int key0 = kb + j * 8 + 2 * qc;
                if (key0     > q0 + g)     sreg[j][0] = -1e30f;
                if (key0 + 1 > q0 + g)     sreg[j][1] = -1e30f;
                if (key0     > q0 + g + 8) sreg[j][2] = -1e30f;
                if (key0 + 1 > q0 + g + 8) sreg[j][3] = -1e30f;
            }
        }

        float mx0 = -1e30f, mx1 = -1e30f;
#pragma unroll
        for (int j = 0; j < 8; j++) {
            mx0 = fmaxf(mx0, fmaxf(sreg[j][0], sreg[j][1]));
            mx1 = fmaxf(mx1, fmaxf(sreg[j][2], sreg[j][3]));
        }
        mx0 = fmaxf(mx0, __shfl_xor_sync(0xffffffffu, mx0, 1));
        mx0 = fmaxf(mx0, __shfl_xor_sync(0xffffffffu, mx0, 2));
        mx1 = fmaxf(mx1, __shfl_xor_sync(0xffffffffu, mx1, 1));
        mx1 = fmaxf(mx1, __shfl_xor_sync(0xffffffffu, mx1, 2));
        float mn0 = fmaxf(m0, mx0), mn1 = fmaxf(m1, mx1);
        float f0 = __expf(m0 - mn0), f1 = __expf(m1 - mn1);
        m0 = mn0; m1 = mn1;

        float sum0 = 0.0f, sum1 = 0.0f;
#pragma unroll
        for (int j = 0; j < 8; j++) {
            sreg[j][0] = __expf(sreg[j][0] - mn0);
            sreg[j][1] = __expf(sreg[j][1] - mn0);
            sreg[j][2] = __expf(sreg[j][2] - mn1);
            sreg[j][3] = __expf(sreg[j][3] - mn1);
            sum0 += sreg[j][0] + sreg[j][1];
            sum1 += sreg[j][2] + sreg[j][3];
        }
        sum0 += __shfl_xor_sync(0xffffffffu, sum0, 1);
        sum0 += __shfl_xor_sync(0xffffffffu, sum0, 2);
        sum1 += __shfl_xor_sync(0xffffffffu, sum1, 1);
        sum1 += __shfl_xor_sync(0xffffffffu, sum1, 2);
        l0 = l0 * f0 + sum0;
        l1 = l1 * f1 + sum1;

#pragma unroll
        for (int n = 0; n < 16; n++) {
            o[n][0] *= f0; o[n][1] *= f0;
            o[n][2] *= f1; o[n][3] *= f1;
        }

        uint32_t pa[4][4];
#pragma unroll
        for (int kc = 0; kc < 4; kc++) {
            pa[kc][0] = pack_h2(sreg[2 * kc][0],     sreg[2 * kc][1]);
            pa[kc][1] = pack_h2(sreg[2 * kc][2],     sreg[2 * kc][3]);
            pa[kc][2] = pack_h2(sreg[2 * kc + 1][0], sreg[2 * kc + 1][1]);
            pa[kc][3] = pack_h2(sreg[2 * kc + 1][2], sreg[2 * kc + 1][3]);
        }

#pragma unroll
        for (int kc = 0; kc < 4; kc++) {
#pragma unroll
            for (int d0 = 0; d0 < 8; d0++) {
                uint32_t r[4];
                ldsm4t(r, vS + (kc * 16 + v_row) * KVROW + d0 * 32 + v_db);
                mma_f16(o[2 * d0],     pa[kc], r[0], r[1]);
                mma_f16(o[2 * d0 + 1], pa[kc], r[2], r[3]);
            }
        }
    }

    const float inv0 = 1.0f / l0;
    const float inv1 = 1.0f / l1;
    const size_t base0 = ((size_t)b * SEQ + q0 + g)     * 4096 + h * 128;
    const size_t base1 = ((size_t)b * SEQ + q0 + g + 8) * 4096 + h * 128;
#pragma unroll
    for (int n = 0; n < 16; n++) {
        *(__half2*)&O16[base0 + n * 8 + 2 * qc] =
            __floats2half2_rn(o[n][0] * inv0, o[n][1] * inv0);
        *(__half2*)&O16[base1 + n * 8 + 2 * qc] =
            __floats2half2_rn(o[n][2] * inv1, o[n][3] * inv1);
    }
}

// ---------------------------------------------------------------------------
extern "C" void kernel_launch(void* const* d_in, const int* in_sizes, int n_in,
                              void* d_out, int out_size)
{
    const float* x = (const float*)d_in[0];
    int off = (n_in >= 6 && in_sizes[1] <= 4) ? 2 : 1;
    const float* wq = (const float*)d_in[off + 0];
    const float* wk = (const float*)d_in[off + 1];
    const float* wv = (const float*)d_in[off + 2];
    const float* wo = (const float*)d_in[off + 3];
    float* out = (float*)d_out;

    __half *q, *k, *v;
    float *ct, *st;
    cudaGetSymbolAddress((void**)&q,  g_q);
    cudaGetSymbolAddress((void**)&k,  g_k);
    cudaGetSymbolAddress((void**)&v,  g_v);
    cudaGetSymbolAddress((void**)&ct, g_cos);
    cudaGetSymbolAddress((void**)&st, g_sin);

    __half *x16, *wq16, *wk16, *wv16, *wo16, *a16;
    cudaGetSymbolAddress((void**)&x16,  g_x16);
    cudaGetSymbolAddress((void**)&wq16, g_wq16);
    cudaGetSymbolAddress((void**)&wk16, g_wk16);
    cudaGetSymbolAddress((void**)&wv16, g_wv16);
    cudaGetSymbolAddress((void**)&wo16, g_wo16);
    cudaGetSymbolAddress((void**)&a16,  g_a16);

    cudaFuncSetAttribute(gemm_mma, cudaFuncAttributeMaxDynamicSharedMemorySize, 3 * STAGE_SZ);
    cudaFuncSetAttribute(attn_tc,  cudaFuncAttributeMaxDynamicSharedMemorySize, ATTN_SMEM);

    const int n4 = DIM * DIM / 4;
    const int cgrid = (n4 + 255) / 256;
    dim3 gg(DIM / 128, DIM / 128);

    const float SC   = 0.015625f;                        // 2^-6 (weights x64)
    const float SC_Q = SC * 0.08838834764831845f;        // fold 1/sqrt(128) into q

    // side stream for weight casts / rope table (fork-join inside capture)
    cudaStream_t s1;
    cudaStreamCreateWithFlags(&s1, cudaStreamNonBlocking);
    cudaEvent_t evF, evQ, evK, evV, evO;
    cudaEventCreateWithFlags(&evF, cudaEventDisableTiming);
    cudaEventCreateWithFlags(&evQ, cudaEventDisableTiming);
    cudaEventCreateWithFlags(&evK, cudaEventDisableTiming);
    cudaEventCreateWithFlags(&evV, cudaEventDisableTiming);
    cudaEventCreateWithFlags(&evO, cudaEventDisableTiming);

    cudaEventRecord(evF, 0);
    cudaStreamWaitEvent(s1, evF, 0);

    rope_table<<<(SEQ * (HD / 2) + 255) / 256, 256, 0, s1>>>(ct, st);
    split_wt<<<cgrid, 256, 0, s1>>>(wq, wq16, n4);
    cudaEventRecord(evQ, s1);
    split_wt<<<cgrid, 256, 0, s1>>>(wk, wk16, n4);
    cudaEventRecord(evK, s1);
    split_wt<<<cgrid, 256, 0, s1>>>(wv, wv16, n4);
    cudaEventRecord(evV, s1);
    split_wt<<<cgrid, 256, 0, s1>>>(wo, wo16, n4);
    cudaEventRecord(evO, s1);

    split_act<<<cgrid, 256>>>(x, x16, n4);

    cudaStreamWaitEvent(0, evQ, 0);
    gemm_mma<<<gg, 256, 3 * STAGE_SZ>>>(x16, wq16, q, nullptr, SC_Q, ct, st);
    cudaStreamWaitEvent(0, evK, 0);
    gemm_mma<<<gg, 256, 3 * STAGE_SZ>>>(x16, wk16, k, nullptr, SC, ct, st);
    cudaStreamWaitEvent(0, evV, 0);
    gemm_mma<<<gg, 256, 3 * STAGE_SZ>>>(x16, wv16, v, nullptr, SC, nullptr, nullptr);

    attn_tc<<<dim3(SEQ / 128, NH, BSZ), 256, ATTN_SMEM>>>(q, k, v, a16);

    cudaStreamWaitEvent(0, evO, 0);
    gemm_mma<<<gg, 256, 3 * STAGE_SZ>>>(a16, wo16, nullptr, out, SC, nullptr, nullptr);
}